// round 1
// baseline (speedup 1.0000x reference)
#include <cuda_runtime.h>
#include <cstdint>
#include <cstdio>

// ---------------- problem constants ----------------
#define NN      32768      // nodes
#define EE      131072     // edges
#define HH      512        // hidden
#define HEH     128        // edge hidden
#define H2      1024       // 2*H
#define OUTD    1024
#define BB      1024       // graphs
#define NPG     32
#define LL      6
#define EPSV    1e-5f

__device__ __constant__ int c_node_off[9] = {0,119,128,139,151,160,165,173,175};
__device__ __constant__ int c_edge_off[3] = {0,119,128};

// ---------------- scratch (device globals; no allocs allowed) ----------------
__device__ float g_z   [(size_t)NN * HH];
__device__ float g_agg [(size_t)NN * HH];
__device__ float g_eemb[(size_t)EE * HEH];
__device__ float g_ee  [(size_t)EE * HH];
__device__ float g_h   [(size_t)NN * H2];
__device__ float g_zpre[(size_t)NN * HH];
__device__ float g_zout[(size_t)NN * OUTD];
__device__ float g_v   [OUTD + 1];         // v[0..1023], c at [1024]
__device__ float g_hg  [(size_t)BB * OUTD];
__device__ float g_stats[2048];            // sum[0..cols), sumsq at [1024+c)

// ---------------- embedding kernels ----------------
__global__ void embed_nodes(const int* __restrict__ x, const float* __restrict__ tab,
                            float* __restrict__ z) {
    int n = blockIdx.x;
    __shared__ int idx[9];
    if (threadIdx.x < 9) idx[threadIdx.x] = x[n * 9 + threadIdx.x] + c_node_off[threadIdx.x];
    __syncthreads();
    for (int c = threadIdx.x; c < HH; c += blockDim.x) {
        float acc = 0.f;
#pragma unroll
        for (int f = 0; f < 9; f++) acc += tab[(size_t)idx[f] * HH + c];
        z[(size_t)n * HH + c] = acc;
    }
}

__global__ void embed_edges(const int* __restrict__ ea, const float* __restrict__ tab,
                            float* __restrict__ out) {
    int e = blockIdx.x;
    __shared__ int idx[3];
    if (threadIdx.x < 3) idx[threadIdx.x] = ea[e * 3 + threadIdx.x] + c_edge_off[threadIdx.x];
    __syncthreads();
    for (int c = threadIdx.x; c < HEH; c += blockDim.x) {
        float acc = 0.f;
#pragma unroll
        for (int f = 0; f < 3; f++) acc += tab[(size_t)idx[f] * HEH + c];
        out[(size_t)e * HEH + c] = acc;
    }
}

// ---------------- tiled SGEMM: C = (A [+A2]) @ B + bias ----------------
// BM=128, BN=128, BK=16, 256 threads, 8x8 per thread. All dims are exact multiples.
#define GBM 128
#define GBN 128
#define GBK 16

template <bool ADDA2>
__global__ void __launch_bounds__(256)
sgemm(int M, int N, int K,
      const float* __restrict__ A, const float* __restrict__ A2,
      const float* __restrict__ B, const float* __restrict__ bias,
      float* __restrict__ C) {
    __shared__ float As[GBK][GBM];
    __shared__ float Bs[GBK][GBN];

    const int tid = threadIdx.x;
    const int brow = blockIdx.y, bcol = blockIdx.x;
    const int trow = (tid / 16) * 8;
    const int tcol = (tid % 16) * 8;

    const float* Ab  = A  + (size_t)brow * GBM * K;
    const float* A2b = ADDA2 ? (A2 + (size_t)brow * GBM * K) : nullptr;
    const float* Bb  = B + (size_t)bcol * GBN;

    float acc[8][8];
#pragma unroll
    for (int i = 0; i < 8; i++)
#pragma unroll
        for (int j = 0; j < 8; j++) acc[i][j] = 0.f;

    for (int k0 = 0; k0 < K; k0 += GBK) {
        // load A tile 128x16 -> As transposed. 512 float4, 2 per thread.
#pragma unroll
        for (int t = 0; t < 2; t++) {
            int id  = tid + 256 * t;
            int row = id >> 2;            // 0..127
            int col = (id & 3) * 4;       // 0,4,8,12
            float4 a = *(const float4*)(Ab + (size_t)row * K + k0 + col);
            if (ADDA2) {
                float4 a2 = *(const float4*)(A2b + (size_t)row * K + k0 + col);
                a.x += a2.x; a.y += a2.y; a.z += a2.z; a.w += a2.w;
            }
            As[col + 0][row] = a.x;
            As[col + 1][row] = a.y;
            As[col + 2][row] = a.z;
            As[col + 3][row] = a.w;
        }
        // load B tile 16x128. 512 float4, 2 per thread.
#pragma unroll
        for (int t = 0; t < 2; t++) {
            int id  = tid + 256 * t;
            int row = id >> 5;            // 0..15
            int col = (id & 31) * 4;      // 0..124
            *(float4*)&Bs[row][col] = *(const float4*)(Bb + (size_t)(k0 + row) * N + col);
        }
        __syncthreads();

#pragma unroll
        for (int kk = 0; kk < GBK; kk++) {
            float4 a0 = *(float4*)&As[kk][trow];
            float4 a1 = *(float4*)&As[kk][trow + 4];
            float4 b0 = *(float4*)&Bs[kk][tcol];
            float4 b1 = *(float4*)&Bs[kk][tcol + 4];
            float ar[8] = {a0.x, a0.y, a0.z, a0.w, a1.x, a1.y, a1.z, a1.w};
            float br[8] = {b0.x, b0.y, b0.z, b0.w, b1.x, b1.y, b1.z, b1.w};
#pragma unroll
            for (int i = 0; i < 8; i++)
#pragma unroll
                for (int j = 0; j < 8; j++) acc[i][j] += ar[i] * br[j];
        }
        __syncthreads();
    }

    // epilogue with bias
#pragma unroll
    for (int i = 0; i < 8; i++) {
        size_t r = (size_t)brow * GBM + trow + i;
        float* crow = C + r * N + (size_t)bcol * GBN + tcol;
        const float* brow_b = bias + (size_t)bcol * GBN + tcol;
#pragma unroll
        for (int j = 0; j < 8; j += 4) {
            float4 o;
            o.x = acc[i][j + 0] + brow_b[j + 0];
            o.y = acc[i][j + 1] + brow_b[j + 1];
            o.z = acc[i][j + 2] + brow_b[j + 2];
            o.w = acc[i][j + 3] + brow_b[j + 3];
            *(float4*)(crow + j) = o;
        }
    }
}

// ---------------- BatchNorm (training-mode, over rows) ----------------
// stage 1: per-column sum & sumsq (block = 8 rows x 32 cols)
__global__ void col_stats(const float* __restrict__ X, int rows, int cols,
                          float* __restrict__ stats) {
    int lane  = threadIdx.x & 31;
    int rlane = threadIdx.x >> 5;    // 0..7
    int c = blockIdx.x * 32 + lane;
    float s = 0.f, q = 0.f;
    for (int r = blockIdx.y * 8 + rlane; r < rows; r += gridDim.y * 8) {
        float v = X[(size_t)r * cols + c];
        s += v; q += v * v;
    }
    __shared__ float shs[8][33];
    __shared__ float shq[8][33];
    shs[rlane][lane] = s;
    shq[rlane][lane] = q;
    __syncthreads();
    if (rlane == 0) {
#pragma unroll
        for (int i = 1; i < 8; i++) { s += shs[i][lane]; q += shq[i][lane]; }
        atomicAdd(&stats[c], s);
        atomicAdd(&stats[1024 + c], q);
    }
}

// stage 2: stats -> scale/shift in place
__global__ void bn_prep(float* __restrict__ stats, int cols, float inv_rows,
                        const float* __restrict__ g, const float* __restrict__ b) {
    int c = blockIdx.x * blockDim.x + threadIdx.x;
    if (c >= cols) return;
    float m   = stats[c] * inv_rows;
    float var = stats[1024 + c] * inv_rows - m * m;
    float sc  = g[c] * rsqrtf(var + EPSV);
    stats[c] = sc;
    stats[1024 + c] = b[c] - m * sc;
}

// stage 3a: elementwise apply + relu (vectorized)
__global__ void bn_relu(const float* __restrict__ X, float* __restrict__ Y,
                        size_t total4, int cols, const float* __restrict__ stats) {
    size_t i = (size_t)blockIdx.x * blockDim.x + threadIdx.x;
    if (i >= total4) return;
    int c = (int)((i * 4) % cols);
    float4 x = ((const float4*)X)[i];
    float4 y;
    y.x = fmaxf(0.f, x.x * stats[c + 0] + stats[1024 + c + 0]);
    y.y = fmaxf(0.f, x.y * stats[c + 1] + stats[1024 + c + 1]);
    y.z = fmaxf(0.f, x.z * stats[c + 2] + stats[1024 + c + 2]);
    y.w = fmaxf(0.f, x.w * stats[c + 3] + stats[1024 + c + 3]);
    ((float4*)Y)[i] = y;
}

// stage 3b (edge path): bn+relu on ee, then agg[dst] += z[src] + ee  (scatter)
__global__ void bn_scatter(const float* __restrict__ ee, const float* __restrict__ stats,
                           const float* __restrict__ z, const int* __restrict__ eidx,
                           float* __restrict__ agg) {
    int e = blockIdx.x;
    int s = eidx[e];
    int d = eidx[EE + e];
    const float* eer = ee + (size_t)e * HH;
    const float* zr  = z  + (size_t)s * HH;
    float* ar        = agg + (size_t)d * HH;
    for (int c = threadIdx.x; c < HH; c += blockDim.x) {
        float v = fmaxf(0.f, eer[c] * stats[c] + stats[1024 + c]);
        atomicAdd(&ar[c], zr[c] + v);
    }
}

// ---------------- pooling ----------------
// v[j] = sum_h gapW[j,h]*attW[h];  v[1024] = sum_h gapB[h]*attW[h] + attB
__global__ void att_vec(const float* __restrict__ gapW, const float* __restrict__ gapB,
                        const float* __restrict__ attW, const float* __restrict__ attB,
                        float* __restrict__ v) {
    int w = blockIdx.x * (blockDim.x / 32) + (threadIdx.x / 32);
    int lane = threadIdx.x & 31;
    if (w > OUTD) return;
    const float* row = (w < OUTD) ? (gapW + (size_t)w * HH) : gapB;
    float acc = 0.f;
    for (int h = lane; h < HH; h += 32) acc += row[h] * attW[h];
#pragma unroll
    for (int o = 16; o; o >>= 1) acc += __shfl_xor_sync(0xffffffffu, acc, o);
    if (lane == 0) v[w] = acc + ((w == OUTD) ? attB[0] : 0.f);
}

// per-graph: att = zout . v + c, softmax over 32 nodes, weighted sum -> hg[b]
__global__ void pool(const float* __restrict__ zout, const float* __restrict__ v,
                     float* __restrict__ hg) {
    __shared__ float satt[NPG];
    __shared__ float salpha[NPG];
    int b = blockIdx.x;
    int warp = threadIdx.x / 32, lane = threadIdx.x & 31;
    const float cst = v[OUTD];
    for (int n = warp; n < NPG; n += 8) {
        const float* row = zout + ((size_t)b * NPG + n) * OUTD;
        float acc = 0.f;
        for (int k = lane; k < OUTD; k += 32) acc += row[k] * v[k];
#pragma unroll
        for (int o = 16; o; o >>= 1) acc += __shfl_xor_sync(0xffffffffu, acc, o);
        if (lane == 0) satt[n] = acc + cst;
    }
    __syncthreads();
    if (threadIdx.x < 32) {
        float a = satt[threadIdx.x];
        float mx = a;
#pragma unroll
        for (int o = 16; o; o >>= 1) mx = fmaxf(mx, __shfl_xor_sync(0xffffffffu, mx, o));
        float ex = expf(a - mx);
        float s = ex;
#pragma unroll
        for (int o = 16; o; o >>= 1) s += __shfl_xor_sync(0xffffffffu, s, o);
        salpha[threadIdx.x] = ex / s;
    }
    __syncthreads();
    for (int j = threadIdx.x; j < OUTD; j += 256) {
        float acc = 0.f;
#pragma unroll
        for (int n = 0; n < NPG; n++)
            acc += salpha[n] * zout[((size_t)b * NPG + n) * OUTD + j];
        hg[(size_t)b * OUTD + j] = acc;
    }
}

// ---------------- host orchestration ----------------
extern "C" void kernel_launch(void* const* d_in, const int* in_sizes, int n_in,
                              void* d_out, int out_size) {
    const int*   x        = (const int*)  d_in[0];
    const int*   edgeattr = (const int*)  d_in[1];
    const int*   eidx     = (const int*)  d_in[2];
    // d_in[3] = batch (implicit: arange/NPG)
    const float* node_tab = (const float*)d_in[4];
    const float* edge_tab = (const float*)d_in[5];
    const float* bondW    = (const float*)d_in[6];
    const float* bondB    = (const float*)d_in[7];
    const float* bondG    = (const float*)d_in[8];
    const float* bondBeta = (const float*)d_in[9];
    const float* atomW1   = (const float*)d_in[10];
    const float* atomB1   = (const float*)d_in[11];
    const float* atomG    = (const float*)d_in[12];
    const float* atomBeta = (const float*)d_in[13];
    const float* atomW2   = (const float*)d_in[14];
    const float* atomB2   = (const float*)d_in[15];
    const float* normG    = (const float*)d_in[16];
    const float* normB    = (const float*)d_in[17];
    const float* outW     = (const float*)d_in[18];
    const float* outB     = (const float*)d_in[19];
    const float* gapW     = (const float*)d_in[20];
    const float* gapB     = (const float*)d_in[21];
    const float* attW     = (const float*)d_in[22];
    const float* attB     = (const float*)d_in[23];
    const float* projW    = (const float*)d_in[24];
    const float* projB    = (const float*)d_in[25];
    float* out = (float*)d_out;

    float *p_z, *p_agg, *p_eemb, *p_ee, *p_h, *p_zpre, *p_zout, *p_v, *p_hg, *p_stats;
    cudaGetSymbolAddress((void**)&p_z, g_z);
    cudaGetSymbolAddress((void**)&p_agg, g_agg);
    cudaGetSymbolAddress((void**)&p_eemb, g_eemb);
    cudaGetSymbolAddress((void**)&p_ee, g_ee);
    cudaGetSymbolAddress((void**)&p_h, g_h);
    cudaGetSymbolAddress((void**)&p_zpre, g_zpre);
    cudaGetSymbolAddress((void**)&p_zout, g_zout);
    cudaGetSymbolAddress((void**)&p_v, g_v);
    cudaGetSymbolAddress((void**)&p_hg, g_hg);
    cudaGetSymbolAddress((void**)&p_stats, g_stats);

    // embeddings
    embed_nodes<<<NN, 256>>>(x, node_tab, p_z);
    embed_edges<<<EE, 128>>>(edgeattr, edge_tab, p_eemb);

    for (int l = 0; l < LL; l++) {
        const float* bW  = bondW    + (size_t)l * HEH * HH;
        const float* bB  = bondB    + (size_t)l * HH;
        const float* bG  = bondG    + (size_t)l * HH;
        const float* bBe = bondBeta + (size_t)l * HH;
        const float* aW1 = atomW1   + (size_t)l * HH * H2;
        const float* aB1 = atomB1   + (size_t)l * H2;
        const float* aG  = atomG    + (size_t)l * H2;
        const float* aBe = atomBeta + (size_t)l * H2;
        const float* aW2 = atomW2   + (size_t)l * H2 * HH;
        const float* aB2 = atomB2   + (size_t)l * HH;
        const float* nG  = normG    + (size_t)l * HH;
        const float* nB  = normB    + (size_t)l * HH;

        // ee_pre = e_emb @ bW + bB    [E, 512]
        sgemm<false><<<dim3(HH / GBN, EE / GBM), 256>>>(EE, HH, HEH, p_eemb, nullptr, bW, bB, p_ee);
        // BN stats over E rows
        cudaMemsetAsync(p_stats, 0, 2048 * sizeof(float));
        col_stats<<<dim3(HH / 32, 128), 256>>>(p_ee, EE, HH, p_stats);
        bn_prep<<<(HH + 255) / 256, 256>>>(p_stats, HH, 1.f / EE, bG, bBe);
        // agg = segsum(z[src] + relu(bn(ee)))
        cudaMemsetAsync(p_agg, 0, (size_t)NN * HH * sizeof(float));
        bn_scatter<<<EE, 256>>>(p_ee, p_stats, p_z, eidx, p_agg);

        // h_pre = (z + agg) @ aW1 + aB1    [N, 1024]
        sgemm<true><<<dim3(H2 / GBN, NN / GBM), 256>>>(NN, H2, HH, p_agg, p_z, aW1, aB1, p_h);
        cudaMemsetAsync(p_stats, 0, 2048 * sizeof(float));
        col_stats<<<dim3(H2 / 32, 64), 256>>>(p_h, NN, H2, p_stats);
        bn_prep<<<(H2 + 255) / 256, 256>>>(p_stats, H2, 1.f / NN, aG, aBe);
        bn_relu<<<(unsigned)(((size_t)NN * H2 / 4 + 255) / 256), 256>>>(p_h, p_h, (size_t)NN * H2 / 4, H2, p_stats);

        // z_pre = h @ aW2 + aB2    [N, 512]
        sgemm<false><<<dim3(HH / GBN, NN / GBM), 256>>>(NN, HH, H2, p_h, nullptr, aW2, aB2, p_zpre);
        cudaMemsetAsync(p_stats, 0, 2048 * sizeof(float));
        col_stats<<<dim3(HH / 32, 64), 256>>>(p_zpre, NN, HH, p_stats);
        bn_prep<<<(HH + 255) / 256, 256>>>(p_stats, HH, 1.f / NN, nG, nB);
        bn_relu<<<(unsigned)(((size_t)NN * HH / 4 + 255) / 256), 256>>>(p_zpre, p_z, (size_t)NN * HH / 4, HH, p_stats);
    }

    // zout = z @ outW + outB    [N, 1024]
    sgemm<false><<<dim3(OUTD / GBN, NN / GBM), 256>>>(NN, OUTD, HH, p_z, nullptr, outW, outB, p_zout);

    // attention pooling (gapW@attW folded into vector v)
    att_vec<<<129, 256>>>(gapW, gapB, attW, attB, p_v);
    pool<<<BB, 256>>>(p_zout, p_v, p_hg);

    // out = hg @ projW + projB    [B, OUT]
    sgemm<false><<<dim3(OUTD / GBN, BB / GBM), 256>>>(BB, OUTD, OUTD, p_hg, nullptr, projW, projB, out);
}

// round 3
// speedup vs baseline: 1.7919x; 1.7919x over previous
#include <cuda_runtime.h>
#include <cuda_bf16.h>
#include <cstdint>

// ---------------- problem constants ----------------
#define NN      32768
#define EE      131072
#define HH      512
#define HEH     128
#define H2      1024
#define OUTD    1024
#define BB      1024
#define NPG     32
#define LL      6
#define EPSV    1e-5f

__device__ __constant__ int c_node_off[9] = {0,119,128,139,151,160,165,173,175};
__device__ __constant__ int c_edge_off[3] = {0,119,128};

// ---------------- scratch (device globals; no allocs allowed) ----------------
__device__ float g_z   [(size_t)NN * HH];
__device__ float g_agg [(size_t)NN * HH];
__device__ float g_eemb[(size_t)EE * HEH];
__device__ float g_ee  [(size_t)EE * HH];
__device__ float g_h   [(size_t)NN * H2];
__device__ float g_zpre[(size_t)NN * HH];
__device__ float g_zout[(size_t)NN * OUTD];
__device__ float g_v   [OUTD + 1];
__device__ float g_hg  [(size_t)BB * OUTD];
__device__ float g_stats[2048];
// transposed weights [N, K] fp32
__device__ float g_bondWt [(size_t)LL * HH * HEH];
__device__ float g_atomW1t[(size_t)LL * H2 * HH];
__device__ float g_atomW2t[(size_t)LL * HH * H2];
__device__ float g_outWt  [(size_t)OUTD * HH];
__device__ float g_projWt [(size_t)OUTD * OUTD];

// ---------------- mma.sync helpers (sm_80+, legal on plain sm_103 target) ----------------
__device__ __forceinline__ uint32_t smem_u32(const void* p) {
    uint32_t a;
    asm("{ .reg .u64 t; cvta.to.shared.u64 t, %1; cvt.u32.u64 %0, t; }" : "=r"(a) : "l"(p));
    return a;
}
__device__ __forceinline__ void ldm_x4(uint32_t* r, uint32_t addr) {
    asm volatile("ldmatrix.sync.aligned.m8n8.x4.shared.b16 {%0,%1,%2,%3}, [%4];"
                 : "=r"(r[0]), "=r"(r[1]), "=r"(r[2]), "=r"(r[3]) : "r"(addr));
}
__device__ __forceinline__ void mma_bf16(float* c, const uint32_t* a, const uint32_t* b) {
    asm volatile("mma.sync.aligned.m16n8k16.row.col.f32.bf16.bf16.f32 "
                 "{%0,%1,%2,%3}, {%4,%5,%6,%7}, {%8,%9}, {%0,%1,%2,%3};"
                 : "+f"(c[0]), "+f"(c[1]), "+f"(c[2]), "+f"(c[3])
                 : "r"(a[0]), "r"(a[1]), "r"(a[2]), "r"(a[3]), "r"(b[0]), "r"(b[1]));
}

__device__ __forceinline__ uint32_t pk(__nv_bfloat16 a, __nv_bfloat16 b) {
    return (uint32_t)__bfloat16_as_ushort(a) | ((uint32_t)__bfloat16_as_ushort(b) << 16);
}

// SMEM tile layout: 128 rows x 32 bf16, padded row stride 80 bytes (conflict-free ldmatrix)
#define ROWB 80

__device__ __forceinline__ void store_split(char* th, char* tl, int row, int c4, float4 v) {
    __nv_bfloat16 h0 = __float2bfloat16(v.x), h1 = __float2bfloat16(v.y);
    __nv_bfloat16 h2 = __float2bfloat16(v.z), h3 = __float2bfloat16(v.w);
    __nv_bfloat16 l0 = __float2bfloat16(v.x - __bfloat162float(h0));
    __nv_bfloat16 l1 = __float2bfloat16(v.y - __bfloat162float(h1));
    __nv_bfloat16 l2 = __float2bfloat16(v.z - __bfloat162float(h2));
    __nv_bfloat16 l3 = __float2bfloat16(v.w - __bfloat162float(h3));
    uint32_t off = (uint32_t)(row * ROWB + c4 * 8);
    *(uint2*)(th + off) = make_uint2(pk(h0, h1), pk(h2, h3));
    *(uint2*)(tl + off) = make_uint2(pk(l0, l1), pk(l2, l3));
}

// ---------------- tensor-core GEMM: C[M,N] = (A [+A2])[M,K] @ Bt[N,K]^T + bias ----------------
// 128x128 tile, BK=32, 256 threads (8 warps, 2x4), warp tile 64x32.
// 3-product bf16 split: Ah*Bh + Ah*Bl + Al*Bh.
template <bool ADDA2>
__global__ void __launch_bounds__(256)
gemm_mma(int N, int K,
         const float* __restrict__ A, const float* __restrict__ A2,
         const float* __restrict__ Bt, const float* __restrict__ bias,
         float* __restrict__ C) {
    __shared__ char sAh[128 * ROWB];
    __shared__ char sAl[128 * ROWB];
    __shared__ char sBh[128 * ROWB];
    __shared__ char sBl[128 * ROWB];

    const int tid = threadIdx.x, lane = tid & 31, wid = tid >> 5;
    const int wr = wid >> 2, wc = wid & 3;           // warp row (0..1), col (0..3)
    const int brow = blockIdx.y, bcol = blockIdx.x;

    const uint32_t uAh = smem_u32(sAh), uAl = smem_u32(sAl);
    const uint32_t uBh = smem_u32(sBh), uBl = smem_u32(sBl);

    const float* Ab  = A + (size_t)brow * 128 * K;
    const float* A2b = ADDA2 ? (A2 + (size_t)brow * 128 * K) : nullptr;
    const float* Bb  = Bt + (size_t)bcol * 128 * K;

    float acc[4][4][4];
#pragma unroll
    for (int i = 0; i < 4; i++)
#pragma unroll
        for (int j = 0; j < 4; j++)
#pragma unroll
            for (int q = 0; q < 4; q++) acc[i][j][q] = 0.f;

    // ldmatrix lane address components (constant across k-loop)
    const int a_row = (lane & 15);            // + row0
    const int a_half = (lane >> 4) * 16;      // byte offset within 32-byte k-chunk
    const int b_row = (lane & 7) + ((lane >> 4) << 3);
    const int b_half = ((lane >> 3) & 1) * 16;

    for (int k0 = 0; k0 < K; k0 += 32) {
        // ---- load & split 128x32 fp32 -> bf16 hi/lo (A and B) ----
        const float* ga  = Ab + k0;
        const float* ga2 = ADDA2 ? (A2b + k0) : nullptr;
        const float* gb  = Bb + k0;
#pragma unroll
        for (int t = 0; t < 4; t++) {
            int id = tid + 256 * t;
            int row = id >> 3, c4 = id & 7;
            float4 v = *(const float4*)(ga + (size_t)row * K + c4 * 4);
            if (ADDA2) {
                float4 w = *(const float4*)(ga2 + (size_t)row * K + c4 * 4);
                v.x += w.x; v.y += w.y; v.z += w.z; v.w += w.w;
            }
            store_split(sAh, sAl, row, c4, v);
        }
#pragma unroll
        for (int t = 0; t < 4; t++) {
            int id = tid + 256 * t;
            int row = id >> 3, c4 = id & 7;
            float4 v = *(const float4*)(gb + (size_t)row * K + c4 * 4);
            store_split(sBh, sBl, row, c4, v);
        }
        __syncthreads();

#pragma unroll
        for (int ks = 0; ks < 2; ks++) {
            const int kb = ks * 32;   // byte offset of 16-col k-step (16 bf16 = 32B)
            uint32_t ah[4][4], al[4][4];
#pragma unroll
            for (int mt = 0; mt < 4; mt++) {
                int row0 = wr * 64 + mt * 16;
                uint32_t off = (uint32_t)((row0 + a_row) * ROWB + kb + a_half);
                ldm_x4(ah[mt], uAh + off);
                ldm_x4(al[mt], uAl + off);
            }
            uint32_t bh[4][2], bl[4][2];
#pragma unroll
            for (int np = 0; np < 2; np++) {  // pairs of n-tiles via x4
                int n0 = wc * 32 + np * 16;
                uint32_t off = (uint32_t)((n0 + b_row) * ROWB + kb + b_half);
                uint32_t r[4];
                ldm_x4(r, uBh + off);
                bh[np * 2][0] = r[0]; bh[np * 2][1] = r[1];
                bh[np * 2 + 1][0] = r[2]; bh[np * 2 + 1][1] = r[3];
                ldm_x4(r, uBl + off);
                bl[np * 2][0] = r[0]; bl[np * 2][1] = r[1];
                bl[np * 2 + 1][0] = r[2]; bl[np * 2 + 1][1] = r[3];
            }
#pragma unroll
            for (int mt = 0; mt < 4; mt++)
#pragma unroll
                for (int nt = 0; nt < 4; nt++) {
                    mma_bf16(acc[mt][nt], ah[mt], bh[nt]);
                    mma_bf16(acc[mt][nt], ah[mt], bl[nt]);
                    mma_bf16(acc[mt][nt], al[mt], bh[nt]);
                }
        }
        __syncthreads();
    }

    // ---- epilogue: add bias, store fp32 ----
#pragma unroll
    for (int mt = 0; mt < 4; mt++) {
        int row0 = brow * 128 + wr * 64 + mt * 16 + (lane >> 2);
#pragma unroll
        for (int nt = 0; nt < 4; nt++) {
            int col = bcol * 128 + wc * 32 + nt * 8 + (lane & 3) * 2;
            float b0 = bias[col], b1 = bias[col + 1];
            float2 o0 = make_float2(acc[mt][nt][0] + b0, acc[mt][nt][1] + b1);
            float2 o1 = make_float2(acc[mt][nt][2] + b0, acc[mt][nt][3] + b1);
            *(float2*)(C + (size_t)row0 * N + col) = o0;
            *(float2*)(C + (size_t)(row0 + 8) * N + col) = o1;
        }
    }
}

// ---------------- weight transpose: S[K,N] -> D[N,K] ----------------
__global__ void transpose_f32(const float* __restrict__ S, float* __restrict__ D, int K, int N) {
    __shared__ float t[32][33];
    int k0 = blockIdx.y * 32, n0 = blockIdx.x * 32;
    int x = threadIdx.x, y = threadIdx.y;
#pragma unroll
    for (int i = 0; i < 32; i += 8) t[y + i][x] = S[(size_t)(k0 + y + i) * N + n0 + x];
    __syncthreads();
#pragma unroll
    for (int i = 0; i < 32; i += 8) D[(size_t)(n0 + y + i) * K + k0 + x] = t[x][y + i];
}

// ---------------- embedding kernels ----------------
__global__ void embed_nodes(const int* __restrict__ x, const float* __restrict__ tab,
                            float* __restrict__ z) {
    int n = blockIdx.x;
    __shared__ int idx[9];
    if (threadIdx.x < 9) idx[threadIdx.x] = x[n * 9 + threadIdx.x] + c_node_off[threadIdx.x];
    __syncthreads();
    for (int c = threadIdx.x; c < HH; c += blockDim.x) {
        float acc = 0.f;
#pragma unroll
        for (int f = 0; f < 9; f++) acc += tab[(size_t)idx[f] * HH + c];
        z[(size_t)n * HH + c] = acc;
    }
}

__global__ void embed_edges(const int* __restrict__ ea, const float* __restrict__ tab,
                            float* __restrict__ out) {
    int e = blockIdx.x;
    __shared__ int idx[3];
    if (threadIdx.x < 3) idx[threadIdx.x] = ea[e * 3 + threadIdx.x] + c_edge_off[threadIdx.x];
    __syncthreads();
    for (int c = threadIdx.x; c < HEH; c += blockDim.x) {
        float acc = 0.f;
#pragma unroll
        for (int f = 0; f < 3; f++) acc += tab[(size_t)idx[f] * HEH + c];
        out[(size_t)e * HEH + c] = acc;
    }
}

// ---------------- BatchNorm ----------------
__global__ void col_stats(const float* __restrict__ X, int rows, int cols,
                          float* __restrict__ stats) {
    int lane = threadIdx.x & 31;
    int rlane = threadIdx.x >> 5;
    int c = blockIdx.x * 32 + lane;
    float s = 0.f, q = 0.f;
    for (int r = blockIdx.y * 8 + rlane; r < rows; r += gridDim.y * 8) {
        float v = X[(size_t)r * cols + c];
        s += v; q += v * v;
    }
    __shared__ float shs[8][33];
    __shared__ float shq[8][33];
    shs[rlane][lane] = s;
    shq[rlane][lane] = q;
    __syncthreads();
    if (rlane == 0) {
#pragma unroll
        for (int i = 1; i < 8; i++) { s += shs[i][lane]; q += shq[i][lane]; }
        atomicAdd(&stats[c], s);
        atomicAdd(&stats[1024 + c], q);
    }
}

__global__ void bn_prep(float* __restrict__ stats, int cols, float inv_rows,
                        const float* __restrict__ g, const float* __restrict__ b) {
    int c = blockIdx.x * blockDim.x + threadIdx.x;
    if (c >= cols) return;
    float m = stats[c] * inv_rows;
    float var = stats[1024 + c] * inv_rows - m * m;
    float sc = g[c] * rsqrtf(var + EPSV);
    stats[c] = sc;
    stats[1024 + c] = b[c] - m * sc;
}

__global__ void bn_relu(const float* __restrict__ X, float* __restrict__ Y,
                        size_t total4, int cols, const float* __restrict__ stats) {
    size_t i = (size_t)blockIdx.x * blockDim.x + threadIdx.x;
    if (i >= total4) return;
    int c = (int)((i * 4) % cols);
    float4 x = ((const float4*)X)[i];
    float4 y;
    y.x = fmaxf(0.f, x.x * stats[c + 0] + stats[1024 + c + 0]);
    y.y = fmaxf(0.f, x.y * stats[c + 1] + stats[1024 + c + 1]);
    y.z = fmaxf(0.f, x.z * stats[c + 2] + stats[1024 + c + 2]);
    y.w = fmaxf(0.f, x.w * stats[c + 3] + stats[1024 + c + 3]);
    ((float4*)Y)[i] = y;
}

__global__ void bn_scatter(const float* __restrict__ ee, const float* __restrict__ stats,
                           const float* __restrict__ z, const int* __restrict__ eidx,
                           float* __restrict__ agg) {
    int e = blockIdx.x;
    int s = eidx[e];
    int d = eidx[EE + e];
    const float* eer = ee + (size_t)e * HH;
    const float* zr  = z + (size_t)s * HH;
    float* ar = agg + (size_t)d * HH;
    for (int c = threadIdx.x; c < HH; c += blockDim.x) {
        float v = fmaxf(0.f, eer[c] * stats[c] + stats[1024 + c]);
        atomicAdd(&ar[c], zr[c] + v);
    }
}

// ---------------- pooling ----------------
__global__ void att_vec(const float* __restrict__ gapW, const float* __restrict__ gapB,
                        const float* __restrict__ attW, const float* __restrict__ attB,
                        float* __restrict__ v) {
    int w = blockIdx.x * (blockDim.x / 32) + (threadIdx.x / 32);
    int lane = threadIdx.x & 31;
    if (w > OUTD) return;
    const float* row = (w < OUTD) ? (gapW + (size_t)w * HH) : gapB;
    float acc = 0.f;
    for (int h = lane; h < HH; h += 32) acc += row[h] * attW[h];
#pragma unroll
    for (int o = 16; o; o >>= 1) acc += __shfl_xor_sync(0xffffffffu, acc, o);
    if (lane == 0) v[w] = acc + ((w == OUTD) ? attB[0] : 0.f);
}

__global__ void pool(const float* __restrict__ zout, const float* __restrict__ v,
                     float* __restrict__ hg) {
    __shared__ float satt[NPG];
    __shared__ float salpha[NPG];
    int b = blockIdx.x;
    int warp = threadIdx.x / 32, lane = threadIdx.x & 31;
    const float cst = v[OUTD];
    for (int n = warp; n < NPG; n += 8) {
        const float* row = zout + ((size_t)b * NPG + n) * OUTD;
        float acc = 0.f;
        for (int k = lane; k < OUTD; k += 32) acc += row[k] * v[k];
#pragma unroll
        for (int o = 16; o; o >>= 1) acc += __shfl_xor_sync(0xffffffffu, acc, o);
        if (lane == 0) satt[n] = acc + cst;
    }
    __syncthreads();
    if (threadIdx.x < 32) {
        float a = satt[threadIdx.x];
        float mx = a;
#pragma unroll
        for (int o = 16; o; o >>= 1) mx = fmaxf(mx, __shfl_xor_sync(0xffffffffu, mx, o));
        float ex = expf(a - mx);
        float s = ex;
#pragma unroll
        for (int o = 16; o; o >>= 1) s += __shfl_xor_sync(0xffffffffu, s, o);
        salpha[threadIdx.x] = ex / s;
    }
    __syncthreads();
    for (int j = threadIdx.x; j < OUTD; j += 256) {
        float acc = 0.f;
#pragma unroll
        for (int n = 0; n < NPG; n++)
            acc += salpha[n] * zout[((size_t)b * NPG + n) * OUTD + j];
        hg[(size_t)b * OUTD + j] = acc;
    }
}

// ---------------- host orchestration ----------------
extern "C" void kernel_launch(void* const* d_in, const int* in_sizes, int n_in,
                              void* d_out, int out_size) {
    const int*   x        = (const int*)  d_in[0];
    const int*   edgeattr = (const int*)  d_in[1];
    const int*   eidx     = (const int*)  d_in[2];
    const float* node_tab = (const float*)d_in[4];
    const float* edge_tab = (const float*)d_in[5];
    const float* bondW    = (const float*)d_in[6];
    const float* bondB    = (const float*)d_in[7];
    const float* bondG    = (const float*)d_in[8];
    const float* bondBeta = (const float*)d_in[9];
    const float* atomW1   = (const float*)d_in[10];
    const float* atomB1   = (const float*)d_in[11];
    const float* atomG    = (const float*)d_in[12];
    const float* atomBeta = (const float*)d_in[13];
    const float* atomW2   = (const float*)d_in[14];
    const float* atomB2   = (const float*)d_in[15];
    const float* normG    = (const float*)d_in[16];
    const float* normB    = (const float*)d_in[17];
    const float* outW     = (const float*)d_in[18];
    const float* outB     = (const float*)d_in[19];
    const float* gapW     = (const float*)d_in[20];
    const float* gapB     = (const float*)d_in[21];
    const float* attW     = (const float*)d_in[22];
    const float* attB     = (const float*)d_in[23];
    const float* projW    = (const float*)d_in[24];
    const float* projB    = (const float*)d_in[25];
    float* out = (float*)d_out;

    float *p_z, *p_agg, *p_eemb, *p_ee, *p_h, *p_zpre, *p_zout, *p_v, *p_hg, *p_stats;
    float *p_bondWt, *p_atomW1t, *p_atomW2t, *p_outWt, *p_projWt;
    cudaGetSymbolAddress((void**)&p_z, g_z);
    cudaGetSymbolAddress((void**)&p_agg, g_agg);
    cudaGetSymbolAddress((void**)&p_eemb, g_eemb);
    cudaGetSymbolAddress((void**)&p_ee, g_ee);
    cudaGetSymbolAddress((void**)&p_h, g_h);
    cudaGetSymbolAddress((void**)&p_zpre, g_zpre);
    cudaGetSymbolAddress((void**)&p_zout, g_zout);
    cudaGetSymbolAddress((void**)&p_v, g_v);
    cudaGetSymbolAddress((void**)&p_hg, g_hg);
    cudaGetSymbolAddress((void**)&p_stats, g_stats);
    cudaGetSymbolAddress((void**)&p_bondWt, g_bondWt);
    cudaGetSymbolAddress((void**)&p_atomW1t, g_atomW1t);
    cudaGetSymbolAddress((void**)&p_atomW2t, g_atomW2t);
    cudaGetSymbolAddress((void**)&p_outWt, g_outWt);
    cudaGetSymbolAddress((void**)&p_projWt, g_projWt);

    // weight transposes [K,N] -> [N,K]
    for (int l = 0; l < LL; l++) {
        transpose_f32<<<dim3(HH / 32, HEH / 32), dim3(32, 8)>>>(
            bondW + (size_t)l * HEH * HH, p_bondWt + (size_t)l * HH * HEH, HEH, HH);
        transpose_f32<<<dim3(H2 / 32, HH / 32), dim3(32, 8)>>>(
            atomW1 + (size_t)l * HH * H2, p_atomW1t + (size_t)l * H2 * HH, HH, H2);
        transpose_f32<<<dim3(HH / 32, H2 / 32), dim3(32, 8)>>>(
            atomW2 + (size_t)l * H2 * HH, p_atomW2t + (size_t)l * HH * H2, H2, HH);
    }
    transpose_f32<<<dim3(OUTD / 32, HH / 32), dim3(32, 8)>>>(outW, p_outWt, HH, OUTD);
    transpose_f32<<<dim3(OUTD / 32, OUTD / 32), dim3(32, 8)>>>(projW, p_projWt, OUTD, OUTD);

    // embeddings
    embed_nodes<<<NN, 256>>>(x, node_tab, p_z);
    embed_edges<<<EE, 128>>>(edgeattr, edge_tab, p_eemb);

    for (int l = 0; l < LL; l++) {
        const float* bWt  = p_bondWt  + (size_t)l * HH * HEH;
        const float* bB   = bondB     + (size_t)l * HH;
        const float* bG   = bondG     + (size_t)l * HH;
        const float* bBe  = bondBeta  + (size_t)l * HH;
        const float* aW1t = p_atomW1t + (size_t)l * H2 * HH;
        const float* aB1  = atomB1    + (size_t)l * H2;
        const float* aG   = atomG     + (size_t)l * H2;
        const float* aBe  = atomBeta  + (size_t)l * H2;
        const float* aW2t = p_atomW2t + (size_t)l * HH * H2;
        const float* aB2  = atomB2    + (size_t)l * HH;
        const float* nG   = normG     + (size_t)l * HH;
        const float* nB   = normB     + (size_t)l * HH;

        // ee_pre = e_emb @ bW + bB   [E, 512], K=128
        gemm_mma<false><<<dim3(HH / 128, EE / 128), 256>>>(HH, HEH, p_eemb, nullptr, bWt, bB, p_ee);
        cudaMemsetAsync(p_stats, 0, 2048 * sizeof(float));
        col_stats<<<dim3(HH / 32, 128), 256>>>(p_ee, EE, HH, p_stats);
        bn_prep<<<(HH + 255) / 256, 256>>>(p_stats, HH, 1.f / EE, bG, bBe);
        cudaMemsetAsync(p_agg, 0, (size_t)NN * HH * sizeof(float));
        bn_scatter<<<EE, 256>>>(p_ee, p_stats, p_z, eidx, p_agg);

        // h_pre = (z + agg) @ aW1 + aB1   [N, 1024], K=512
        gemm_mma<true><<<dim3(H2 / 128, NN / 128), 256>>>(H2, HH, p_agg, p_z, aW1t, aB1, p_h);
        cudaMemsetAsync(p_stats, 0, 2048 * sizeof(float));
        col_stats<<<dim3(H2 / 32, 64), 256>>>(p_h, NN, H2, p_stats);
        bn_prep<<<(H2 + 255) / 256, 256>>>(p_stats, H2, 1.f / NN, aG, aBe);
        bn_relu<<<(unsigned)(((size_t)NN * H2 / 4 + 255) / 256), 256>>>(p_h, p_h, (size_t)NN * H2 / 4, H2, p_stats);

        // z_pre = h @ aW2 + aB2   [N, 512], K=1024
        gemm_mma<false><<<dim3(HH / 128, NN / 128), 256>>>(HH, H2, p_h, nullptr, aW2t, aB2, p_zpre);
        cudaMemsetAsync(p_stats, 0, 2048 * sizeof(float));
        col_stats<<<dim3(HH / 32, 64), 256>>>(p_zpre, NN, HH, p_stats);
        bn_prep<<<(HH + 255) / 256, 256>>>(p_stats, HH, 1.f / NN, nG, nB);
        bn_relu<<<(unsigned)(((size_t)NN * HH / 4 + 255) / 256), 256>>>(p_zpre, p_z, (size_t)NN * HH / 4, HH, p_stats);
    }

    // zout = z @ outW + outB   [N, 1024], K=512
    gemm_mma<false><<<dim3(OUTD / 128, NN / 128), 256>>>(OUTD, HH, p_z, nullptr, p_outWt, outB, p_zout);

    att_vec<<<129, 256>>>(gapW, gapB, attW, attB, p_v);
    pool<<<BB, 256>>>(p_zout, p_v, p_hg);

    // out = hg @ projW + projB   [B, OUT], K=1024
    gemm_mma<false><<<dim3(OUTD / 128, BB / 128), 256>>>(OUTD, OUTD, p_hg, nullptr, p_projWt, projB, out);
}

// round 4
// speedup vs baseline: 1.9609x; 1.0943x over previous
#include <cuda_runtime.h>
#include <cuda_bf16.h>
#include <cstdint>

// ---------------- problem constants ----------------
#define NN      32768
#define EE      131072
#define HH      512
#define HEH     128
#define H2      1024
#define OUTD    1024
#define BB      1024
#define NPG     32
#define LL      6
#define EPSV    1e-5f
#define NCOMBO  264        // 22*6*2 distinct edge-attr combos

__device__ __constant__ int c_node_off[9] = {0,119,128,139,151,160,165,173,175};

// ---------------- scratch (device globals; no allocs allowed) ----------------
__device__ float g_z    [(size_t)NN * HH];
__device__ float g_agg  [(size_t)NN * HH];
__device__ float g_h    [(size_t)NN * H2];
__device__ float g_zpre [(size_t)NN * HH];
__device__ float g_zout [(size_t)NN * OUTD];
__device__ float g_v    [OUTD + 1];
__device__ float g_hg   [(size_t)BB * OUTD];
__device__ float g_stats[4096];            // two 2048-float buffers
__device__ int   g_combo[EE];
__device__ int   g_cnt  [NCOMBO];
__device__ float g_embu [NCOMBO * HEH];
__device__ float g_eeu  [NCOMBO * HH];
__device__ float g_eeact[NCOMBO * HH];
// transposed weights [N, K] fp32
__device__ float g_atomW1t[(size_t)LL * H2 * HH];
__device__ float g_atomW2t[(size_t)LL * HH * H2];
__device__ float g_outWt  [(size_t)OUTD * HH];
__device__ float g_projWt [(size_t)OUTD * OUTD];

// ---------------- mma.sync helpers ----------------
__device__ __forceinline__ uint32_t smem_u32(const void* p) {
    uint32_t a;
    asm("{ .reg .u64 t; cvta.to.shared.u64 t, %1; cvt.u32.u64 %0, t; }" : "=r"(a) : "l"(p));
    return a;
}
__device__ __forceinline__ void ldm_x4(uint32_t* r, uint32_t addr) {
    asm volatile("ldmatrix.sync.aligned.m8n8.x4.shared.b16 {%0,%1,%2,%3}, [%4];"
                 : "=r"(r[0]), "=r"(r[1]), "=r"(r[2]), "=r"(r[3]) : "r"(addr));
}
__device__ __forceinline__ void mma_bf16(float* c, const uint32_t* a, const uint32_t* b) {
    asm volatile("mma.sync.aligned.m16n8k16.row.col.f32.bf16.bf16.f32 "
                 "{%0,%1,%2,%3}, {%4,%5,%6,%7}, {%8,%9}, {%0,%1,%2,%3};"
                 : "+f"(c[0]), "+f"(c[1]), "+f"(c[2]), "+f"(c[3])
                 : "r"(a[0]), "r"(a[1]), "r"(a[2]), "r"(a[3]), "r"(b[0]), "r"(b[1]));
}
__device__ __forceinline__ uint32_t pk(__nv_bfloat16 a, __nv_bfloat16 b) {
    return (uint32_t)__bfloat16_as_ushort(a) | ((uint32_t)__bfloat16_as_ushort(b) << 16);
}

// SMEM tile: 128 rows x 32 bf16, row stride 80B (conflict-free ldmatrix)
#define ROWB   80
#define TILEB  (128 * ROWB)       // 10240
#define STAGEB (4 * TILEB)        // 40960 : Ah, Al, Bh, Bl
#define GEMM_SMEM (2 * STAGEB)    // 81920 : double buffered

__device__ __forceinline__ void store_split(char* th, char* tl, int row, int c4, float4 v) {
    __nv_bfloat16 h0 = __float2bfloat16(v.x), h1 = __float2bfloat16(v.y);
    __nv_bfloat16 h2 = __float2bfloat16(v.z), h3 = __float2bfloat16(v.w);
    __nv_bfloat16 l0 = __float2bfloat16(v.x - __bfloat162float(h0));
    __nv_bfloat16 l1 = __float2bfloat16(v.y - __bfloat162float(h1));
    __nv_bfloat16 l2 = __float2bfloat16(v.z - __bfloat162float(h2));
    __nv_bfloat16 l3 = __float2bfloat16(v.w - __bfloat162float(h3));
    uint32_t off = (uint32_t)(row * ROWB + c4 * 8);
    *(uint2*)(th + off) = make_uint2(pk(h0, h1), pk(h2, h3));
    *(uint2*)(tl + off) = make_uint2(pk(l0, l1), pk(l2, l3));
}

// ---------------- tensor-core GEMM ----------------
// C[M,N] = f(A [+A2])[M,K] @ Bt[N,K]^T + bias
// BNA: f(x) = relu(x*bnp[k] + bnp[1024+k]) applied element-wise on A load.
// STATS: accumulate per-column sum / sumsq of C into stats[c], stats[1024+c].
// 128x128 tile, BK=32, 256 thr (8 warps 2x4), warp tile 64x32.
// 3-product bf16 split: Ah*Bh + Ah*Bl + Al*Bh. Reg-prefetch + dbl-buffered SMEM.
template <bool ADDA2, bool STATS, bool BNA>
__global__ void __launch_bounds__(256)
gemm_mma(int N, int K,
         const float* __restrict__ A, const float* __restrict__ A2,
         const float* __restrict__ Bt, const float* __restrict__ bias,
         float* __restrict__ C, const float* __restrict__ bnp,
         float* __restrict__ stats) {
    extern __shared__ char smem[];

    const int tid = threadIdx.x, lane = tid & 31, wid = tid >> 5;
    const int wr = wid >> 2, wc = wid & 3;
    const int brow = blockIdx.y, bcol = blockIdx.x;

    const float* Ab  = A + (size_t)brow * 128 * K;
    const float* A2b = ADDA2 ? (A2 + (size_t)brow * 128 * K) : nullptr;
    const float* Bb  = Bt + (size_t)bcol * 128 * K;

    const int ld_row = tid >> 3, ld_c4 = tid & 7;   // t adds 32 to row

    float acc[4][4][4];
#pragma unroll
    for (int i = 0; i < 4; i++)
#pragma unroll
        for (int j = 0; j < 4; j++)
#pragma unroll
            for (int q = 0; q < 4; q++) acc[i][j][q] = 0.f;

    const int a_row  = (lane & 15);
    const int a_half = (lane >> 4) * 16;
    const int b_row  = (lane & 7) + ((lane >> 4) << 3);
    const int b_half = ((lane >> 3) & 1) * 16;
    const uint32_t ubase = smem_u32(smem);

    float4 pa[4], pb[4];

    auto load_regs = [&](int k0) {
#pragma unroll
        for (int t = 0; t < 4; t++) {
            int row = ld_row + 32 * t;
            float4 v = *(const float4*)(Ab + (size_t)row * K + k0 + ld_c4 * 4);
            if (ADDA2) {
                float4 w = *(const float4*)(A2b + (size_t)row * K + k0 + ld_c4 * 4);
                v.x += w.x; v.y += w.y; v.z += w.z; v.w += w.w;
            }
            if (BNA) {
                int c = k0 + ld_c4 * 4;
                v.x = fmaxf(0.f, v.x * __ldg(&bnp[c + 0]) + __ldg(&bnp[1024 + c + 0]));
                v.y = fmaxf(0.f, v.y * __ldg(&bnp[c + 1]) + __ldg(&bnp[1024 + c + 1]));
                v.z = fmaxf(0.f, v.z * __ldg(&bnp[c + 2]) + __ldg(&bnp[1024 + c + 2]));
                v.w = fmaxf(0.f, v.w * __ldg(&bnp[c + 3]) + __ldg(&bnp[1024 + c + 3]));
            }
            pa[t] = v;
        }
#pragma unroll
        for (int t = 0; t < 4; t++) {
            int row = ld_row + 32 * t;
            pb[t] = *(const float4*)(Bb + (size_t)row * K + k0 + ld_c4 * 4);
        }
    };
    auto store_stage = [&](int s) {
        char* Ah = smem + s * STAGEB;
        char* Al = Ah + TILEB;
        char* Bh = Al + TILEB;
        char* Bl = Bh + TILEB;
#pragma unroll
        for (int t = 0; t < 4; t++) store_split(Ah, Al, ld_row + 32 * t, ld_c4, pa[t]);
#pragma unroll
        for (int t = 0; t < 4; t++) store_split(Bh, Bl, ld_row + 32 * t, ld_c4, pb[t]);
    };
    auto compute = [&](int s) {
        uint32_t uAh = ubase + s * STAGEB;
        uint32_t uAl = uAh + TILEB, uBh = uAl + TILEB, uBl = uBh + TILEB;
#pragma unroll
        for (int ks = 0; ks < 2; ks++) {
            const int kb = ks * 32;
            uint32_t ah[4][4], al[4][4];
#pragma unroll
            for (int mt = 0; mt < 4; mt++) {
                uint32_t off = (uint32_t)((wr * 64 + mt * 16 + a_row) * ROWB + kb + a_half);
                ldm_x4(ah[mt], uAh + off);
                ldm_x4(al[mt], uAl + off);
            }
            uint32_t bh[4][2], bl[4][2];
#pragma unroll
            for (int np = 0; np < 2; np++) {
                uint32_t off = (uint32_t)((wc * 32 + np * 16 + b_row) * ROWB + kb + b_half);
                uint32_t r[4];
                ldm_x4(r, uBh + off);
                bh[np * 2][0] = r[0]; bh[np * 2][1] = r[1];
                bh[np * 2 + 1][0] = r[2]; bh[np * 2 + 1][1] = r[3];
                ldm_x4(r, uBl + off);
                bl[np * 2][0] = r[0]; bl[np * 2][1] = r[1];
                bl[np * 2 + 1][0] = r[2]; bl[np * 2 + 1][1] = r[3];
            }
#pragma unroll
            for (int mt = 0; mt < 4; mt++)
#pragma unroll
                for (int nt = 0; nt < 4; nt++) {
                    mma_bf16(acc[mt][nt], ah[mt], bh[nt]);
                    mma_bf16(acc[mt][nt], ah[mt], bl[nt]);
                    mma_bf16(acc[mt][nt], al[mt], bh[nt]);
                }
        }
    };

    const int nk = K >> 5;
    load_regs(0);
    store_stage(0);
    __syncthreads();
    for (int k = 0; k < nk; k++) {
        int s = k & 1;
        if (k + 1 < nk) load_regs((k + 1) * 32);
        compute(s);
        if (k + 1 < nk) store_stage(s ^ 1);
        __syncthreads();
    }

    // ---- epilogue: bias, store, optional fused column stats ----
    float s1[8], s2[8];
    if (STATS) {
#pragma unroll
        for (int j = 0; j < 8; j++) { s1[j] = 0.f; s2[j] = 0.f; }
    }
#pragma unroll
    for (int mt = 0; mt < 4; mt++) {
        int row0 = brow * 128 + wr * 64 + mt * 16 + (lane >> 2);
#pragma unroll
        for (int nt = 0; nt < 4; nt++) {
            int col = bcol * 128 + wc * 32 + nt * 8 + (lane & 3) * 2;
            float b0 = bias[col], b1 = bias[col + 1];
            float v00 = acc[mt][nt][0] + b0, v01 = acc[mt][nt][1] + b1;
            float v10 = acc[mt][nt][2] + b0, v11 = acc[mt][nt][3] + b1;
            *(float2*)(C + (size_t)row0 * N + col) = make_float2(v00, v01);
            *(float2*)(C + (size_t)(row0 + 8) * N + col) = make_float2(v10, v11);
            if (STATS) {
                s1[nt * 2 + 0] += v00 + v10;
                s1[nt * 2 + 1] += v01 + v11;
                s2[nt * 2 + 0] += v00 * v00 + v10 * v10;
                s2[nt * 2 + 1] += v01 * v01 + v11 * v11;
            }
        }
    }
    if (STATS) {
#pragma unroll
        for (int j = 0; j < 8; j++) {
#pragma unroll
            for (int o = 4; o <= 16; o <<= 1) {
                s1[j] += __shfl_xor_sync(0xffffffffu, s1[j], o);
                s2[j] += __shfl_xor_sync(0xffffffffu, s2[j], o);
            }
        }
        if (lane < 4) {
#pragma unroll
            for (int nt = 0; nt < 4; nt++) {
#pragma unroll
                for (int p = 0; p < 2; p++) {
                    int col = bcol * 128 + wc * 32 + nt * 8 + lane * 2 + p;
                    atomicAdd(&stats[col], s1[nt * 2 + p]);
                    atomicAdd(&stats[1024 + col], s2[nt * 2 + p]);
                }
            }
        }
    }
}

// ---------------- weight transpose: S[K,N] -> D[N,K] ----------------
__global__ void transpose_f32(const float* __restrict__ S, float* __restrict__ D, int K, int N) {
    __shared__ float t[32][33];
    int k0 = blockIdx.y * 32, n0 = blockIdx.x * 32;
    int x = threadIdx.x, y = threadIdx.y;
#pragma unroll
    for (int i = 0; i < 32; i += 8) t[y + i][x] = S[(size_t)(k0 + y + i) * N + n0 + x];
    __syncthreads();
#pragma unroll
    for (int i = 0; i < 32; i += 8) D[(size_t)(n0 + y + i) * K + k0 + x] = t[x][y + i];
}

// ---------------- embeddings / edge-combo machinery ----------------
__global__ void embed_nodes(const int* __restrict__ x, const float* __restrict__ tab,
                            float* __restrict__ z) {
    int n = blockIdx.x;
    __shared__ int idx[9];
    if (threadIdx.x < 9) idx[threadIdx.x] = x[n * 9 + threadIdx.x] + c_node_off[threadIdx.x];
    __syncthreads();
    for (int c = threadIdx.x; c < HH; c += blockDim.x) {
        float acc = 0.f;
#pragma unroll
        for (int f = 0; f < 9; f++) acc += tab[(size_t)idx[f] * HH + c];
        z[(size_t)n * HH + c] = acc;
    }
}

__global__ void combo_hist(const int* __restrict__ ea, int* __restrict__ combo,
                           int* __restrict__ cnt) {
    int e = blockIdx.x * 256 + threadIdx.x;
    if (e >= EE) return;
    int c = ea[e * 3] * 12 + ea[e * 3 + 1] * 2 + ea[e * 3 + 2];
    combo[e] = c;
    atomicAdd(&cnt[c], 1);
}

__global__ void embed_edges_u(const float* __restrict__ tab, float* __restrict__ embu) {
    int u = blockIdx.x;
    int a0 = u / 12, a1 = (u % 12) / 2, a2 = u & 1;
    int c = threadIdx.x;   // 128 threads
    embu[u * HEH + c] = tab[(size_t)a0 * HEH + c]
                      + tab[(size_t)(119 + a1) * HEH + c]
                      + tab[(size_t)(128 + a2) * HEH + c];
}

// ee_u = emb_u @ bW + bB   (264 x 512, K=128), bW in original [K,N] layout
__global__ void bond_small(const float* __restrict__ embu, const float* __restrict__ bW,
                           const float* __restrict__ bB, float* __restrict__ eeu) {
    __shared__ float se[HEH];
    int u = blockIdx.x;
    if (threadIdx.x < HEH) se[threadIdx.x] = embu[u * HEH + threadIdx.x];
    __syncthreads();
    int c = threadIdx.x;   // 512 threads
    float acc = bB[c];
#pragma unroll 4
    for (int k = 0; k < HEH; k++) acc += se[k] * bW[(size_t)k * HH + c];
    eeu[u * HH + c] = acc;
}

// weighted column stats over the 264 unique rows
__global__ void wstats(const float* __restrict__ eeu, const int* __restrict__ cnt,
                       float* __restrict__ stats) {
    int c = blockIdx.x * 256 + threadIdx.x;   // 512 cols
    float m = 0.f, q = 0.f;
    for (int u = 0; u < NCOMBO; u++) {
        float w = (float)cnt[u];
        float v = eeu[u * HH + c];
        m += w * v;
        q += w * v * v;
    }
    stats[c] = m;
    stats[1024 + c] = q;
}

__global__ void bn_prep(float* __restrict__ stats, int cols, float inv_rows,
                        const float* __restrict__ g, const float* __restrict__ b) {
    int c = blockIdx.x * blockDim.x + threadIdx.x;
    if (c >= cols) return;
    float m = stats[c] * inv_rows;
    float var = stats[1024 + c] * inv_rows - m * m;
    float sc = g[c] * rsqrtf(var + EPSV);
    stats[c] = sc;
    stats[1024 + c] = b[c] - m * sc;
}

__global__ void eeact_apply(const float* __restrict__ eeu, const float* __restrict__ stats,
                            float* __restrict__ eeact) {
    int u = blockIdx.x;
    int c = threadIdx.x;   // 512 threads
    eeact[u * HH + c] = fmaxf(0.f, eeu[u * HH + c] * stats[c] + stats[1024 + c]);
}

__global__ void bn_relu(const float* __restrict__ X, float* __restrict__ Y,
                        size_t total4, int cols, const float* __restrict__ stats) {
    size_t i = (size_t)blockIdx.x * blockDim.x + threadIdx.x;
    if (i >= total4) return;
    int c = (int)((i * 4) % cols);
    float4 x = ((const float4*)X)[i];
    float4 y;
    y.x = fmaxf(0.f, x.x * stats[c + 0] + stats[1024 + c + 0]);
    y.y = fmaxf(0.f, x.y * stats[c + 1] + stats[1024 + c + 1]);
    y.z = fmaxf(0.f, x.z * stats[c + 2] + stats[1024 + c + 2]);
    y.w = fmaxf(0.f, x.w * stats[c + 3] + stats[1024 + c + 3]);
    ((float4*)Y)[i] = y;
}

// agg[dst] += z[src] + eeact[combo]
__global__ void scatter_msg(const float* __restrict__ eeact, const int* __restrict__ combo,
                            const float* __restrict__ z, const int* __restrict__ eidx,
                            float* __restrict__ agg) {
    int e = blockIdx.x;
    int s = eidx[e];
    int d = eidx[EE + e];
    int u = combo[e];
    int c = threadIdx.x * 4;   // 128 threads x 4 cols
    float4 zv = *(const float4*)(z + (size_t)s * HH + c);
    float4 ev = *(const float4*)(eeact + (size_t)u * HH + c);
    float* ar = agg + (size_t)d * HH + c;
    atomicAdd(ar + 0, zv.x + ev.x);
    atomicAdd(ar + 1, zv.y + ev.y);
    atomicAdd(ar + 2, zv.z + ev.z);
    atomicAdd(ar + 3, zv.w + ev.w);
}

// ---------------- pooling ----------------
__global__ void att_vec(const float* __restrict__ gapW, const float* __restrict__ gapB,
                        const float* __restrict__ attW, const float* __restrict__ attB,
                        float* __restrict__ v) {
    int w = blockIdx.x * (blockDim.x / 32) + (threadIdx.x / 32);
    int lane = threadIdx.x & 31;
    if (w > OUTD) return;
    const float* row = (w < OUTD) ? (gapW + (size_t)w * HH) : gapB;
    float acc = 0.f;
    for (int h = lane; h < HH; h += 32) acc += row[h] * attW[h];
#pragma unroll
    for (int o = 16; o; o >>= 1) acc += __shfl_xor_sync(0xffffffffu, acc, o);
    if (lane == 0) v[w] = acc + ((w == OUTD) ? attB[0] : 0.f);
}

__global__ void pool(const float* __restrict__ zout, const float* __restrict__ v,
                     float* __restrict__ hg) {
    __shared__ float satt[NPG];
    __shared__ float salpha[NPG];
    int b = blockIdx.x;
    int warp = threadIdx.x / 32, lane = threadIdx.x & 31;
    const float cst = v[OUTD];
    for (int n = warp; n < NPG; n += 8) {
        const float* row = zout + ((size_t)b * NPG + n) * OUTD;
        float acc = 0.f;
        for (int k = lane; k < OUTD; k += 32) acc += row[k] * v[k];
#pragma unroll
        for (int o = 16; o; o >>= 1) acc += __shfl_xor_sync(0xffffffffu, acc, o);
        if (lane == 0) satt[n] = acc + cst;
    }
    __syncthreads();
    if (threadIdx.x < 32) {
        float a = satt[threadIdx.x];
        float mx = a;
#pragma unroll
        for (int o = 16; o; o >>= 1) mx = fmaxf(mx, __shfl_xor_sync(0xffffffffu, mx, o));
        float ex = expf(a - mx);
        float s = ex;
#pragma unroll
        for (int o = 16; o; o >>= 1) s += __shfl_xor_sync(0xffffffffu, s, o);
        salpha[threadIdx.x] = ex / s;
    }
    __syncthreads();
    for (int j = threadIdx.x; j < OUTD; j += 256) {
        float acc = 0.f;
#pragma unroll
        for (int n = 0; n < NPG; n++)
            acc += salpha[n] * zout[((size_t)b * NPG + n) * OUTD + j];
        hg[(size_t)b * OUTD + j] = acc;
    }
}

// ---------------- host orchestration ----------------
extern "C" void kernel_launch(void* const* d_in, const int* in_sizes, int n_in,
                              void* d_out, int out_size) {
    const int*   x        = (const int*)  d_in[0];
    const int*   edgeattr = (const int*)  d_in[1];
    const int*   eidx     = (const int*)  d_in[2];
    const float* node_tab = (const float*)d_in[4];
    const float* edge_tab = (const float*)d_in[5];
    const float* bondW    = (const float*)d_in[6];
    const float* bondB    = (const float*)d_in[7];
    const float* bondG    = (const float*)d_in[8];
    const float* bondBeta = (const float*)d_in[9];
    const float* atomW1   = (const float*)d_in[10];
    const float* atomB1   = (const float*)d_in[11];
    const float* atomG    = (const float*)d_in[12];
    const float* atomBeta = (const float*)d_in[13];
    const float* atomW2   = (const float*)d_in[14];
    const float* atomB2   = (const float*)d_in[15];
    const float* normG    = (const float*)d_in[16];
    const float* normB    = (const float*)d_in[17];
    const float* outW     = (const float*)d_in[18];
    const float* outB     = (const float*)d_in[19];
    const float* gapW     = (const float*)d_in[20];
    const float* gapB     = (const float*)d_in[21];
    const float* attW     = (const float*)d_in[22];
    const float* attB     = (const float*)d_in[23];
    const float* projW    = (const float*)d_in[24];
    const float* projB    = (const float*)d_in[25];
    float* out = (float*)d_out;

    float *p_z, *p_agg, *p_h, *p_zpre, *p_zout, *p_v, *p_hg, *p_stats;
    float *p_embu, *p_eeu, *p_eeact;
    int *p_combo, *p_cnt;
    float *p_atomW1t, *p_atomW2t, *p_outWt, *p_projWt;
    cudaGetSymbolAddress((void**)&p_z, g_z);
    cudaGetSymbolAddress((void**)&p_agg, g_agg);
    cudaGetSymbolAddress((void**)&p_h, g_h);
    cudaGetSymbolAddress((void**)&p_zpre, g_zpre);
    cudaGetSymbolAddress((void**)&p_zout, g_zout);
    cudaGetSymbolAddress((void**)&p_v, g_v);
    cudaGetSymbolAddress((void**)&p_hg, g_hg);
    cudaGetSymbolAddress((void**)&p_stats, g_stats);
    cudaGetSymbolAddress((void**)&p_combo, g_combo);
    cudaGetSymbolAddress((void**)&p_cnt, g_cnt);
    cudaGetSymbolAddress((void**)&p_embu, g_embu);
    cudaGetSymbolAddress((void**)&p_eeu, g_eeu);
    cudaGetSymbolAddress((void**)&p_eeact, g_eeact);
    cudaGetSymbolAddress((void**)&p_atomW1t, g_atomW1t);
    cudaGetSymbolAddress((void**)&p_atomW2t, g_atomW2t);
    cudaGetSymbolAddress((void**)&p_outWt, g_outWt);
    cudaGetSymbolAddress((void**)&p_projWt, g_projWt);

    float* buf1 = p_stats;
    float* buf2 = p_stats + 2048;

    cudaFuncSetAttribute(gemm_mma<true,  true,  false>, cudaFuncAttributeMaxDynamicSharedMemorySize, GEMM_SMEM);
    cudaFuncSetAttribute(gemm_mma<false, true,  true >, cudaFuncAttributeMaxDynamicSharedMemorySize, GEMM_SMEM);
    cudaFuncSetAttribute(gemm_mma<false, false, false>, cudaFuncAttributeMaxDynamicSharedMemorySize, GEMM_SMEM);

    // weight transposes [K,N] -> [N,K]
    for (int l = 0; l < LL; l++) {
        transpose_f32<<<dim3(H2 / 32, HH / 32), dim3(32, 8)>>>(
            atomW1 + (size_t)l * HH * H2, p_atomW1t + (size_t)l * H2 * HH, HH, H2);
        transpose_f32<<<dim3(HH / 32, H2 / 32), dim3(32, 8)>>>(
            atomW2 + (size_t)l * H2 * HH, p_atomW2t + (size_t)l * HH * H2, H2, HH);
    }
    transpose_f32<<<dim3(OUTD / 32, HH / 32), dim3(32, 8)>>>(outW, p_outWt, HH, OUTD);
    transpose_f32<<<dim3(OUTD / 32, OUTD / 32), dim3(32, 8)>>>(projW, p_projWt, OUTD, OUTD);

    // embeddings + edge combo machinery
    embed_nodes<<<NN, 256>>>(x, node_tab, p_z);
    cudaMemsetAsync(p_cnt, 0, NCOMBO * sizeof(int));
    combo_hist<<<(EE + 255) / 256, 256>>>(edgeattr, p_combo, p_cnt);
    embed_edges_u<<<NCOMBO, HEH>>>(edge_tab, p_embu);

    for (int l = 0; l < LL; l++) {
        const float* bW   = bondW     + (size_t)l * HEH * HH;
        const float* bB   = bondB     + (size_t)l * HH;
        const float* bG   = bondG     + (size_t)l * HH;
        const float* bBe  = bondBeta  + (size_t)l * HH;
        const float* aW1t = p_atomW1t + (size_t)l * H2 * HH;
        const float* aB1  = atomB1    + (size_t)l * H2;
        const float* aG   = atomG     + (size_t)l * H2;
        const float* aBe  = atomBeta  + (size_t)l * H2;
        const float* aW2t = p_atomW2t + (size_t)l * HH * H2;
        const float* aB2  = atomB2    + (size_t)l * HH;
        const float* nG   = normG     + (size_t)l * HH;
        const float* nB   = normB     + (size_t)l * HH;

        // bond path on 264 unique combos
        bond_small<<<NCOMBO, HH>>>(p_embu, bW, bB, p_eeu);
        wstats<<<2, 256>>>(p_eeu, p_cnt, buf1);
        bn_prep<<<2, 256>>>(buf1, HH, 1.f / EE, bG, bBe);
        eeact_apply<<<NCOMBO, HH>>>(p_eeu, buf1, p_eeact);

        // message aggregation
        cudaMemsetAsync(p_agg, 0, (size_t)NN * HH * sizeof(float));
        scatter_msg<<<EE, 128>>>(p_eeact, p_combo, p_z, eidx, p_agg);

        // h_pre = (agg + z) @ aW1 + aB1, stats fused
        cudaMemsetAsync(buf1, 0, 2048 * sizeof(float));
        gemm_mma<true, true, false><<<dim3(H2 / 128, NN / 128), 256, GEMM_SMEM>>>(
            H2, HH, p_agg, p_z, aW1t, aB1, p_h, nullptr, buf1);
        bn_prep<<<4, 256>>>(buf1, H2, 1.f / NN, aG, aBe);

        // z_pre = relu(bn(h_pre)) @ aW2 + aB2, bn fused on A-load, stats fused
        cudaMemsetAsync(buf2, 0, 2048 * sizeof(float));
        gemm_mma<false, true, true><<<dim3(HH / 128, NN / 128), 256, GEMM_SMEM>>>(
            HH, H2, p_h, nullptr, aW2t, aB2, p_zpre, buf1, buf2);
        bn_prep<<<2, 256>>>(buf2, HH, 1.f / NN, nG, nB);
        bn_relu<<<(unsigned)(((size_t)NN * HH / 4 + 255) / 256), 256>>>(
            p_zpre, p_z, (size_t)NN * HH / 4, HH, buf2);
    }

    // zout = z @ outW + outB
    gemm_mma<false, false, false><<<dim3(OUTD / 128, NN / 128), 256, GEMM_SMEM>>>(
        OUTD, HH, p_z, nullptr, p_outWt, outB, p_zout, nullptr, nullptr);

    att_vec<<<129, 256>>>(gapW, gapB, attW, attB, p_v);
    pool<<<BB, 256>>>(p_zout, p_v, p_hg);

    // out = hg @ projW + projB
    gemm_mma<false, false, false><<<dim3(OUTD / 128, BB / 128), 256, GEMM_SMEM>>>(
        OUTD, OUTD, p_hg, nullptr, p_projWt, projB, out, nullptr, nullptr);
}

// round 5
// speedup vs baseline: 2.7652x; 1.4102x over previous
#include <cuda_runtime.h>
#include <cuda_bf16.h>
#include <cstdint>

// ---------------- problem constants ----------------
#define NN      32768
#define EE      131072
#define HH      512
#define HEH     128
#define H2      1024
#define OUTD    1024
#define BB      1024
#define NPG     32
#define LL      6
#define EPSV    1e-5f
#define NCOMBO  264

__device__ __constant__ int c_node_off[9] = {0,119,128,139,151,160,165,173,175};

// ---------------- scratch (device globals; no allocs allowed) ----------------
__device__ float g_z    [(size_t)NN * HH];
__device__ float g_agg  [(size_t)NN * HH];
__device__ float g_h    [(size_t)NN * H2];
__device__ float g_zpre [(size_t)NN * HH];
__device__ float g_zout [(size_t)NN * OUTD];
__device__ float g_v    [OUTD + 1];
__device__ float g_hg   [(size_t)BB * OUTD];
__device__ float g_stats[4096];
__device__ int   g_combo[EE];
__device__ int   g_cnt  [NCOMBO];
__device__ float g_embu [NCOMBO * HEH];
__device__ float g_eeu  [NCOMBO * HH];
__device__ float g_eeact[NCOMBO * HH];
// pre-split bf16 activations (hi/lo)
__device__ __nv_bfloat16 g_aggh[(size_t)NN * HH];
__device__ __nv_bfloat16 g_aggl[(size_t)NN * HH];
__device__ __nv_bfloat16 g_hh  [(size_t)NN * H2];
__device__ __nv_bfloat16 g_hl  [(size_t)NN * H2];
__device__ __nv_bfloat16 g_zh  [(size_t)NN * HH];
__device__ __nv_bfloat16 g_zl  [(size_t)NN * HH];
__device__ __nv_bfloat16 g_hgh [(size_t)BB * OUTD];
__device__ __nv_bfloat16 g_hgl [(size_t)BB * OUTD];
// pre-split transposed weights [N, K] bf16 hi/lo
__device__ __nv_bfloat16 g_aW1h[(size_t)LL * H2 * HH];
__device__ __nv_bfloat16 g_aW1l[(size_t)LL * H2 * HH];
__device__ __nv_bfloat16 g_aW2h[(size_t)LL * HH * H2];
__device__ __nv_bfloat16 g_aW2l[(size_t)LL * HH * H2];
__device__ __nv_bfloat16 g_oWh [(size_t)OUTD * HH];
__device__ __nv_bfloat16 g_oWl [(size_t)OUTD * HH];
__device__ __nv_bfloat16 g_pWh [(size_t)OUTD * OUTD];
__device__ __nv_bfloat16 g_pWl [(size_t)OUTD * OUTD];

// ---------------- asm helpers ----------------
__device__ __forceinline__ uint32_t smem_u32(const void* p) {
    uint32_t a;
    asm("{ .reg .u64 t; cvta.to.shared.u64 t, %1; cvt.u32.u64 %0, t; }" : "=r"(a) : "l"(p));
    return a;
}
__device__ __forceinline__ void ldm_x4(uint32_t* r, uint32_t addr) {
    asm volatile("ldmatrix.sync.aligned.m8n8.x4.shared.b16 {%0,%1,%2,%3}, [%4];"
                 : "=r"(r[0]), "=r"(r[1]), "=r"(r[2]), "=r"(r[3]) : "r"(addr));
}
__device__ __forceinline__ void mma_bf16(float* c, const uint32_t* a, const uint32_t* b) {
    asm volatile("mma.sync.aligned.m16n8k16.row.col.f32.bf16.bf16.f32 "
                 "{%0,%1,%2,%3}, {%4,%5,%6,%7}, {%8,%9}, {%0,%1,%2,%3};"
                 : "+f"(c[0]), "+f"(c[1]), "+f"(c[2]), "+f"(c[3])
                 : "r"(a[0]), "r"(a[1]), "r"(a[2]), "r"(a[3]), "r"(b[0]), "r"(b[1]));
}
__device__ __forceinline__ void cpasync16(uint32_t sa, const void* ga) {
    asm volatile("cp.async.cg.shared.global [%0], [%1], 16;" :: "r"(sa), "l"(ga));
}
#define CP_COMMIT() asm volatile("cp.async.commit_group;" ::: "memory")
#define CP_WAIT1()  asm volatile("cp.async.wait_group 1;" ::: "memory")

__device__ __forceinline__ uint32_t pk(__nv_bfloat16 a, __nv_bfloat16 b) {
    return (uint32_t)__bfloat16_as_ushort(a) | ((uint32_t)__bfloat16_as_ushort(b) << 16);
}
__device__ __forceinline__ void split4(float4 v, uint2& hi, uint2& lo) {
    __nv_bfloat16 h0 = __float2bfloat16(v.x), h1 = __float2bfloat16(v.y);
    __nv_bfloat16 h2 = __float2bfloat16(v.z), h3 = __float2bfloat16(v.w);
    __nv_bfloat16 l0 = __float2bfloat16(v.x - __bfloat162float(h0));
    __nv_bfloat16 l1 = __float2bfloat16(v.y - __bfloat162float(h1));
    __nv_bfloat16 l2 = __float2bfloat16(v.z - __bfloat162float(h2));
    __nv_bfloat16 l3 = __float2bfloat16(v.w - __bfloat162float(h3));
    hi = make_uint2(pk(h0, h1), pk(h2, h3));
    lo = make_uint2(pk(l0, l1), pk(l2, l3));
}

// SMEM tile: 128 rows x 32 bf16 (64B data), row stride 80B
#define ROWB   80
#define TILEB  (128 * ROWB)       // 10240
#define STAGEB (4 * TILEB)        // 40960 : Ah, Al, Bh, Bl
#define GEMM_SMEM (2 * STAGEB)    // 81920

// ---------------- tensor-core GEMM (all operands pre-split bf16) ----------------
// C[M,N] = A[M,K] @ Bt[N,K]^T + bias ; 3-product: Ah*Bh + Ah*Bl + Al*Bh
// 128x128 tile, BK=32, 256 thr (8 warps 2x4), cp.async 2-stage pipeline, 2 CTA/SM.
template <bool STATS>
__global__ void __launch_bounds__(256, 2)
gemm_mma(int N, int K,
         const __nv_bfloat16* __restrict__ Ah, const __nv_bfloat16* __restrict__ Al,
         const __nv_bfloat16* __restrict__ Bh, const __nv_bfloat16* __restrict__ Bl,
         const float* __restrict__ bias, float* __restrict__ C,
         float* __restrict__ stats) {
    extern __shared__ char smem[];

    const int tid = threadIdx.x, lane = tid & 31, wid = tid >> 5;
    const int wr = wid >> 2, wc = wid & 3;
    const int brow = blockIdx.y, bcol = blockIdx.x;

    const size_t Kb = (size_t)K * 2;   // row bytes
    const char* pAh = (const char*)(Ah + (size_t)brow * 128 * K);
    const char* pAl = (const char*)(Al + (size_t)brow * 128 * K);
    const char* pBh = (const char*)(Bh + (size_t)bcol * 128 * K);
    const char* pBl = (const char*)(Bl + (size_t)bcol * 128 * K);

    const uint32_t ubase = smem_u32(smem);
    // loader mapping: 512 chunks (128 rows x 4 x16B) per tile; 2 per thread per tile
    const int r0 = tid >> 2, c0 = (tid & 3) * 16;          // chunk 0: rows 0..63
    const int r1 = (tid >> 2) + 64, c1 = (tid & 3) * 16;   // chunk 1: rows 64..127

    auto issue = [&](int k0, int s) {
        uint32_t base = ubase + s * STAGEB;
        size_t g0 = (size_t)r0 * Kb + (size_t)k0 * 64 + c0;
        size_t g1 = (size_t)r1 * Kb + (size_t)k0 * 64 + c1;
        uint32_t s0 = (uint32_t)(r0 * ROWB + c0);
        uint32_t s1 = (uint32_t)(r1 * ROWB + c1);
        cpasync16(base + s0,             pAh + g0);
        cpasync16(base + s1,             pAh + g1);
        cpasync16(base + TILEB + s0,     pAl + g0);
        cpasync16(base + TILEB + s1,     pAl + g1);
        cpasync16(base + 2 * TILEB + s0, pBh + g0);
        cpasync16(base + 2 * TILEB + s1, pBh + g1);
        cpasync16(base + 3 * TILEB + s0, pBl + g0);
        cpasync16(base + 3 * TILEB + s1, pBl + g1);
    };

    float acc[4][4][4];
#pragma unroll
    for (int i = 0; i < 4; i++)
#pragma unroll
        for (int j = 0; j < 4; j++)
#pragma unroll
            for (int q = 0; q < 4; q++) acc[i][j][q] = 0.f;

    const int a_row  = (lane & 15);
    const int a_half = (lane >> 4) * 16;
    const int b_row  = (lane & 7) + ((lane >> 4) << 3);
    const int b_half = ((lane >> 3) & 1) * 16;

    auto compute = [&](int s) {
        uint32_t uAh = ubase + s * STAGEB;
        uint32_t uAl = uAh + TILEB, uBh = uAl + TILEB, uBl = uBh + TILEB;
#pragma unroll
        for (int ks = 0; ks < 2; ks++) {
            const int kb = ks * 32;
            uint32_t ah[4][4], al[4][4];
#pragma unroll
            for (int mt = 0; mt < 4; mt++) {
                uint32_t off = (uint32_t)((wr * 64 + mt * 16 + a_row) * ROWB + kb + a_half);
                ldm_x4(ah[mt], uAh + off);
                ldm_x4(al[mt], uAl + off);
            }
            uint32_t bh[4][2], bl[4][2];
#pragma unroll
            for (int np = 0; np < 2; np++) {
                uint32_t off = (uint32_t)((wc * 32 + np * 16 + b_row) * ROWB + kb + b_half);
                uint32_t r[4];
                ldm_x4(r, uBh + off);
                bh[np * 2][0] = r[0]; bh[np * 2][1] = r[1];
                bh[np * 2 + 1][0] = r[2]; bh[np * 2 + 1][1] = r[3];
                ldm_x4(r, uBl + off);
                bl[np * 2][0] = r[0]; bl[np * 2][1] = r[1];
                bl[np * 2 + 1][0] = r[2]; bl[np * 2 + 1][1] = r[3];
            }
#pragma unroll
            for (int mt = 0; mt < 4; mt++)
#pragma unroll
                for (int nt = 0; nt < 4; nt++) {
                    mma_bf16(acc[mt][nt], ah[mt], bh[nt]);
                    mma_bf16(acc[mt][nt], ah[mt], bl[nt]);
                    mma_bf16(acc[mt][nt], al[mt], bh[nt]);
                }
        }
    };

    const int nk = K >> 5;   // >= 16 for all our shapes
    issue(0, 0); CP_COMMIT();
    issue(1, 1); CP_COMMIT();
    for (int k = 0; k < nk; k++) {
        const int s = k & 1;
        CP_WAIT1();
        __syncthreads();
        compute(s);
        __syncthreads();
        if (k + 2 < nk) issue(k + 2, s);
        CP_COMMIT();   // always commit so wait_group 1 keeps stage k+1 covered
    }

    // ---- epilogue: bias, store, optional fused column stats ----
    float s1[8], s2[8];
    if (STATS) {
#pragma unroll
        for (int j = 0; j < 8; j++) { s1[j] = 0.f; s2[j] = 0.f; }
    }
#pragma unroll
    for (int mt = 0; mt < 4; mt++) {
        int row0 = brow * 128 + wr * 64 + mt * 16 + (lane >> 2);
#pragma unroll
        for (int nt = 0; nt < 4; nt++) {
            int col = bcol * 128 + wc * 32 + nt * 8 + (lane & 3) * 2;
            float b0 = bias[col], b1 = bias[col + 1];
            float v00 = acc[mt][nt][0] + b0, v01 = acc[mt][nt][1] + b1;
            float v10 = acc[mt][nt][2] + b0, v11 = acc[mt][nt][3] + b1;
            *(float2*)(C + (size_t)row0 * N + col) = make_float2(v00, v01);
            *(float2*)(C + (size_t)(row0 + 8) * N + col) = make_float2(v10, v11);
            if (STATS) {
                s1[nt * 2 + 0] += v00 + v10;
                s1[nt * 2 + 1] += v01 + v11;
                s2[nt * 2 + 0] += v00 * v00 + v10 * v10;
                s2[nt * 2 + 1] += v01 * v01 + v11 * v11;
            }
        }
    }
    if (STATS) {
#pragma unroll
        for (int j = 0; j < 8; j++) {
#pragma unroll
            for (int o = 4; o <= 16; o <<= 1) {
                s1[j] += __shfl_xor_sync(0xffffffffu, s1[j], o);
                s2[j] += __shfl_xor_sync(0xffffffffu, s2[j], o);
            }
        }
        if (lane < 4) {
#pragma unroll
            for (int nt = 0; nt < 4; nt++) {
#pragma unroll
                for (int p = 0; p < 2; p++) {
                    int col = bcol * 128 + wc * 32 + nt * 8 + lane * 2 + p;
                    atomicAdd(&stats[col], s1[nt * 2 + p]);
                    atomicAdd(&stats[1024 + col], s2[nt * 2 + p]);
                }
            }
        }
    }
}

// ---------------- weight transpose + split: S[K,N] fp32 -> Dh/Dl[N,K] bf16 ----------------
__global__ void transpose_split(const float* __restrict__ S,
                                __nv_bfloat16* __restrict__ Dh,
                                __nv_bfloat16* __restrict__ Dl, int K, int N) {
    __shared__ float t[32][33];
    int k0 = blockIdx.y * 32, n0 = blockIdx.x * 32;
    int x = threadIdx.x, y = threadIdx.y;
#pragma unroll
    for (int i = 0; i < 32; i += 8) t[y + i][x] = S[(size_t)(k0 + y + i) * N + n0 + x];
    __syncthreads();
#pragma unroll
    for (int i = 0; i < 32; i += 8) {
        float v = t[x][y + i];
        __nv_bfloat16 h = __float2bfloat16(v);
        __nv_bfloat16 l = __float2bfloat16(v - __bfloat162float(h));
        Dh[(size_t)(n0 + y + i) * K + k0 + x] = h;
        Dl[(size_t)(n0 + y + i) * K + k0 + x] = l;
    }
}

// ---------------- split passes ----------------
__global__ void split_f32(const float* __restrict__ X,
                          __nv_bfloat16* __restrict__ Xh, __nv_bfloat16* __restrict__ Xl,
                          size_t total4) {
    size_t i = (size_t)blockIdx.x * blockDim.x + threadIdx.x;
    if (i >= total4) return;
    uint2 hi, lo;
    split4(((const float4*)X)[i], hi, lo);
    ((uint2*)Xh)[i] = hi;
    ((uint2*)Xl)[i] = lo;
}

__global__ void bn_relu_split(const float* __restrict__ X,
                              __nv_bfloat16* __restrict__ Xh, __nv_bfloat16* __restrict__ Xl,
                              size_t total4, int cols, const float* __restrict__ stats) {
    size_t i = (size_t)blockIdx.x * blockDim.x + threadIdx.x;
    if (i >= total4) return;
    int c = (int)((i * 4) % cols);
    float4 x = ((const float4*)X)[i];
    float4 y;
    y.x = fmaxf(0.f, x.x * stats[c + 0] + stats[1024 + c + 0]);
    y.y = fmaxf(0.f, x.y * stats[c + 1] + stats[1024 + c + 1]);
    y.z = fmaxf(0.f, x.z * stats[c + 2] + stats[1024 + c + 2]);
    y.w = fmaxf(0.f, x.w * stats[c + 3] + stats[1024 + c + 3]);
    uint2 hi, lo;
    split4(y, hi, lo);
    ((uint2*)Xh)[i] = hi;
    ((uint2*)Xl)[i] = lo;
}

__global__ void bn_relu(const float* __restrict__ X, float* __restrict__ Y,
                        size_t total4, int cols, const float* __restrict__ stats) {
    size_t i = (size_t)blockIdx.x * blockDim.x + threadIdx.x;
    if (i >= total4) return;
    int c = (int)((i * 4) % cols);
    float4 x = ((const float4*)X)[i];
    float4 y;
    y.x = fmaxf(0.f, x.x * stats[c + 0] + stats[1024 + c + 0]);
    y.y = fmaxf(0.f, x.y * stats[c + 1] + stats[1024 + c + 1]);
    y.z = fmaxf(0.f, x.z * stats[c + 2] + stats[1024 + c + 2]);
    y.w = fmaxf(0.f, x.w * stats[c + 3] + stats[1024 + c + 3]);
    ((float4*)Y)[i] = y;
}

// ---------------- embeddings / edge-combo machinery ----------------
__global__ void embed_nodes(const int* __restrict__ x, const float* __restrict__ tab,
                            float* __restrict__ z) {
    int n = blockIdx.x;
    __shared__ int idx[9];
    if (threadIdx.x < 9) idx[threadIdx.x] = x[n * 9 + threadIdx.x] + c_node_off[threadIdx.x];
    __syncthreads();
    for (int c = threadIdx.x; c < HH; c += blockDim.x) {
        float acc = 0.f;
#pragma unroll
        for (int f = 0; f < 9; f++) acc += tab[(size_t)idx[f] * HH + c];
        z[(size_t)n * HH + c] = acc;
    }
}

__global__ void combo_hist(const int* __restrict__ ea, int* __restrict__ combo,
                           int* __restrict__ cnt) {
    int e = blockIdx.x * 256 + threadIdx.x;
    if (e >= EE) return;
    int c = ea[e * 3] * 12 + ea[e * 3 + 1] * 2 + ea[e * 3 + 2];
    combo[e] = c;
    atomicAdd(&cnt[c], 1);
}

__global__ void embed_edges_u(const float* __restrict__ tab, float* __restrict__ embu) {
    int u = blockIdx.x;
    int a0 = u / 12, a1 = (u % 12) / 2, a2 = u & 1;
    int c = threadIdx.x;
    embu[u * HEH + c] = tab[(size_t)a0 * HEH + c]
                      + tab[(size_t)(119 + a1) * HEH + c]
                      + tab[(size_t)(128 + a2) * HEH + c];
}

__global__ void bond_small(const float* __restrict__ embu, const float* __restrict__ bW,
                           const float* __restrict__ bB, float* __restrict__ eeu) {
    __shared__ float se[HEH];
    int u = blockIdx.x;
    if (threadIdx.x < HEH) se[threadIdx.x] = embu[u * HEH + threadIdx.x];
    __syncthreads();
    int c = threadIdx.x;
    float acc = bB[c];
#pragma unroll 4
    for (int k = 0; k < HEH; k++) acc += se[k] * bW[(size_t)k * HH + c];
    eeu[u * HH + c] = acc;
}

__global__ void wstats(const float* __restrict__ eeu, const int* __restrict__ cnt,
                       float* __restrict__ stats) {
    int c = blockIdx.x * 256 + threadIdx.x;
    float m = 0.f, q = 0.f;
    for (int u = 0; u < NCOMBO; u++) {
        float w = (float)cnt[u];
        float v = eeu[u * HH + c];
        m += w * v;
        q += w * v * v;
    }
    stats[c] = m;
    stats[1024 + c] = q;
}

__global__ void bn_prep(float* __restrict__ stats, int cols, float inv_rows,
                        const float* __restrict__ g, const float* __restrict__ b) {
    int c = blockIdx.x * blockDim.x + threadIdx.x;
    if (c >= cols) return;
    float m = stats[c] * inv_rows;
    float var = stats[1024 + c] * inv_rows - m * m;
    float sc = g[c] * rsqrtf(var + EPSV);
    stats[c] = sc;
    stats[1024 + c] = b[c] - m * sc;
}

__global__ void eeact_apply(const float* __restrict__ eeu, const float* __restrict__ stats,
                            float* __restrict__ eeact) {
    int u = blockIdx.x;
    int c = threadIdx.x;
    eeact[u * HH + c] = fmaxf(0.f, eeu[u * HH + c] * stats[c] + stats[1024 + c]);
}

// agg[dst] += z[src] + eeact[combo]   (agg pre-initialized to z)
__global__ void scatter_msg(const float* __restrict__ eeact, const int* __restrict__ combo,
                            const float* __restrict__ z, const int* __restrict__ eidx,
                            float* __restrict__ agg) {
    int e = blockIdx.x;
    int s = eidx[e];
    int d = eidx[EE + e];
    int u = combo[e];
    int c = threadIdx.x * 4;
    float4 zv = *(const float4*)(z + (size_t)s * HH + c);
    float4 ev = *(const float4*)(eeact + (size_t)u * HH + c);
    float* ar = agg + (size_t)d * HH + c;
    atomicAdd(ar + 0, zv.x + ev.x);
    atomicAdd(ar + 1, zv.y + ev.y);
    atomicAdd(ar + 2, zv.z + ev.z);
    atomicAdd(ar + 3, zv.w + ev.w);
}

// ---------------- pooling ----------------
__global__ void att_vec(const float* __restrict__ gapW, const float* __restrict__ gapB,
                        const float* __restrict__ attW, const float* __restrict__ attB,
                        float* __restrict__ v) {
    int w = blockIdx.x * (blockDim.x / 32) + (threadIdx.x / 32);
    int lane = threadIdx.x & 31;
    if (w > OUTD) return;
    const float* row = (w < OUTD) ? (gapW + (size_t)w * HH) : gapB;
    float acc = 0.f;
    for (int h = lane; h < HH; h += 32) acc += row[h] * attW[h];
#pragma unroll
    for (int o = 16; o; o >>= 1) acc += __shfl_xor_sync(0xffffffffu, acc, o);
    if (lane == 0) v[w] = acc + ((w == OUTD) ? attB[0] : 0.f);
}

__global__ void pool(const float* __restrict__ zout, const float* __restrict__ v,
                     float* __restrict__ hg) {
    __shared__ float satt[NPG];
    __shared__ float salpha[NPG];
    int b = blockIdx.x;
    int warp = threadIdx.x / 32, lane = threadIdx.x & 31;
    const float cst = v[OUTD];
    for (int n = warp; n < NPG; n += 8) {
        const float* row = zout + ((size_t)b * NPG + n) * OUTD;
        float acc = 0.f;
        for (int k = lane; k < OUTD; k += 32) acc += row[k] * v[k];
#pragma unroll
        for (int o = 16; o; o >>= 1) acc += __shfl_xor_sync(0xffffffffu, acc, o);
        if (lane == 0) satt[n] = acc + cst;
    }
    __syncthreads();
    if (threadIdx.x < 32) {
        float a = satt[threadIdx.x];
        float mx = a;
#pragma unroll
        for (int o = 16; o; o >>= 1) mx = fmaxf(mx, __shfl_xor_sync(0xffffffffu, mx, o));
        float ex = expf(a - mx);
        float s = ex;
#pragma unroll
        for (int o = 16; o; o >>= 1) s += __shfl_xor_sync(0xffffffffu, s, o);
        salpha[threadIdx.x] = ex / s;
    }
    __syncthreads();
    for (int j = threadIdx.x; j < OUTD; j += 256) {
        float acc = 0.f;
#pragma unroll
        for (int n = 0; n < NPG; n++)
            acc += salpha[n] * zout[((size_t)b * NPG + n) * OUTD + j];
        hg[(size_t)b * OUTD + j] = acc;
    }
}

// ---------------- host orchestration ----------------
extern "C" void kernel_launch(void* const* d_in, const int* in_sizes, int n_in,
                              void* d_out, int out_size) {
    const int*   x        = (const int*)  d_in[0];
    const int*   edgeattr = (const int*)  d_in[1];
    const int*   eidx     = (const int*)  d_in[2];
    const float* node_tab = (const float*)d_in[4];
    const float* edge_tab = (const float*)d_in[5];
    const float* bondW    = (const float*)d_in[6];
    const float* bondB    = (const float*)d_in[7];
    const float* bondG    = (const float*)d_in[8];
    const float* bondBeta = (const float*)d_in[9];
    const float* atomW1   = (const float*)d_in[10];
    const float* atomB1   = (const float*)d_in[11];
    const float* atomG    = (const float*)d_in[12];
    const float* atomBeta = (const float*)d_in[13];
    const float* atomW2   = (const float*)d_in[14];
    const float* atomB2   = (const float*)d_in[15];
    const float* normG    = (const float*)d_in[16];
    const float* normB    = (const float*)d_in[17];
    const float* outW     = (const float*)d_in[18];
    const float* outB     = (const float*)d_in[19];
    const float* gapW     = (const float*)d_in[20];
    const float* gapB     = (const float*)d_in[21];
    const float* attW     = (const float*)d_in[22];
    const float* attB     = (const float*)d_in[23];
    const float* projW    = (const float*)d_in[24];
    const float* projB    = (const float*)d_in[25];
    float* out = (float*)d_out;

    float *p_z, *p_agg, *p_h, *p_zpre, *p_zout, *p_v, *p_hg, *p_stats;
    float *p_embu, *p_eeu, *p_eeact;
    int *p_combo, *p_cnt;
    __nv_bfloat16 *p_aggh, *p_aggl, *p_hh, *p_hl, *p_zh, *p_zl, *p_hgh, *p_hgl;
    __nv_bfloat16 *p_aW1h, *p_aW1l, *p_aW2h, *p_aW2l, *p_oWh, *p_oWl, *p_pWh, *p_pWl;
    cudaGetSymbolAddress((void**)&p_z, g_z);
    cudaGetSymbolAddress((void**)&p_agg, g_agg);
    cudaGetSymbolAddress((void**)&p_h, g_h);
    cudaGetSymbolAddress((void**)&p_zpre, g_zpre);
    cudaGetSymbolAddress((void**)&p_zout, g_zout);
    cudaGetSymbolAddress((void**)&p_v, g_v);
    cudaGetSymbolAddress((void**)&p_hg, g_hg);
    cudaGetSymbolAddress((void**)&p_stats, g_stats);
    cudaGetSymbolAddress((void**)&p_combo, g_combo);
    cudaGetSymbolAddress((void**)&p_cnt, g_cnt);
    cudaGetSymbolAddress((void**)&p_embu, g_embu);
    cudaGetSymbolAddress((void**)&p_eeu, g_eeu);
    cudaGetSymbolAddress((void**)&p_eeact, g_eeact);
    cudaGetSymbolAddress((void**)&p_aggh, g_aggh);
    cudaGetSymbolAddress((void**)&p_aggl, g_aggl);
    cudaGetSymbolAddress((void**)&p_hh, g_hh);
    cudaGetSymbolAddress((void**)&p_hl, g_hl);
    cudaGetSymbolAddress((void**)&p_zh, g_zh);
    cudaGetSymbolAddress((void**)&p_zl, g_zl);
    cudaGetSymbolAddress((void**)&p_hgh, g_hgh);
    cudaGetSymbolAddress((void**)&p_hgl, g_hgl);
    cudaGetSymbolAddress((void**)&p_aW1h, g_aW1h);
    cudaGetSymbolAddress((void**)&p_aW1l, g_aW1l);
    cudaGetSymbolAddress((void**)&p_aW2h, g_aW2h);
    cudaGetSymbolAddress((void**)&p_aW2l, g_aW2l);
    cudaGetSymbolAddress((void**)&p_oWh, g_oWh);
    cudaGetSymbolAddress((void**)&p_oWl, g_oWl);
    cudaGetSymbolAddress((void**)&p_pWh, g_pWh);
    cudaGetSymbolAddress((void**)&p_pWl, g_pWl);

    float* buf1 = p_stats;
    float* buf2 = p_stats + 2048;

    cudaFuncSetAttribute(gemm_mma<true >, cudaFuncAttributeMaxDynamicSharedMemorySize, GEMM_SMEM);
    cudaFuncSetAttribute(gemm_mma<false>, cudaFuncAttributeMaxDynamicSharedMemorySize, GEMM_SMEM);

    // weight transposes + bf16 split
    for (int l = 0; l < LL; l++) {
        transpose_split<<<dim3(H2 / 32, HH / 32), dim3(32, 8)>>>(
            atomW1 + (size_t)l * HH * H2, p_aW1h + (size_t)l * H2 * HH,
            p_aW1l + (size_t)l * H2 * HH, HH, H2);
        transpose_split<<<dim3(HH / 32, H2 / 32), dim3(32, 8)>>>(
            atomW2 + (size_t)l * H2 * HH, p_aW2h + (size_t)l * HH * H2,
            p_aW2l + (size_t)l * HH * H2, H2, HH);
    }
    transpose_split<<<dim3(OUTD / 32, HH / 32), dim3(32, 8)>>>(outW, p_oWh, p_oWl, HH, OUTD);
    transpose_split<<<dim3(OUTD / 32, OUTD / 32), dim3(32, 8)>>>(projW, p_pWh, p_pWl, OUTD, OUTD);

    // embeddings + edge combo machinery
    embed_nodes<<<NN, 256>>>(x, node_tab, p_z);
    cudaMemsetAsync(p_cnt, 0, NCOMBO * sizeof(int));
    combo_hist<<<(EE + 255) / 256, 256>>>(edgeattr, p_combo, p_cnt);
    embed_edges_u<<<NCOMBO, HEH>>>(edge_tab, p_embu);

    const size_t ZB = (size_t)NN * HH * sizeof(float);

    for (int l = 0; l < LL; l++) {
        const float* bW   = bondW    + (size_t)l * HEH * HH;
        const float* bB   = bondB    + (size_t)l * HH;
        const float* bG   = bondG    + (size_t)l * HH;
        const float* bBe  = bondBeta + (size_t)l * HH;
        const __nv_bfloat16* aW1h = p_aW1h + (size_t)l * H2 * HH;
        const __nv_bfloat16* aW1l = p_aW1l + (size_t)l * H2 * HH;
        const float* aB1  = atomB1   + (size_t)l * H2;
        const float* aG   = atomG    + (size_t)l * H2;
        const float* aBe  = atomBeta + (size_t)l * H2;
        const __nv_bfloat16* aW2h = p_aW2h + (size_t)l * HH * H2;
        const __nv_bfloat16* aW2l = p_aW2l + (size_t)l * HH * H2;
        const float* aB2  = atomB2   + (size_t)l * HH;
        const float* nG   = normG    + (size_t)l * HH;
        const float* nB   = normB    + (size_t)l * HH;

        // bond path on 264 unique combos
        bond_small<<<NCOMBO, HH>>>(p_embu, bW, bB, p_eeu);
        wstats<<<2, 256>>>(p_eeu, p_cnt, buf1);
        bn_prep<<<2, 256>>>(buf1, HH, 1.f / EE, bG, bBe);
        eeact_apply<<<NCOMBO, HH>>>(p_eeu, buf1, p_eeact);

        // agg = z + segment_sum(messages); then split to bf16 hi/lo
        cudaMemcpyAsync(p_agg, p_z, ZB, cudaMemcpyDeviceToDevice);
        scatter_msg<<<EE, 128>>>(p_eeact, p_combo, p_z, eidx, p_agg);
        split_f32<<<(unsigned)(((size_t)NN * HH / 4 + 255) / 256), 256>>>(
            p_agg, p_aggh, p_aggl, (size_t)NN * HH / 4);

        // h_pre = agg @ aW1 + aB1, stats fused
        cudaMemsetAsync(buf1, 0, 2048 * sizeof(float));
        gemm_mma<true><<<dim3(H2 / 128, NN / 128), 256, GEMM_SMEM>>>(
            H2, HH, p_aggh, p_aggl, aW1h, aW1l, aB1, p_h, buf1);
        bn_prep<<<4, 256>>>(buf1, H2, 1.f / NN, aG, aBe);

        // h_act = relu(bn(h_pre)) split to bf16 hi/lo
        bn_relu_split<<<(unsigned)(((size_t)NN * H2 / 4 + 255) / 256), 256>>>(
            p_h, p_hh, p_hl, (size_t)NN * H2 / 4, H2, buf1);

        // z_pre = h_act @ aW2 + aB2, stats fused
        cudaMemsetAsync(buf2, 0, 2048 * sizeof(float));
        gemm_mma<true><<<dim3(HH / 128, NN / 128), 256, GEMM_SMEM>>>(
            HH, H2, p_hh, p_hl, aW2h, aW2l, aB2, p_zpre, buf2);
        bn_prep<<<2, 256>>>(buf2, HH, 1.f / NN, nG, nB);
        bn_relu<<<(unsigned)(((size_t)NN * HH / 4 + 255) / 256), 256>>>(
            p_zpre, p_z, (size_t)NN * HH / 4, HH, buf2);
    }

    // zout = z @ outW + outB
    split_f32<<<(unsigned)(((size_t)NN * HH / 4 + 255) / 256), 256>>>(
        p_z, p_zh, p_zl, (size_t)NN * HH / 4);
    gemm_mma<false><<<dim3(OUTD / 128, NN / 128), 256, GEMM_SMEM>>>(
        OUTD, HH, p_zh, p_zl, p_oWh, p_oWl, outB, p_zout, nullptr);

    att_vec<<<129, 256>>>(gapW, gapB, attW, attB, p_v);
    pool<<<BB, 256>>>(p_zout, p_v, p_hg);

    // out = hg @ projW + projB
    split_f32<<<(unsigned)(((size_t)BB * OUTD / 4 + 255) / 256), 256>>>(
        p_hg, p_hgh, p_hgl, (size_t)BB * OUTD / 4);
    gemm_mma<false><<<dim3(OUTD / 128, BB / 128), 256, GEMM_SMEM>>>(
        OUTD, OUTD, p_hgh, p_hgl, p_pWh, p_pWl, projB, out, nullptr);
}

// round 6
// speedup vs baseline: 3.2352x; 1.1700x over previous
#include <cuda_runtime.h>
#include <cuda_bf16.h>
#include <cstdint>

// ---------------- problem constants ----------------
#define NN      32768
#define EE      131072
#define HH      512
#define HEH     128
#define H2      1024
#define OUTD    1024
#define BB      1024
#define NPG     32
#define EPG     128        // edges per graph
#define LL      6
#define EPSV    1e-5f
#define NCOMBO  264

__device__ __constant__ int c_node_off[9] = {0,119,128,139,151,160,165,173,175};

// ---------------- scratch (device globals; no allocs allowed) ----------------
__device__ float g_z    [(size_t)NN * HH];
__device__ float g_h    [(size_t)NN * H2];
__device__ float g_zpre [(size_t)NN * HH];
__device__ float g_zout [(size_t)NN * OUTD];
__device__ float g_v    [OUTD + 1];
__device__ float g_hg   [(size_t)BB * OUTD];
__device__ float g_stats[4096];
__device__ float g_estats[LL * 2048];
__device__ int   g_combo[EE];
__device__ int   g_cnt  [NCOMBO];
__device__ float g_embu [NCOMBO * HEH];
__device__ float g_eeu  [(size_t)LL * NCOMBO * HH];
__device__ float g_eeact[(size_t)LL * NCOMBO * HH];
// pre-split bf16 activations (hi/lo)
__device__ __nv_bfloat16 g_aggh[(size_t)NN * HH];
__device__ __nv_bfloat16 g_aggl[(size_t)NN * HH];
__device__ __nv_bfloat16 g_hh  [(size_t)NN * H2];
__device__ __nv_bfloat16 g_hl  [(size_t)NN * H2];
__device__ __nv_bfloat16 g_zh  [(size_t)NN * HH];
__device__ __nv_bfloat16 g_zl  [(size_t)NN * HH];
__device__ __nv_bfloat16 g_hgh [(size_t)BB * OUTD];
__device__ __nv_bfloat16 g_hgl [(size_t)BB * OUTD];
// pre-split transposed weights [N, K] bf16 hi/lo
__device__ __nv_bfloat16 g_aW1h[(size_t)LL * H2 * HH];
__device__ __nv_bfloat16 g_aW1l[(size_t)LL * H2 * HH];
__device__ __nv_bfloat16 g_aW2h[(size_t)LL * HH * H2];
__device__ __nv_bfloat16 g_aW2l[(size_t)LL * HH * H2];
__device__ __nv_bfloat16 g_oWh [(size_t)OUTD * HH];
__device__ __nv_bfloat16 g_oWl [(size_t)OUTD * HH];
__device__ __nv_bfloat16 g_pWh [(size_t)OUTD * OUTD];
__device__ __nv_bfloat16 g_pWl [(size_t)OUTD * OUTD];

// ---------------- asm helpers ----------------
__device__ __forceinline__ uint32_t smem_u32(const void* p) {
    uint32_t a;
    asm("{ .reg .u64 t; cvta.to.shared.u64 t, %1; cvt.u32.u64 %0, t; }" : "=r"(a) : "l"(p));
    return a;
}
__device__ __forceinline__ void ldm_x4(uint32_t* r, uint32_t addr) {
    asm volatile("ldmatrix.sync.aligned.m8n8.x4.shared.b16 {%0,%1,%2,%3}, [%4];"
                 : "=r"(r[0]), "=r"(r[1]), "=r"(r[2]), "=r"(r[3]) : "r"(addr));
}
__device__ __forceinline__ void mma_bf16(float* c, const uint32_t* a, const uint32_t* b) {
    asm volatile("mma.sync.aligned.m16n8k16.row.col.f32.bf16.bf16.f32 "
                 "{%0,%1,%2,%3}, {%4,%5,%6,%7}, {%8,%9}, {%0,%1,%2,%3};"
                 : "+f"(c[0]), "+f"(c[1]), "+f"(c[2]), "+f"(c[3])
                 : "r"(a[0]), "r"(a[1]), "r"(a[2]), "r"(a[3]), "r"(b[0]), "r"(b[1]));
}
__device__ __forceinline__ void cpasync16(uint32_t sa, const void* ga) {
    asm volatile("cp.async.cg.shared.global [%0], [%1], 16;" :: "r"(sa), "l"(ga));
}
#define CP_COMMIT() asm volatile("cp.async.commit_group;" ::: "memory")
#define CP_WAIT1()  asm volatile("cp.async.wait_group 1;" ::: "memory")

__device__ __forceinline__ uint32_t pk(__nv_bfloat16 a, __nv_bfloat16 b) {
    return (uint32_t)__bfloat16_as_ushort(a) | ((uint32_t)__bfloat16_as_ushort(b) << 16);
}
__device__ __forceinline__ void split4(float4 v, uint2& hi, uint2& lo) {
    __nv_bfloat16 h0 = __float2bfloat16(v.x), h1 = __float2bfloat16(v.y);
    __nv_bfloat16 h2 = __float2bfloat16(v.z), h3 = __float2bfloat16(v.w);
    __nv_bfloat16 l0 = __float2bfloat16(v.x - __bfloat162float(h0));
    __nv_bfloat16 l1 = __float2bfloat16(v.y - __bfloat162float(h1));
    __nv_bfloat16 l2 = __float2bfloat16(v.z - __bfloat162float(h2));
    __nv_bfloat16 l3 = __float2bfloat16(v.w - __bfloat162float(h3));
    hi = make_uint2(pk(h0, h1), pk(h2, h3));
    lo = make_uint2(pk(l0, l1), pk(l2, l3));
}

// SMEM tile: 128 rows x 32 bf16 (64B data), row stride 80B
#define ROWB   80
#define TILEB  (128 * ROWB)
#define STAGEB (4 * TILEB)
#define GEMM_SMEM (2 * STAGEB)

// ---------------- tensor-core GEMM (all operands pre-split bf16) ----------------
template <bool STATS>
__global__ void __launch_bounds__(256, 2)
gemm_mma(int N, int K,
         const __nv_bfloat16* __restrict__ Ah, const __nv_bfloat16* __restrict__ Al,
         const __nv_bfloat16* __restrict__ Bh, const __nv_bfloat16* __restrict__ Bl,
         const float* __restrict__ bias, float* __restrict__ C,
         float* __restrict__ stats) {
    extern __shared__ char smem[];

    const int tid = threadIdx.x, lane = tid & 31, wid = tid >> 5;
    const int wr = wid >> 2, wc = wid & 3;
    const int brow = blockIdx.y, bcol = blockIdx.x;

    const size_t Kb = (size_t)K * 2;
    const char* pAh = (const char*)(Ah + (size_t)brow * 128 * K);
    const char* pAl = (const char*)(Al + (size_t)brow * 128 * K);
    const char* pBh = (const char*)(Bh + (size_t)bcol * 128 * K);
    const char* pBl = (const char*)(Bl + (size_t)bcol * 128 * K);

    const uint32_t ubase = smem_u32(smem);
    const int r0 = tid >> 2, c0 = (tid & 3) * 16;
    const int r1 = (tid >> 2) + 64, c1 = (tid & 3) * 16;

    auto issue = [&](int k0, int s) {
        uint32_t base = ubase + s * STAGEB;
        size_t g0 = (size_t)r0 * Kb + (size_t)k0 * 64 + c0;
        size_t g1 = (size_t)r1 * Kb + (size_t)k0 * 64 + c1;
        uint32_t s0 = (uint32_t)(r0 * ROWB + c0);
        uint32_t s1 = (uint32_t)(r1 * ROWB + c1);
        cpasync16(base + s0,             pAh + g0);
        cpasync16(base + s1,             pAh + g1);
        cpasync16(base + TILEB + s0,     pAl + g0);
        cpasync16(base + TILEB + s1,     pAl + g1);
        cpasync16(base + 2 * TILEB + s0, pBh + g0);
        cpasync16(base + 2 * TILEB + s1, pBh + g1);
        cpasync16(base + 3 * TILEB + s0, pBl + g0);
        cpasync16(base + 3 * TILEB + s1, pBl + g1);
    };

    float acc[4][4][4];
#pragma unroll
    for (int i = 0; i < 4; i++)
#pragma unroll
        for (int j = 0; j < 4; j++)
#pragma unroll
            for (int q = 0; q < 4; q++) acc[i][j][q] = 0.f;

    const int a_row  = (lane & 15);
    const int a_half = (lane >> 4) * 16;
    const int b_row  = (lane & 7) + ((lane >> 4) << 3);
    const int b_half = ((lane >> 3) & 1) * 16;

    auto compute = [&](int s) {
        uint32_t uAh = ubase + s * STAGEB;
        uint32_t uAl = uAh + TILEB, uBh = uAl + TILEB, uBl = uBh + TILEB;
#pragma unroll
        for (int ks = 0; ks < 2; ks++) {
            const int kb = ks * 32;
            uint32_t ah[4][4], al[4][4];
#pragma unroll
            for (int mt = 0; mt < 4; mt++) {
                uint32_t off = (uint32_t)((wr * 64 + mt * 16 + a_row) * ROWB + kb + a_half);
                ldm_x4(ah[mt], uAh + off);
                ldm_x4(al[mt], uAl + off);
            }
            uint32_t bh[4][2], bl[4][2];
#pragma unroll
            for (int np = 0; np < 2; np++) {
                uint32_t off = (uint32_t)((wc * 32 + np * 16 + b_row) * ROWB + kb + b_half);
                uint32_t r[4];
                ldm_x4(r, uBh + off);
                bh[np * 2][0] = r[0]; bh[np * 2][1] = r[1];
                bh[np * 2 + 1][0] = r[2]; bh[np * 2 + 1][1] = r[3];
                ldm_x4(r, uBl + off);
                bl[np * 2][0] = r[0]; bl[np * 2][1] = r[1];
                bl[np * 2 + 1][0] = r[2]; bl[np * 2 + 1][1] = r[3];
            }
#pragma unroll
            for (int mt = 0; mt < 4; mt++)
#pragma unroll
                for (int nt = 0; nt < 4; nt++) {
                    mma_bf16(acc[mt][nt], ah[mt], bh[nt]);
                    mma_bf16(acc[mt][nt], ah[mt], bl[nt]);
                    mma_bf16(acc[mt][nt], al[mt], bh[nt]);
                }
        }
    };

    const int nk = K >> 5;
    issue(0, 0); CP_COMMIT();
    issue(1, 1); CP_COMMIT();
    for (int k = 0; k < nk; k++) {
        const int s = k & 1;
        CP_WAIT1();
        __syncthreads();
        compute(s);
        __syncthreads();
        if (k + 2 < nk) issue(k + 2, s);
        CP_COMMIT();
    }

    float s1[8], s2[8];
    if (STATS) {
#pragma unroll
        for (int j = 0; j < 8; j++) { s1[j] = 0.f; s2[j] = 0.f; }
    }
#pragma unroll
    for (int mt = 0; mt < 4; mt++) {
        int row0 = brow * 128 + wr * 64 + mt * 16 + (lane >> 2);
#pragma unroll
        for (int nt = 0; nt < 4; nt++) {
            int col = bcol * 128 + wc * 32 + nt * 8 + (lane & 3) * 2;
            float b0 = bias[col], b1 = bias[col + 1];
            float v00 = acc[mt][nt][0] + b0, v01 = acc[mt][nt][1] + b1;
            float v10 = acc[mt][nt][2] + b0, v11 = acc[mt][nt][3] + b1;
            *(float2*)(C + (size_t)row0 * N + col) = make_float2(v00, v01);
            *(float2*)(C + (size_t)(row0 + 8) * N + col) = make_float2(v10, v11);
            if (STATS) {
                s1[nt * 2 + 0] += v00 + v10;
                s1[nt * 2 + 1] += v01 + v11;
                s2[nt * 2 + 0] += v00 * v00 + v10 * v10;
                s2[nt * 2 + 1] += v01 * v01 + v11 * v11;
            }
        }
    }
    if (STATS) {
#pragma unroll
        for (int j = 0; j < 8; j++) {
#pragma unroll
            for (int o = 4; o <= 16; o <<= 1) {
                s1[j] += __shfl_xor_sync(0xffffffffu, s1[j], o);
                s2[j] += __shfl_xor_sync(0xffffffffu, s2[j], o);
            }
        }
        if (lane < 4) {
#pragma unroll
            for (int nt = 0; nt < 4; nt++) {
#pragma unroll
                for (int p = 0; p < 2; p++) {
                    int col = bcol * 128 + wc * 32 + nt * 8 + lane * 2 + p;
                    atomicAdd(&stats[col], s1[nt * 2 + p]);
                    atomicAdd(&stats[1024 + col], s2[nt * 2 + p]);
                }
            }
        }
    }
}

// ---------------- per-graph aggregation (no atomics) ----------------
// agg[b,n] = z[b,n] + sum_{e in graph b} (z[src_e] + eeact[combo_e]) [dst_e == n]
// One CTA per graph, 512 threads = columns. SMEM accumulator 32x512 fp32.
// Writes bf16 hi/lo split directly.
__global__ void __launch_bounds__(512, 2)
graph_aggregate(const float* __restrict__ z, const float* __restrict__ eeact,
                const int* __restrict__ eidx, const int* __restrict__ combo,
                __nv_bfloat16* __restrict__ aggh, __nv_bfloat16* __restrict__ aggl) {
    extern __shared__ float sagg[];   // NPG * HH floats = 64KB
    __shared__ int s_src[EPG], s_dst[EPG], s_u[EPG];

    const int b = blockIdx.x;
    const int tid = threadIdx.x;      // column 0..511

    if (tid < EPG) {
        s_src[tid] = eidx[b * EPG + tid] - b * NPG;
        s_dst[tid] = eidx[EE + b * EPG + tid] - b * NPG;
        s_u[tid]   = combo[b * EPG + tid];
    }
    const float* zb = z + (size_t)b * NPG * HH;
#pragma unroll
    for (int n = 0; n < NPG; n++)
        sagg[n * HH + tid] = zb[n * HH + tid];
    __syncthreads();

    // software-pipelined accumulation
    float zv = __ldg(&zb[s_src[0] * HH + tid]);
    float ev = __ldg(&eeact[(size_t)s_u[0] * HH + tid]);
#pragma unroll 4
    for (int e = 0; e < EPG; e++) {
        float cur = zv + ev;
        int d = s_dst[e];
        if (e + 1 < EPG) {
            zv = __ldg(&zb[s_src[e + 1] * HH + tid]);
            ev = __ldg(&eeact[(size_t)s_u[e + 1] * HH + tid]);
        }
        sagg[d * HH + tid] += cur;
    }
    __syncthreads();

    __nv_bfloat16* oh = aggh + (size_t)b * NPG * HH + tid;
    __nv_bfloat16* ol = aggl + (size_t)b * NPG * HH + tid;
#pragma unroll
    for (int n = 0; n < NPG; n++) {
        float v = sagg[n * HH + tid];
        __nv_bfloat16 h = __float2bfloat16(v);
        __nv_bfloat16 l = __float2bfloat16(v - __bfloat162float(h));
        oh[n * HH] = h;
        ol[n * HH] = l;
    }
}

// ---------------- weight transpose + split ----------------
__global__ void transpose_split(const float* __restrict__ S,
                                __nv_bfloat16* __restrict__ Dh,
                                __nv_bfloat16* __restrict__ Dl, int K, int N) {
    __shared__ float t[32][33];
    int k0 = blockIdx.y * 32, n0 = blockIdx.x * 32;
    int x = threadIdx.x, y = threadIdx.y;
#pragma unroll
    for (int i = 0; i < 32; i += 8) t[y + i][x] = S[(size_t)(k0 + y + i) * N + n0 + x];
    __syncthreads();
#pragma unroll
    for (int i = 0; i < 32; i += 8) {
        float v = t[x][y + i];
        __nv_bfloat16 h = __float2bfloat16(v);
        __nv_bfloat16 l = __float2bfloat16(v - __bfloat162float(h));
        Dh[(size_t)(n0 + y + i) * K + k0 + x] = h;
        Dl[(size_t)(n0 + y + i) * K + k0 + x] = l;
    }
}

// ---------------- split / bn passes ----------------
__global__ void split_f32(const float* __restrict__ X,
                          __nv_bfloat16* __restrict__ Xh, __nv_bfloat16* __restrict__ Xl,
                          size_t total4) {
    size_t i = (size_t)blockIdx.x * blockDim.x + threadIdx.x;
    if (i >= total4) return;
    uint2 hi, lo;
    split4(((const float4*)X)[i], hi, lo);
    ((uint2*)Xh)[i] = hi;
    ((uint2*)Xl)[i] = lo;
}

__global__ void bn_relu_split(const float* __restrict__ X,
                              __nv_bfloat16* __restrict__ Xh, __nv_bfloat16* __restrict__ Xl,
                              size_t total4, int cols, const float* __restrict__ stats) {
    size_t i = (size_t)blockIdx.x * blockDim.x + threadIdx.x;
    if (i >= total4) return;
    int c = (int)((i * 4) % cols);
    float4 x = ((const float4*)X)[i];
    float4 y;
    y.x = fmaxf(0.f, x.x * stats[c + 0] + stats[1024 + c + 0]);
    y.y = fmaxf(0.f, x.y * stats[c + 1] + stats[1024 + c + 1]);
    y.z = fmaxf(0.f, x.z * stats[c + 2] + stats[1024 + c + 2]);
    y.w = fmaxf(0.f, x.w * stats[c + 3] + stats[1024 + c + 3]);
    uint2 hi, lo;
    split4(y, hi, lo);
    ((uint2*)Xh)[i] = hi;
    ((uint2*)Xl)[i] = lo;
}

__global__ void bn_relu(const float* __restrict__ X, float* __restrict__ Y,
                        size_t total4, int cols, const float* __restrict__ stats) {
    size_t i = (size_t)blockIdx.x * blockDim.x + threadIdx.x;
    if (i >= total4) return;
    int c = (int)((i * 4) % cols);
    float4 x = ((const float4*)X)[i];
    float4 y;
    y.x = fmaxf(0.f, x.x * stats[c + 0] + stats[1024 + c + 0]);
    y.y = fmaxf(0.f, x.y * stats[c + 1] + stats[1024 + c + 1]);
    y.z = fmaxf(0.f, x.z * stats[c + 2] + stats[1024 + c + 2]);
    y.w = fmaxf(0.f, x.w * stats[c + 3] + stats[1024 + c + 3]);
    ((float4*)Y)[i] = y;
}

// ---------------- embeddings / batched bond path ----------------
__global__ void embed_nodes(const int* __restrict__ x, const float* __restrict__ tab,
                            float* __restrict__ z) {
    int n = blockIdx.x;
    __shared__ int idx[9];
    if (threadIdx.x < 9) idx[threadIdx.x] = x[n * 9 + threadIdx.x] + c_node_off[threadIdx.x];
    __syncthreads();
    for (int c = threadIdx.x; c < HH; c += blockDim.x) {
        float acc = 0.f;
#pragma unroll
        for (int f = 0; f < 9; f++) acc += tab[(size_t)idx[f] * HH + c];
        z[(size_t)n * HH + c] = acc;
    }
}

__global__ void combo_hist(const int* __restrict__ ea, int* __restrict__ combo,
                           int* __restrict__ cnt) {
    int e = blockIdx.x * 256 + threadIdx.x;
    if (e >= EE) return;
    int c = ea[e * 3] * 12 + ea[e * 3 + 1] * 2 + ea[e * 3 + 2];
    combo[e] = c;
    atomicAdd(&cnt[c], 1);
}

__global__ void embed_edges_u(const float* __restrict__ tab, float* __restrict__ embu) {
    int u = blockIdx.x;
    int a0 = u / 12, a1 = (u % 12) / 2, a2 = u & 1;
    int c = threadIdx.x;
    embu[u * HEH + c] = tab[(size_t)a0 * HEH + c]
                      + tab[(size_t)(119 + a1) * HEH + c]
                      + tab[(size_t)(128 + a2) * HEH + c];
}

// batched over layers: grid (NCOMBO, LL)
__global__ void bond_small(const float* __restrict__ embu, const float* __restrict__ bondW,
                           const float* __restrict__ bondB, float* __restrict__ eeu) {
    __shared__ float se[HEH];
    int u = blockIdx.x, l = blockIdx.y;
    const float* bW = bondW + (size_t)l * HEH * HH;
    if (threadIdx.x < HEH) se[threadIdx.x] = embu[u * HEH + threadIdx.x];
    __syncthreads();
    int c = threadIdx.x;
    float acc = bondB[l * HH + c];
#pragma unroll 4
    for (int k = 0; k < HEH; k++) acc += se[k] * bW[(size_t)k * HH + c];
    eeu[((size_t)l * NCOMBO + u) * HH + c] = acc;
}

// grid (2, LL)
__global__ void wstats(const float* __restrict__ eeu, const int* __restrict__ cnt,
                       float* __restrict__ estats) {
    int l = blockIdx.y;
    int c = blockIdx.x * 256 + threadIdx.x;
    const float* base = eeu + (size_t)l * NCOMBO * HH;
    float m = 0.f, q = 0.f;
    for (int u = 0; u < NCOMBO; u++) {
        float w = (float)cnt[u];
        float v = base[u * HH + c];
        m += w * v;
        q += w * v * v;
    }
    estats[l * 2048 + c] = m;
    estats[l * 2048 + 1024 + c] = q;
}

// grid (2, LL): edge BN prep, batched
__global__ void bn_prep_e(float* __restrict__ estats, const float* __restrict__ g,
                          const float* __restrict__ b) {
    int l = blockIdx.y;
    int c = blockIdx.x * 256 + threadIdx.x;
    float* st = estats + l * 2048;
    float m = st[c] * (1.f / EE);
    float var = st[1024 + c] * (1.f / EE) - m * m;
    float sc = g[l * HH + c] * rsqrtf(var + EPSV);
    st[c] = sc;
    st[1024 + c] = b[l * HH + c] - m * sc;
}

// grid (NCOMBO, LL)
__global__ void eeact_apply(const float* __restrict__ eeu, const float* __restrict__ estats,
                            float* __restrict__ eeact) {
    int u = blockIdx.x, l = blockIdx.y;
    int c = threadIdx.x;
    const float* st = estats + l * 2048;
    size_t i = ((size_t)l * NCOMBO + u) * HH + c;
    eeact[i] = fmaxf(0.f, eeu[i] * st[c] + st[1024 + c]);
}

// node BN prep (per-layer)
__global__ void bn_prep(float* __restrict__ stats, int cols, float inv_rows,
                        const float* __restrict__ g, const float* __restrict__ b) {
    int c = blockIdx.x * blockDim.x + threadIdx.x;
    if (c >= cols) return;
    float m = stats[c] * inv_rows;
    float var = stats[1024 + c] * inv_rows - m * m;
    float sc = g[c] * rsqrtf(var + EPSV);
    stats[c] = sc;
    stats[1024 + c] = b[c] - m * sc;
}

// ---------------- pooling ----------------
__global__ void att_vec(const float* __restrict__ gapW, const float* __restrict__ gapB,
                        const float* __restrict__ attW, const float* __restrict__ attB,
                        float* __restrict__ v) {
    int w = blockIdx.x * (blockDim.x / 32) + (threadIdx.x / 32);
    int lane = threadIdx.x & 31;
    if (w > OUTD) return;
    const float* row = (w < OUTD) ? (gapW + (size_t)w * HH) : gapB;
    float acc = 0.f;
    for (int h = lane; h < HH; h += 32) acc += row[h] * attW[h];
#pragma unroll
    for (int o = 16; o; o >>= 1) acc += __shfl_xor_sync(0xffffffffu, acc, o);
    if (lane == 0) v[w] = acc + ((w == OUTD) ? attB[0] : 0.f);
}

__global__ void pool(const float* __restrict__ zout, const float* __restrict__ v,
                     float* __restrict__ hg) {
    __shared__ float satt[NPG];
    __shared__ float salpha[NPG];
    int b = blockIdx.x;
    int warp = threadIdx.x / 32, lane = threadIdx.x & 31;
    const float cst = v[OUTD];
    for (int n = warp; n < NPG; n += 8) {
        const float* row = zout + ((size_t)b * NPG + n) * OUTD;
        float acc = 0.f;
        for (int k = lane; k < OUTD; k += 32) acc += row[k] * v[k];
#pragma unroll
        for (int o = 16; o; o >>= 1) acc += __shfl_xor_sync(0xffffffffu, acc, o);
        if (lane == 0) satt[n] = acc + cst;
    }
    __syncthreads();
    if (threadIdx.x < 32) {
        float a = satt[threadIdx.x];
        float mx = a;
#pragma unroll
        for (int o = 16; o; o >>= 1) mx = fmaxf(mx, __shfl_xor_sync(0xffffffffu, mx, o));
        float ex = expf(a - mx);
        float s = ex;
#pragma unroll
        for (int o = 16; o; o >>= 1) s += __shfl_xor_sync(0xffffffffu, s, o);
        salpha[threadIdx.x] = ex / s;
    }
    __syncthreads();
    for (int j = threadIdx.x; j < OUTD; j += 256) {
        float acc = 0.f;
#pragma unroll
        for (int n = 0; n < NPG; n++)
            acc += salpha[n] * zout[((size_t)b * NPG + n) * OUTD + j];
        hg[(size_t)b * OUTD + j] = acc;
    }
}

// ---------------- host orchestration ----------------
extern "C" void kernel_launch(void* const* d_in, const int* in_sizes, int n_in,
                              void* d_out, int out_size) {
    const int*   x        = (const int*)  d_in[0];
    const int*   edgeattr = (const int*)  d_in[1];
    const int*   eidx     = (const int*)  d_in[2];
    const float* node_tab = (const float*)d_in[4];
    const float* edge_tab = (const float*)d_in[5];
    const float* bondW    = (const float*)d_in[6];
    const float* bondB    = (const float*)d_in[7];
    const float* bondG    = (const float*)d_in[8];
    const float* bondBeta = (const float*)d_in[9];
    const float* atomW1   = (const float*)d_in[10];
    const float* atomB1   = (const float*)d_in[11];
    const float* atomG    = (const float*)d_in[12];
    const float* atomBeta = (const float*)d_in[13];
    const float* atomW2   = (const float*)d_in[14];
    const float* atomB2   = (const float*)d_in[15];
    const float* normG    = (const float*)d_in[16];
    const float* normB    = (const float*)d_in[17];
    const float* outW     = (const float*)d_in[18];
    const float* outB     = (const float*)d_in[19];
    const float* gapW     = (const float*)d_in[20];
    const float* gapB     = (const float*)d_in[21];
    const float* attW     = (const float*)d_in[22];
    const float* attB     = (const float*)d_in[23];
    const float* projW    = (const float*)d_in[24];
    const float* projB    = (const float*)d_in[25];
    float* out = (float*)d_out;

    float *p_z, *p_h, *p_zpre, *p_zout, *p_v, *p_hg, *p_stats, *p_estats;
    float *p_embu, *p_eeu, *p_eeact;
    int *p_combo, *p_cnt;
    __nv_bfloat16 *p_aggh, *p_aggl, *p_hh, *p_hl, *p_zh, *p_zl, *p_hgh, *p_hgl;
    __nv_bfloat16 *p_aW1h, *p_aW1l, *p_aW2h, *p_aW2l, *p_oWh, *p_oWl, *p_pWh, *p_pWl;
    cudaGetSymbolAddress((void**)&p_z, g_z);
    cudaGetSymbolAddress((void**)&p_h, g_h);
    cudaGetSymbolAddress((void**)&p_zpre, g_zpre);
    cudaGetSymbolAddress((void**)&p_zout, g_zout);
    cudaGetSymbolAddress((void**)&p_v, g_v);
    cudaGetSymbolAddress((void**)&p_hg, g_hg);
    cudaGetSymbolAddress((void**)&p_stats, g_stats);
    cudaGetSymbolAddress((void**)&p_estats, g_estats);
    cudaGetSymbolAddress((void**)&p_combo, g_combo);
    cudaGetSymbolAddress((void**)&p_cnt, g_cnt);
    cudaGetSymbolAddress((void**)&p_embu, g_embu);
    cudaGetSymbolAddress((void**)&p_eeu, g_eeu);
    cudaGetSymbolAddress((void**)&p_eeact, g_eeact);
    cudaGetSymbolAddress((void**)&p_aggh, g_aggh);
    cudaGetSymbolAddress((void**)&p_aggl, g_aggl);
    cudaGetSymbolAddress((void**)&p_hh, g_hh);
    cudaGetSymbolAddress((void**)&p_hl, g_hl);
    cudaGetSymbolAddress((void**)&p_zh, g_zh);
    cudaGetSymbolAddress((void**)&p_zl, g_zl);
    cudaGetSymbolAddress((void**)&p_hgh, g_hgh);
    cudaGetSymbolAddress((void**)&p_hgl, g_hgl);
    cudaGetSymbolAddress((void**)&p_aW1h, g_aW1h);
    cudaGetSymbolAddress((void**)&p_aW1l, g_aW1l);
    cudaGetSymbolAddress((void**)&p_aW2h, g_aW2h);
    cudaGetSymbolAddress((void**)&p_aW2l, g_aW2l);
    cudaGetSymbolAddress((void**)&p_oWh, g_oWh);
    cudaGetSymbolAddress((void**)&p_oWl, g_oWl);
    cudaGetSymbolAddress((void**)&p_pWh, g_pWh);
    cudaGetSymbolAddress((void**)&p_pWl, g_pWl);

    float* buf1 = p_stats;
    float* buf2 = p_stats + 2048;

    cudaFuncSetAttribute(gemm_mma<true >, cudaFuncAttributeMaxDynamicSharedMemorySize, GEMM_SMEM);
    cudaFuncSetAttribute(gemm_mma<false>, cudaFuncAttributeMaxDynamicSharedMemorySize, GEMM_SMEM);
    cudaFuncSetAttribute(graph_aggregate, cudaFuncAttributeMaxDynamicSharedMemorySize,
                         NPG * HH * (int)sizeof(float));

    // weight transposes + bf16 split
    for (int l = 0; l < LL; l++) {
        transpose_split<<<dim3(H2 / 32, HH / 32), dim3(32, 8)>>>(
            atomW1 + (size_t)l * HH * H2, p_aW1h + (size_t)l * H2 * HH,
            p_aW1l + (size_t)l * H2 * HH, HH, H2);
        transpose_split<<<dim3(HH / 32, H2 / 32), dim3(32, 8)>>>(
            atomW2 + (size_t)l * H2 * HH, p_aW2h + (size_t)l * HH * H2,
            p_aW2l + (size_t)l * HH * H2, H2, HH);
    }
    transpose_split<<<dim3(OUTD / 32, HH / 32), dim3(32, 8)>>>(outW, p_oWh, p_oWl, HH, OUTD);
    transpose_split<<<dim3(OUTD / 32, OUTD / 32), dim3(32, 8)>>>(projW, p_pWh, p_pWl, OUTD, OUTD);

    // embeddings + edge combo machinery
    embed_nodes<<<NN, 256>>>(x, node_tab, p_z);
    cudaMemsetAsync(p_cnt, 0, NCOMBO * sizeof(int));
    combo_hist<<<(EE + 255) / 256, 256>>>(edgeattr, p_combo, p_cnt);
    embed_edges_u<<<NCOMBO, HEH>>>(edge_tab, p_embu);

    // precompute ALL layers' bond tables (independent of node states)
    bond_small<<<dim3(NCOMBO, LL), HH>>>(p_embu, bondW, bondB, p_eeu);
    wstats<<<dim3(2, LL), 256>>>(p_eeu, p_cnt, p_estats);
    bn_prep_e<<<dim3(2, LL), 256>>>(p_estats, bondG, bondBeta);
    eeact_apply<<<dim3(NCOMBO, LL), HH>>>(p_eeu, p_estats, p_eeact);

    for (int l = 0; l < LL; l++) {
        const __nv_bfloat16* aW1h = p_aW1h + (size_t)l * H2 * HH;
        const __nv_bfloat16* aW1l = p_aW1l + (size_t)l * H2 * HH;
        const float* aB1  = atomB1   + (size_t)l * H2;
        const float* aG   = atomG    + (size_t)l * H2;
        const float* aBe  = atomBeta + (size_t)l * H2;
        const __nv_bfloat16* aW2h = p_aW2h + (size_t)l * HH * H2;
        const __nv_bfloat16* aW2l = p_aW2l + (size_t)l * HH * H2;
        const float* aB2  = atomB2   + (size_t)l * HH;
        const float* nG   = normG    + (size_t)l * HH;
        const float* nB   = normB    + (size_t)l * HH;

        // per-graph aggregation, writes split bf16 agg directly
        graph_aggregate<<<BB, 512, NPG * HH * sizeof(float)>>>(
            p_z, p_eeact + (size_t)l * NCOMBO * HH, eidx, p_combo, p_aggh, p_aggl);

        // h_pre = agg @ aW1 + aB1, stats fused
        cudaMemsetAsync(buf1, 0, 2048 * sizeof(float));
        gemm_mma<true><<<dim3(H2 / 128, NN / 128), 256, GEMM_SMEM>>>(
            H2, HH, p_aggh, p_aggl, aW1h, aW1l, aB1, p_h, buf1);
        bn_prep<<<4, 256>>>(buf1, H2, 1.f / NN, aG, aBe);

        // h_act = relu(bn(h_pre)) split to bf16 hi/lo
        bn_relu_split<<<(unsigned)(((size_t)NN * H2 / 4 + 255) / 256), 256>>>(
            p_h, p_hh, p_hl, (size_t)NN * H2 / 4, H2, buf1);

        // z_pre = h_act @ aW2 + aB2, stats fused
        cudaMemsetAsync(buf2, 0, 2048 * sizeof(float));
        gemm_mma<true><<<dim3(HH / 128, NN / 128), 256, GEMM_SMEM>>>(
            HH, H2, p_hh, p_hl, aW2h, aW2l, aB2, p_zpre, buf2);
        bn_prep<<<2, 256>>>(buf2, HH, 1.f / NN, nG, nB);
        bn_relu<<<(unsigned)(((size_t)NN * HH / 4 + 255) / 256), 256>>>(
            p_zpre, p_z, (size_t)NN * HH / 4, HH, buf2);
    }

    // zout = z @ outW + outB
    split_f32<<<(unsigned)(((size_t)NN * HH / 4 + 255) / 256), 256>>>(
        p_z, p_zh, p_zl, (size_t)NN * HH / 4);
    gemm_mma<false><<<dim3(OUTD / 128, NN / 128), 256, GEMM_SMEM>>>(
        OUTD, HH, p_zh, p_zl, p_oWh, p_oWl, outB, p_zout, nullptr);

    att_vec<<<129, 256>>>(gapW, gapB, attW, attB, p_v);
    pool<<<BB, 256>>>(p_zout, p_v, p_hg);

    // out = hg @ projW + projB
    split_f32<<<(unsigned)(((size_t)BB * OUTD / 4 + 255) / 256), 256>>>(
        p_hg, p_hgh, p_hgl, (size_t)BB * OUTD / 4);
    gemm_mma<false><<<dim3(OUTD / 128, BB / 128), 256, GEMM_SMEM>>>(
        OUTD, OUTD, p_hgh, p_hgl, p_pWh, p_pWl, projB, out, nullptr);
}

// round 7
// speedup vs baseline: 3.6929x; 1.1415x over previous
#include <cuda_runtime.h>
#include <cuda_bf16.h>
#include <cstdint>

// ---------------- problem constants ----------------
#define NN      32768
#define EE      131072
#define HH      512
#define HEH     128
#define H2      1024
#define OUTD    1024
#define BB      1024
#define NPG     32
#define EPG     128
#define LL      6
#define EPSV    1e-5f
#define NCOMBO  264

__device__ __constant__ int c_node_off[9] = {0,119,128,139,151,160,165,173,175};

// ---------------- scratch (device globals; no allocs allowed) ----------------
__device__ float g_z    [(size_t)NN * HH];     // initial embeddings only
__device__ float g_h    [(size_t)NN * H2];
__device__ float g_zpre [(size_t)NN * HH];
__device__ float g_zout [(size_t)NN * OUTD];
__device__ float g_v    [OUTD + 1];
__device__ float g_hg   [(size_t)BB * OUTD];
__device__ float g_stats[8192];     // stats1, stats2, bnp1, bnp2 (2048 each)
__device__ float g_estats[LL * 2048];
__device__ int   g_combo[EE];
__device__ int   g_cnt  [NCOMBO];
__device__ float g_embu [NCOMBO * HEH];
__device__ float g_eeu  [(size_t)LL * NCOMBO * HH];
__device__ float g_eeact[(size_t)LL * NCOMBO * HH];
// pre-split bf16 activations (hi/lo)
__device__ __nv_bfloat16 g_aggh[(size_t)NN * HH];
__device__ __nv_bfloat16 g_aggl[(size_t)NN * HH];
__device__ __nv_bfloat16 g_hh  [(size_t)NN * H2];
__device__ __nv_bfloat16 g_hl  [(size_t)NN * H2];
__device__ __nv_bfloat16 g_zh  [(size_t)NN * HH];
__device__ __nv_bfloat16 g_zl  [(size_t)NN * HH];
__device__ __nv_bfloat16 g_hgh [(size_t)BB * OUTD];
__device__ __nv_bfloat16 g_hgl [(size_t)BB * OUTD];
// pre-split transposed weights [N, K] bf16 hi/lo
__device__ __nv_bfloat16 g_aW1h[(size_t)LL * H2 * HH];
__device__ __nv_bfloat16 g_aW1l[(size_t)LL * H2 * HH];
__device__ __nv_bfloat16 g_aW2h[(size_t)LL * HH * H2];
__device__ __nv_bfloat16 g_aW2l[(size_t)LL * HH * H2];
__device__ __nv_bfloat16 g_oWh [(size_t)OUTD * HH];
__device__ __nv_bfloat16 g_oWl [(size_t)OUTD * HH];
__device__ __nv_bfloat16 g_pWh [(size_t)OUTD * OUTD];
__device__ __nv_bfloat16 g_pWl [(size_t)OUTD * OUTD];

// ---------------- asm helpers ----------------
__device__ __forceinline__ uint32_t smem_u32(const void* p) {
    uint32_t a;
    asm("{ .reg .u64 t; cvta.to.shared.u64 t, %1; cvt.u32.u64 %0, t; }" : "=r"(a) : "l"(p));
    return a;
}
__device__ __forceinline__ void ldm_x4(uint32_t* r, uint32_t addr) {
    asm volatile("ldmatrix.sync.aligned.m8n8.x4.shared.b16 {%0,%1,%2,%3}, [%4];"
                 : "=r"(r[0]), "=r"(r[1]), "=r"(r[2]), "=r"(r[3]) : "r"(addr));
}
__device__ __forceinline__ void mma_bf16(float* c, const uint32_t* a, const uint32_t* b) {
    asm volatile("mma.sync.aligned.m16n8k16.row.col.f32.bf16.bf16.f32 "
                 "{%0,%1,%2,%3}, {%4,%5,%6,%7}, {%8,%9}, {%0,%1,%2,%3};"
                 : "+f"(c[0]), "+f"(c[1]), "+f"(c[2]), "+f"(c[3])
                 : "r"(a[0]), "r"(a[1]), "r"(a[2]), "r"(a[3]), "r"(b[0]), "r"(b[1]));
}
__device__ __forceinline__ void cpasync16(uint32_t sa, const void* ga) {
    asm volatile("cp.async.cg.shared.global [%0], [%1], 16;" :: "r"(sa), "l"(ga));
}
#define CP_COMMIT() asm volatile("cp.async.commit_group;" ::: "memory")
#define CP_WAIT1()  asm volatile("cp.async.wait_group 1;" ::: "memory")

__device__ __forceinline__ uint32_t pk(__nv_bfloat16 a, __nv_bfloat16 b) {
    return (uint32_t)__bfloat16_as_ushort(a) | ((uint32_t)__bfloat16_as_ushort(b) << 16);
}
__device__ __forceinline__ void split4(float4 v, uint2& hi, uint2& lo) {
    __nv_bfloat16 h0 = __float2bfloat16(v.x), h1 = __float2bfloat16(v.y);
    __nv_bfloat16 h2 = __float2bfloat16(v.z), h3 = __float2bfloat16(v.w);
    __nv_bfloat16 l0 = __float2bfloat16(v.x - __bfloat162float(h0));
    __nv_bfloat16 l1 = __float2bfloat16(v.y - __bfloat162float(h1));
    __nv_bfloat16 l2 = __float2bfloat16(v.z - __bfloat162float(h2));
    __nv_bfloat16 l3 = __float2bfloat16(v.w - __bfloat162float(h3));
    hi = make_uint2(pk(h0, h1), pk(h2, h3));
    lo = make_uint2(pk(l0, l1), pk(l2, l3));
}

// SMEM tile: 128 rows x 32 bf16 = 64B/row, XOR chunk swizzle (conflict-free ldmatrix)
#define TILEB  (128 * 64)          // 8192
#define STAGEB (4 * TILEB)         // 32768 : Ah, Al, Bh, Bl
#define NSTAGE 3
#define GEMM_SMEM (NSTAGE * STAGEB)  // 98304

// physical offset of 16B chunk (row, chunk 0..3) within a tile
__device__ __forceinline__ uint32_t swz(int row, int chunk) {
    return (uint32_t)(row * 64 + (((chunk + (row >> 1)) & 3) << 4));
}

// ---------------- tensor-core GEMM (all operands pre-split bf16) ----------------
// C[M,N] = A[M,K] @ Bt[N,K]^T + bias ; 3-product: Ah*Bh + Ah*Bl + Al*Bh
// 128x128 tile, BK=32, 256 thr (8 warps 2x4), 3-stage cp.async, 1 sync/stage, 2 CTA/SM.
template <bool STATS>
__global__ void __launch_bounds__(256, 2)
gemm_mma(int N, int K,
         const __nv_bfloat16* __restrict__ Ah, const __nv_bfloat16* __restrict__ Al,
         const __nv_bfloat16* __restrict__ Bh, const __nv_bfloat16* __restrict__ Bl,
         const float* __restrict__ bias, float* __restrict__ C,
         float* __restrict__ stats) {
    extern __shared__ char smem[];

    const int tid = threadIdx.x, lane = tid & 31, wid = tid >> 5;
    const int wr = wid >> 2, wc = wid & 3;
    const int brow = blockIdx.y, bcol = blockIdx.x;

    const size_t Kb = (size_t)K * 2;
    const char* pAh = (const char*)(Ah + (size_t)brow * 128 * K);
    const char* pAl = (const char*)(Al + (size_t)brow * 128 * K);
    const char* pBh = (const char*)(Bh + (size_t)bcol * 128 * K);
    const char* pBl = (const char*)(Bl + (size_t)bcol * 128 * K);

    const uint32_t ubase = smem_u32(smem);
    // loader: 512 chunks/tile, 2 per thread
    const int lr0 = tid >> 2, lc0 = tid & 3;          // rows 0..63
    const int lr1 = (tid >> 2) + 64, lc1 = tid & 3;   // rows 64..127
    const uint32_t so0 = swz(lr0, lc0), so1 = swz(lr1, lc1);

    auto issue = [&](int k0, int s) {
        uint32_t base = ubase + s * STAGEB;
        size_t g0 = (size_t)lr0 * Kb + (size_t)k0 * 64 + lc0 * 16;
        size_t g1 = (size_t)lr1 * Kb + (size_t)k0 * 64 + lc1 * 16;
        cpasync16(base + so0,             pAh + g0);
        cpasync16(base + so1,             pAh + g1);
        cpasync16(base + TILEB + so0,     pAl + g0);
        cpasync16(base + TILEB + so1,     pAl + g1);
        cpasync16(base + 2 * TILEB + so0, pBh + g0);
        cpasync16(base + 2 * TILEB + so1, pBh + g1);
        cpasync16(base + 3 * TILEB + so0, pBl + g0);
        cpasync16(base + 3 * TILEB + so1, pBl + g1);
    };

    float acc[4][4][4];
#pragma unroll
    for (int i = 0; i < 4; i++)
#pragma unroll
        for (int j = 0; j < 4; j++)
#pragma unroll
            for (int q = 0; q < 4; q++) acc[i][j][q] = 0.f;

    // ldmatrix lane mapping (identical logical layout to prior rounds)
    const int a_row = (lane & 15);
    const int a_c   = (lane >> 4);              // k-chunk offset 0/1
    const int b_row = (lane & 7) + ((lane >> 4) << 3);
    const int b_c   = ((lane >> 3) & 1);

    auto compute = [&](int s) {
        uint32_t uAh = ubase + s * STAGEB;
        uint32_t uAl = uAh + TILEB, uBh = uAl + TILEB, uBl = uBh + TILEB;
#pragma unroll
        for (int ks = 0; ks < 2; ks++) {
            uint32_t ah[4][4], al[4][4];
#pragma unroll
            for (int mt = 0; mt < 4; mt++) {
                int row = wr * 64 + mt * 16 + a_row;
                uint32_t off = swz(row, 2 * ks + a_c);
                ldm_x4(ah[mt], uAh + off);
                ldm_x4(al[mt], uAl + off);
            }
            uint32_t bh[4][2], bl[4][2];
#pragma unroll
            for (int np = 0; np < 2; np++) {
                int row = wc * 32 + np * 16 + b_row;
                uint32_t off = swz(row, 2 * ks + b_c);
                uint32_t r[4];
                ldm_x4(r, uBh + off);
                bh[np * 2][0] = r[0]; bh[np * 2][1] = r[1];
                bh[np * 2 + 1][0] = r[2]; bh[np * 2 + 1][1] = r[3];
                ldm_x4(r, uBl + off);
                bl[np * 2][0] = r[0]; bl[np * 2][1] = r[1];
                bl[np * 2 + 1][0] = r[2]; bl[np * 2 + 1][1] = r[3];
            }
#pragma unroll
            for (int mt = 0; mt < 4; mt++)
#pragma unroll
                for (int nt = 0; nt < 4; nt++) {
                    mma_bf16(acc[mt][nt], ah[mt], bh[nt]);
                    mma_bf16(acc[mt][nt], ah[mt], bl[nt]);
                    mma_bf16(acc[mt][nt], al[mt], bh[nt]);
                }
        }
    };

    const int nk = K >> 5;   // >= 16 for all shapes here
    issue(0, 0); CP_COMMIT();
    issue(1, 1); CP_COMMIT();
    CP_WAIT1();
    __syncthreads();
    // steady state: compute stage k; issue group k+2 into stage (k+2)%3
    // (that stage was computed at iter k-1; the barrier at end of k-1 makes it safe)
    int s = 0, snext = 2;
    for (int k = 0; k < nk; k++) {
        compute(s);
        if (k + 2 < nk) issue(k + 2, snext);
        CP_COMMIT();
        CP_WAIT1();
        __syncthreads();
        s = (s == 2) ? 0 : s + 1;
        snext = (snext == 2) ? 0 : snext + 1;
    }

    // ---- epilogue: bias, store, optional fused column stats ----
    float s1[8], s2[8];
    if (STATS) {
#pragma unroll
        for (int j = 0; j < 8; j++) { s1[j] = 0.f; s2[j] = 0.f; }
    }
#pragma unroll
    for (int mt = 0; mt < 4; mt++) {
        int row0 = brow * 128 + wr * 64 + mt * 16 + (lane >> 2);
#pragma unroll
        for (int nt = 0; nt < 4; nt++) {
            int col = bcol * 128 + wc * 32 + nt * 8 + (lane & 3) * 2;
            float b0 = bias[col], b1 = bias[col + 1];
            float v00 = acc[mt][nt][0] + b0, v01 = acc[mt][nt][1] + b1;
            float v10 = acc[mt][nt][2] + b0, v11 = acc[mt][nt][3] + b1;
            *(float2*)(C + (size_t)row0 * N + col) = make_float2(v00, v01);
            *(float2*)(C + (size_t)(row0 + 8) * N + col) = make_float2(v10, v11);
            if (STATS) {
                s1[nt * 2 + 0] += v00 + v10;
                s1[nt * 2 + 1] += v01 + v11;
                s2[nt * 2 + 0] += v00 * v00 + v10 * v10;
                s2[nt * 2 + 1] += v01 * v01 + v11 * v11;
            }
        }
    }
    if (STATS) {
#pragma unroll
        for (int j = 0; j < 8; j++) {
#pragma unroll
            for (int o = 4; o <= 16; o <<= 1) {
                s1[j] += __shfl_xor_sync(0xffffffffu, s1[j], o);
                s2[j] += __shfl_xor_sync(0xffffffffu, s2[j], o);
            }
        }
        if (lane < 4) {
#pragma unroll
            for (int nt = 0; nt < 4; nt++) {
#pragma unroll
                for (int p = 0; p < 2; p++) {
                    int col = bcol * 128 + wc * 32 + nt * 8 + lane * 2 + p;
                    atomicAdd(&stats[col], s1[nt * 2 + p]);
                    atomicAdd(&stats[1024 + col], s2[nt * 2 + p]);
                }
            }
        }
    }
}

// ---------------- per-graph aggregation (BN+ReLU fused on input) ----------------
// zsrc = raw embeddings (BN=false) or zpre (BN=true, bnp = scale/shift).
template <bool BN>
__global__ void __launch_bounds__(512, 2)
graph_aggregate(const float* __restrict__ zsrc, const float* __restrict__ bnp,
                const float* __restrict__ eeact,
                const int* __restrict__ eidx, const int* __restrict__ combo,
                __nv_bfloat16* __restrict__ aggh, __nv_bfloat16* __restrict__ aggl) {
    extern __shared__ float sagg[];   // NPG * HH floats = 64KB
    __shared__ int s_src[EPG], s_dst[EPG], s_u[EPG];

    const int b = blockIdx.x;
    const int tid = threadIdx.x;      // column

    float sc = 1.f, sh = 0.f;
    if (BN) { sc = bnp[tid]; sh = bnp[1024 + tid]; }

    if (tid < EPG) {
        s_src[tid] = eidx[b * EPG + tid] - b * NPG;
        s_dst[tid] = eidx[EE + b * EPG + tid] - b * NPG;
        s_u[tid]   = combo[b * EPG + tid];
    }
    const float* zb = zsrc + (size_t)b * NPG * HH;
#pragma unroll
    for (int n = 0; n < NPG; n++) {
        float v = zb[n * HH + tid];
        if (BN) v = fmaxf(0.f, v * sc + sh);
        sagg[n * HH + tid] = v;
    }
    __syncthreads();

    float zv = __ldg(&zb[s_src[0] * HH + tid]);
    float ev = __ldg(&eeact[(size_t)s_u[0] * HH + tid]);
#pragma unroll 4
    for (int e = 0; e < EPG; e++) {
        float zcur = zv;
        if (BN) zcur = fmaxf(0.f, zcur * sc + sh);
        float cur = zcur + ev;
        int d = s_dst[e];
        if (e + 1 < EPG) {
            zv = __ldg(&zb[s_src[e + 1] * HH + tid]);
            ev = __ldg(&eeact[(size_t)s_u[e + 1] * HH + tid]);
        }
        sagg[d * HH + tid] += cur;
    }
    __syncthreads();

    __nv_bfloat16* oh = aggh + (size_t)b * NPG * HH + tid;
    __nv_bfloat16* ol = aggl + (size_t)b * NPG * HH + tid;
#pragma unroll
    for (int n = 0; n < NPG; n++) {
        float v = sagg[n * HH + tid];
        __nv_bfloat16 h = __float2bfloat16(v);
        __nv_bfloat16 l = __float2bfloat16(v - __bfloat162float(h));
        oh[n * HH] = h;
        ol[n * HH] = l;
    }
}

// ---------------- weight transpose + split ----------------
__global__ void transpose_split(const float* __restrict__ S,
                                __nv_bfloat16* __restrict__ Dh,
                                __nv_bfloat16* __restrict__ Dl, int K, int N) {
    __shared__ float t[32][33];
    int k0 = blockIdx.y * 32, n0 = blockIdx.x * 32;
    int x = threadIdx.x, y = threadIdx.y;
#pragma unroll
    for (int i = 0; i < 32; i += 8) t[y + i][x] = S[(size_t)(k0 + y + i) * N + n0 + x];
    __syncthreads();
#pragma unroll
    for (int i = 0; i < 32; i += 8) {
        float v = t[x][y + i];
        __nv_bfloat16 h = __float2bfloat16(v);
        __nv_bfloat16 l = __float2bfloat16(v - __bfloat162float(h));
        Dh[(size_t)(n0 + y + i) * K + k0 + x] = h;
        Dl[(size_t)(n0 + y + i) * K + k0 + x] = l;
    }
}

// ---------------- split / bn passes ----------------
__global__ void split_f32(const float* __restrict__ X,
                          __nv_bfloat16* __restrict__ Xh, __nv_bfloat16* __restrict__ Xl,
                          size_t total4) {
    size_t i = (size_t)blockIdx.x * blockDim.x + threadIdx.x;
    if (i >= total4) return;
    uint2 hi, lo;
    split4(((const float4*)X)[i], hi, lo);
    ((uint2*)Xh)[i] = hi;
    ((uint2*)Xl)[i] = lo;
}

__global__ void bn_relu_split(const float* __restrict__ X,
                              __nv_bfloat16* __restrict__ Xh, __nv_bfloat16* __restrict__ Xl,
                              size_t total4, int cols, const float* __restrict__ bnp) {
    size_t i = (size_t)blockIdx.x * blockDim.x + threadIdx.x;
    if (i >= total4) return;
    int c = (int)((i * 4) % cols);
    float4 x = ((const float4*)X)[i];
    float4 y;
    y.x = fmaxf(0.f, x.x * bnp[c + 0] + bnp[1024 + c + 0]);
    y.y = fmaxf(0.f, x.y * bnp[c + 1] + bnp[1024 + c + 1]);
    y.z = fmaxf(0.f, x.z * bnp[c + 2] + bnp[1024 + c + 2]);
    y.w = fmaxf(0.f, x.w * bnp[c + 3] + bnp[1024 + c + 3]);
    uint2 hi, lo;
    split4(y, hi, lo);
    ((uint2*)Xh)[i] = hi;
    ((uint2*)Xl)[i] = lo;
}

// ---------------- embeddings / batched bond path ----------------
__global__ void embed_nodes(const int* __restrict__ x, const float* __restrict__ tab,
                            float* __restrict__ z) {
    int n = blockIdx.x;
    __shared__ int idx[9];
    if (threadIdx.x < 9) idx[threadIdx.x] = x[n * 9 + threadIdx.x] + c_node_off[threadIdx.x];
    __syncthreads();
    for (int c = threadIdx.x; c < HH; c += blockDim.x) {
        float acc = 0.f;
#pragma unroll
        for (int f = 0; f < 9; f++) acc += tab[(size_t)idx[f] * HH + c];
        z[(size_t)n * HH + c] = acc;
    }
}

__global__ void combo_hist(const int* __restrict__ ea, int* __restrict__ combo,
                           int* __restrict__ cnt) {
    int e = blockIdx.x * 256 + threadIdx.x;
    if (e >= EE) return;
    int c = ea[e * 3] * 12 + ea[e * 3 + 1] * 2 + ea[e * 3 + 2];
    combo[e] = c;
    atomicAdd(&cnt[c], 1);
}

__global__ void embed_edges_u(const float* __restrict__ tab, float* __restrict__ embu) {
    int u = blockIdx.x;
    int a0 = u / 12, a1 = (u % 12) / 2, a2 = u & 1;
    int c = threadIdx.x;
    embu[u * HEH + c] = tab[(size_t)a0 * HEH + c]
                      + tab[(size_t)(119 + a1) * HEH + c]
                      + tab[(size_t)(128 + a2) * HEH + c];
}

__global__ void bond_small(const float* __restrict__ embu, const float* __restrict__ bondW,
                           const float* __restrict__ bondB, float* __restrict__ eeu) {
    __shared__ float se[HEH];
    int u = blockIdx.x, l = blockIdx.y;
    const float* bW = bondW + (size_t)l * HEH * HH;
    if (threadIdx.x < HEH) se[threadIdx.x] = embu[u * HEH + threadIdx.x];
    __syncthreads();
    int c = threadIdx.x;
    float acc = bondB[l * HH + c];
#pragma unroll 4
    for (int k = 0; k < HEH; k++) acc += se[k] * bW[(size_t)k * HH + c];
    eeu[((size_t)l * NCOMBO + u) * HH + c] = acc;
}

__global__ void wstats(const float* __restrict__ eeu, const int* __restrict__ cnt,
                       float* __restrict__ estats) {
    int l = blockIdx.y;
    int c = blockIdx.x * 256 + threadIdx.x;
    const float* base = eeu + (size_t)l * NCOMBO * HH;
    float m = 0.f, q = 0.f;
    for (int u = 0; u < NCOMBO; u++) {
        float w = (float)cnt[u];
        float v = base[u * HH + c];
        m += w * v;
        q += w * v * v;
    }
    estats[l * 2048 + c] = m;
    estats[l * 2048 + 1024 + c] = q;
}

__global__ void bn_prep_e(float* __restrict__ estats, const float* __restrict__ g,
                          const float* __restrict__ b) {
    int l = blockIdx.y;
    int c = blockIdx.x * 256 + threadIdx.x;
    float* st = estats + l * 2048;
    float m = st[c] * (1.f / EE);
    float var = st[1024 + c] * (1.f / EE) - m * m;
    float sc = g[l * HH + c] * rsqrtf(var + EPSV);
    st[c] = sc;
    st[1024 + c] = b[l * HH + c] - m * sc;
}

__global__ void eeact_apply(const float* __restrict__ eeu, const float* __restrict__ estats,
                            float* __restrict__ eeact) {
    int u = blockIdx.x, l = blockIdx.y;
    int c = threadIdx.x;
    const float* st = estats + l * 2048;
    size_t i = ((size_t)l * NCOMBO + u) * HH + c;
    eeact[i] = fmaxf(0.f, eeu[i] * st[c] + st[1024 + c]);
}

// node BN prep: stats -> bnp (separate), then zero stats for next reuse
__global__ void bn_prep2(float* __restrict__ stats, float* __restrict__ bnp, int cols,
                         float inv_rows, const float* __restrict__ g,
                         const float* __restrict__ b) {
    int c = blockIdx.x * blockDim.x + threadIdx.x;
    if (c >= cols) return;
    float m = stats[c] * inv_rows;
    float var = stats[1024 + c] * inv_rows - m * m;
    float sc = g[c] * rsqrtf(var + EPSV);
    bnp[c] = sc;
    bnp[1024 + c] = b[c] - m * sc;
    stats[c] = 0.f;
    stats[1024 + c] = 0.f;
}

// ---------------- pooling ----------------
__global__ void att_vec(const float* __restrict__ gapW, const float* __restrict__ gapB,
                        const float* __restrict__ attW, const float* __restrict__ attB,
                        float* __restrict__ v) {
    int w = blockIdx.x * (blockDim.x / 32) + (threadIdx.x / 32);
    int lane = threadIdx.x & 31;
    if (w > OUTD) return;
    const float* row = (w < OUTD) ? (gapW + (size_t)w * HH) : gapB;
    float acc = 0.f;
    for (int h = lane; h < HH; h += 32) acc += row[h] * attW[h];
#pragma unroll
    for (int o = 16; o; o >>= 1) acc += __shfl_xor_sync(0xffffffffu, acc, o);
    if (lane == 0) v[w] = acc + ((w == OUTD) ? attB[0] : 0.f);
}

__global__ void pool(const float* __restrict__ zout, const float* __restrict__ v,
                     float* __restrict__ hg) {
    __shared__ float satt[NPG];
    __shared__ float salpha[NPG];
    int b = blockIdx.x;
    int warp = threadIdx.x / 32, lane = threadIdx.x & 31;
    const float cst = v[OUTD];
    for (int n = warp; n < NPG; n += 8) {
        const float* row = zout + ((size_t)b * NPG + n) * OUTD;
        float acc = 0.f;
        for (int k = lane; k < OUTD; k += 32) acc += row[k] * v[k];
#pragma unroll
        for (int o = 16; o; o >>= 1) acc += __shfl_xor_sync(0xffffffffu, acc, o);
        if (lane == 0) satt[n] = acc + cst;
    }
    __syncthreads();
    if (threadIdx.x < 32) {
        float a = satt[threadIdx.x];
        float mx = a;
#pragma unroll
        for (int o = 16; o; o >>= 1) mx = fmaxf(mx, __shfl_xor_sync(0xffffffffu, mx, o));
        float ex = expf(a - mx);
        float s = ex;
#pragma unroll
        for (int o = 16; o; o >>= 1) s += __shfl_xor_sync(0xffffffffu, s, o);
        salpha[threadIdx.x] = ex / s;
    }
    __syncthreads();
    for (int j = threadIdx.x; j < OUTD; j += 256) {
        float acc = 0.f;
#pragma unroll
        for (int n = 0; n < NPG; n++)
            acc += salpha[n] * zout[((size_t)b * NPG + n) * OUTD + j];
        hg[(size_t)b * OUTD + j] = acc;
    }
}

// ---------------- host orchestration ----------------
extern "C" void kernel_launch(void* const* d_in, const int* in_sizes, int n_in,
                              void* d_out, int out_size) {
    const int*   x        = (const int*)  d_in[0];
    const int*   edgeattr = (const int*)  d_in[1];
    const int*   eidx     = (const int*)  d_in[2];
    const float* node_tab = (const float*)d_in[4];
    const float* edge_tab = (const float*)d_in[5];
    const float* bondW    = (const float*)d_in[6];
    const float* bondB    = (const float*)d_in[7];
    const float* bondG    = (const float*)d_in[8];
    const float* bondBeta = (const float*)d_in[9];
    const float* atomW1   = (const float*)d_in[10];
    const float* atomB1   = (const float*)d_in[11];
    const float* atomG    = (const float*)d_in[12];
    const float* atomBeta = (const float*)d_in[13];
    const float* atomW2   = (const float*)d_in[14];
    const float* atomB2   = (const float*)d_in[15];
    const float* normG    = (const float*)d_in[16];
    const float* normB    = (const float*)d_in[17];
    const float* outW     = (const float*)d_in[18];
    const float* outB     = (const float*)d_in[19];
    const float* gapW     = (const float*)d_in[20];
    const float* gapB     = (const float*)d_in[21];
    const float* attW     = (const float*)d_in[22];
    const float* attB     = (const float*)d_in[23];
    const float* projW    = (const float*)d_in[24];
    const float* projB    = (const float*)d_in[25];
    float* out = (float*)d_out;

    float *p_z, *p_h, *p_zpre, *p_zout, *p_v, *p_hg, *p_stats, *p_estats;
    float *p_embu, *p_eeu, *p_eeact;
    int *p_combo, *p_cnt;
    __nv_bfloat16 *p_aggh, *p_aggl, *p_hh, *p_hl, *p_zh, *p_zl, *p_hgh, *p_hgl;
    __nv_bfloat16 *p_aW1h, *p_aW1l, *p_aW2h, *p_aW2l, *p_oWh, *p_oWl, *p_pWh, *p_pWl;
    cudaGetSymbolAddress((void**)&p_z, g_z);
    cudaGetSymbolAddress((void**)&p_h, g_h);
    cudaGetSymbolAddress((void**)&p_zpre, g_zpre);
    cudaGetSymbolAddress((void**)&p_zout, g_zout);
    cudaGetSymbolAddress((void**)&p_v, g_v);
    cudaGetSymbolAddress((void**)&p_hg, g_hg);
    cudaGetSymbolAddress((void**)&p_stats, g_stats);
    cudaGetSymbolAddress((void**)&p_estats, g_estats);
    cudaGetSymbolAddress((void**)&p_combo, g_combo);
    cudaGetSymbolAddress((void**)&p_cnt, g_cnt);
    cudaGetSymbolAddress((void**)&p_embu, g_embu);
    cudaGetSymbolAddress((void**)&p_eeu, g_eeu);
    cudaGetSymbolAddress((void**)&p_eeact, g_eeact);
    cudaGetSymbolAddress((void**)&p_aggh, g_aggh);
    cudaGetSymbolAddress((void**)&p_aggl, g_aggl);
    cudaGetSymbolAddress((void**)&p_hh, g_hh);
    cudaGetSymbolAddress((void**)&p_hl, g_hl);
    cudaGetSymbolAddress((void**)&p_zh, g_zh);
    cudaGetSymbolAddress((void**)&p_zl, g_zl);
    cudaGetSymbolAddress((void**)&p_hgh, g_hgh);
    cudaGetSymbolAddress((void**)&p_hgl, g_hgl);
    cudaGetSymbolAddress((void**)&p_aW1h, g_aW1h);
    cudaGetSymbolAddress((void**)&p_aW1l, g_aW1l);
    cudaGetSymbolAddress((void**)&p_aW2h, g_aW2h);
    cudaGetSymbolAddress((void**)&p_aW2l, g_aW2l);
    cudaGetSymbolAddress((void**)&p_oWh, g_oWh);
    cudaGetSymbolAddress((void**)&p_oWl, g_oWl);
    cudaGetSymbolAddress((void**)&p_pWh, g_pWh);
    cudaGetSymbolAddress((void**)&p_pWl, g_pWl);

    float* stats1 = p_stats;
    float* stats2 = p_stats + 2048;
    float* bnp1   = p_stats + 4096;
    float* bnp2   = p_stats + 6144;

    cudaFuncSetAttribute(gemm_mma<true >, cudaFuncAttributeMaxDynamicSharedMemorySize, GEMM_SMEM);
    cudaFuncSetAttribute(gemm_mma<false>, cudaFuncAttributeMaxDynamicSharedMemorySize, GEMM_SMEM);
    cudaFuncSetAttribute(graph_aggregate<false>, cudaFuncAttributeMaxDynamicSharedMemorySize,
                         NPG * HH * (int)sizeof(float));
    cudaFuncSetAttribute(graph_aggregate<true>, cudaFuncAttributeMaxDynamicSharedMemorySize,
                         NPG * HH * (int)sizeof(float));

    // weight transposes + bf16 split
    for (int l = 0; l < LL; l++) {
        transpose_split<<<dim3(H2 / 32, HH / 32), dim3(32, 8)>>>(
            atomW1 + (size_t)l * HH * H2, p_aW1h + (size_t)l * H2 * HH,
            p_aW1l + (size_t)l * H2 * HH, HH, H2);
        transpose_split<<<dim3(HH / 32, H2 / 32), dim3(32, 8)>>>(
            atomW2 + (size_t)l * H2 * HH, p_aW2h + (size_t)l * HH * H2,
            p_aW2l + (size_t)l * HH * H2, H2, HH);
    }
    transpose_split<<<dim3(OUTD / 32, HH / 32), dim3(32, 8)>>>(outW, p_oWh, p_oWl, HH, OUTD);
    transpose_split<<<dim3(OUTD / 32, OUTD / 32), dim3(32, 8)>>>(projW, p_pWh, p_pWl, OUTD, OUTD);

    // embeddings + edge combo machinery
    embed_nodes<<<NN, 256>>>(x, node_tab, p_z);
    cudaMemsetAsync(p_cnt, 0, NCOMBO * sizeof(int));
    cudaMemsetAsync(p_stats, 0, 4096 * sizeof(float));   // zero stats1+stats2 once
    combo_hist<<<(EE + 255) / 256, 256>>>(edgeattr, p_combo, p_cnt);
    embed_edges_u<<<NCOMBO, HEH>>>(edge_tab, p_embu);

    // precompute ALL layers' bond tables
    bond_small<<<dim3(NCOMBO, LL), HH>>>(p_embu, bondW, bondB, p_eeu);
    wstats<<<dim3(2, LL), 256>>>(p_eeu, p_cnt, p_estats);
    bn_prep_e<<<dim3(2, LL), 256>>>(p_estats, bondG, bondBeta);
    eeact_apply<<<dim3(NCOMBO, LL), HH>>>(p_eeu, p_estats, p_eeact);

    for (int l = 0; l < LL; l++) {
        const __nv_bfloat16* aW1h = p_aW1h + (size_t)l * H2 * HH;
        const __nv_bfloat16* aW1l = p_aW1l + (size_t)l * H2 * HH;
        const float* aB1  = atomB1   + (size_t)l * H2;
        const float* aG   = atomG    + (size_t)l * H2;
        const float* aBe  = atomBeta + (size_t)l * H2;
        const __nv_bfloat16* aW2h = p_aW2h + (size_t)l * HH * H2;
        const __nv_bfloat16* aW2l = p_aW2l + (size_t)l * HH * H2;
        const float* aB2  = atomB2   + (size_t)l * HH;
        const float* nG   = normG    + (size_t)l * HH;
        const float* nB   = normB    + (size_t)l * HH;
        const float* eea  = p_eeact + (size_t)l * NCOMBO * HH;

        // aggregation (BN+ReLU of zpre fused for l>0), writes split bf16 agg
        if (l == 0)
            graph_aggregate<false><<<BB, 512, NPG * HH * sizeof(float)>>>(
                p_z, nullptr, eea, eidx, p_combo, p_aggh, p_aggl);
        else
            graph_aggregate<true><<<BB, 512, NPG * HH * sizeof(float)>>>(
                p_zpre, bnp2, eea, eidx, p_combo, p_aggh, p_aggl);

        // h_pre = agg @ aW1 + aB1, stats fused
        gemm_mma<true><<<dim3(H2 / 128, NN / 128), 256, GEMM_SMEM>>>(
            H2, HH, p_aggh, p_aggl, aW1h, aW1l, aB1, p_h, stats1);
        bn_prep2<<<4, 256>>>(stats1, bnp1, H2, 1.f / NN, aG, aBe);

        // h_act = relu(bn(h_pre)) split to bf16 hi/lo
        bn_relu_split<<<(unsigned)(((size_t)NN * H2 / 4 + 255) / 256), 256>>>(
            p_h, p_hh, p_hl, (size_t)NN * H2 / 4, H2, bnp1);

        // z_pre = h_act @ aW2 + aB2, stats fused
        gemm_mma<true><<<dim3(HH / 128, NN / 128), 256, GEMM_SMEM>>>(
            HH, H2, p_hh, p_hl, aW2h, aW2l, aB2, p_zpre, stats2);
        bn_prep2<<<2, 256>>>(stats2, bnp2, HH, 1.f / NN, nG, nB);
    }

    // final activation: z = relu(bn(zpre)) split directly to bf16
    bn_relu_split<<<(unsigned)(((size_t)NN * HH / 4 + 255) / 256), 256>>>(
        p_zpre, p_zh, p_zl, (size_t)NN * HH / 4, HH, bnp2);

    // zout = z @ outW + outB
    gemm_mma<false><<<dim3(OUTD / 128, NN / 128), 256, GEMM_SMEM>>>(
        OUTD, HH, p_zh, p_zl, p_oWh, p_oWl, outB, p_zout, nullptr);

    att_vec<<<129, 256>>>(gapW, gapB, attW, attB, p_v);
    pool<<<BB, 256>>>(p_zout, p_v, p_hg);

    // out = hg @ projW + projB
    split_f32<<<(unsigned)(((size_t)BB * OUTD / 4 + 255) / 256), 256>>>(
        p_hg, p_hgh, p_hgl, (size_t)BB * OUTD / 4);
    gemm_mma<false><<<dim3(OUTD / 128, BB / 128), 256, GEMM_SMEM>>>(
        OUTD, OUTD, p_hgh, p_hgl, p_pWh, p_pWl, projB, out, nullptr);
}

// round 8
// speedup vs baseline: 3.9211x; 1.0618x over previous
#include <cuda_runtime.h>
#include <cuda_bf16.h>
#include <cstdint>

// ---------------- problem constants ----------------
#define NN      32768
#define EE      131072
#define HH      512
#define HEH     128
#define H2      1024
#define OUTD    1024
#define BB      1024
#define NPG     32
#define EPG     128
#define LL      6
#define EPSV    1e-5f
#define NCOMBO  264

__device__ __constant__ int c_node_off[9] = {0,119,128,139,151,160,165,173,175};

// ---------------- scratch (device globals; no allocs allowed) ----------------
__device__ float g_z    [(size_t)NN * HH];     // initial embeddings
__device__ float g_h    [(size_t)NN * H2];
__device__ float g_zpre [(size_t)NN * HH];
__device__ float g_v    [OUTD + 1];
__device__ float g_w    [HH + 1];
__device__ float g_hgpre[(size_t)BB * OUTD];
__device__ float g_stats[8192];     // stats1, stats2, bnp1, bnp2
__device__ float g_estats[LL * 2048];
__device__ int   g_combo[EE];
__device__ int   g_cnt  [NCOMBO];
__device__ float g_embu [NCOMBO * HEH];
__device__ float g_eeu  [(size_t)LL * NCOMBO * HH];
__device__ float g_eeact[(size_t)LL * NCOMBO * HH];
// pre-split bf16 activations (hi/lo)
__device__ __nv_bfloat16 g_aggh[(size_t)NN * HH];
__device__ __nv_bfloat16 g_aggl[(size_t)NN * HH];
__device__ __nv_bfloat16 g_hh  [(size_t)NN * H2];
__device__ __nv_bfloat16 g_hl  [(size_t)NN * H2];
__device__ __nv_bfloat16 g_zgh [(size_t)BB * HH];
__device__ __nv_bfloat16 g_zgl [(size_t)BB * HH];
__device__ __nv_bfloat16 g_hgh [(size_t)BB * OUTD];
__device__ __nv_bfloat16 g_hgl [(size_t)BB * OUTD];
// pre-split transposed weights [N, K] bf16 hi/lo
__device__ __nv_bfloat16 g_aW1h[(size_t)LL * H2 * HH];
__device__ __nv_bfloat16 g_aW1l[(size_t)LL * H2 * HH];
__device__ __nv_bfloat16 g_aW2h[(size_t)LL * HH * H2];
__device__ __nv_bfloat16 g_aW2l[(size_t)LL * HH * H2];
__device__ __nv_bfloat16 g_oWh [(size_t)OUTD * HH];
__device__ __nv_bfloat16 g_oWl [(size_t)OUTD * HH];
__device__ __nv_bfloat16 g_pWh [(size_t)OUTD * OUTD];
__device__ __nv_bfloat16 g_pWl [(size_t)OUTD * OUTD];

// ---------------- asm helpers ----------------
__device__ __forceinline__ uint32_t smem_u32(const void* p) {
    uint32_t a;
    asm("{ .reg .u64 t; cvta.to.shared.u64 t, %1; cvt.u32.u64 %0, t; }" : "=r"(a) : "l"(p));
    return a;
}
__device__ __forceinline__ void ldm_x4(uint32_t* r, uint32_t addr) {
    asm volatile("ldmatrix.sync.aligned.m8n8.x4.shared.b16 {%0,%1,%2,%3}, [%4];"
                 : "=r"(r[0]), "=r"(r[1]), "=r"(r[2]), "=r"(r[3]) : "r"(addr));
}
__device__ __forceinline__ void mma_bf16(float* c, const uint32_t* a, const uint32_t* b) {
    asm volatile("mma.sync.aligned.m16n8k16.row.col.f32.bf16.bf16.f32 "
                 "{%0,%1,%2,%3}, {%4,%5,%6,%7}, {%8,%9}, {%0,%1,%2,%3};"
                 : "+f"(c[0]), "+f"(c[1]), "+f"(c[2]), "+f"(c[3])
                 : "r"(a[0]), "r"(a[1]), "r"(a[2]), "r"(a[3]), "r"(b[0]), "r"(b[1]));
}
__device__ __forceinline__ void cpasync16(uint32_t sa, const void* ga) {
    asm volatile("cp.async.cg.shared.global [%0], [%1], 16;" :: "r"(sa), "l"(ga));
}
#define CP_COMMIT() asm volatile("cp.async.commit_group;" ::: "memory")
#define CP_WAIT1()  asm volatile("cp.async.wait_group 1;" ::: "memory")

__device__ __forceinline__ uint32_t pk(__nv_bfloat16 a, __nv_bfloat16 b) {
    return (uint32_t)__bfloat16_as_ushort(a) | ((uint32_t)__bfloat16_as_ushort(b) << 16);
}
__device__ __forceinline__ void split4(float4 v, uint2& hi, uint2& lo) {
    __nv_bfloat16 h0 = __float2bfloat16(v.x), h1 = __float2bfloat16(v.y);
    __nv_bfloat16 h2 = __float2bfloat16(v.z), h3 = __float2bfloat16(v.w);
    __nv_bfloat16 l0 = __float2bfloat16(v.x - __bfloat162float(h0));
    __nv_bfloat16 l1 = __float2bfloat16(v.y - __bfloat162float(h1));
    __nv_bfloat16 l2 = __float2bfloat16(v.z - __bfloat162float(h2));
    __nv_bfloat16 l3 = __float2bfloat16(v.w - __bfloat162float(h3));
    hi = make_uint2(pk(h0, h1), pk(h2, h3));
    lo = make_uint2(pk(l0, l1), pk(l2, l3));
}

// SMEM tile: 128 rows x 32 bf16 = 64B/row, XOR chunk swizzle
#define TILEB  (128 * 64)
#define STAGEB (4 * TILEB)
#define NSTAGE 3
#define GEMM_SMEM (NSTAGE * STAGEB)

__device__ __forceinline__ uint32_t swz(int row, int chunk) {
    return (uint32_t)(row * 64 + (((chunk + (row >> 1)) & 3) << 4));
}

// ---------------- tensor-core GEMM (all operands pre-split bf16) ----------------
template <bool STATS>
__global__ void __launch_bounds__(256, 2)
gemm_mma(int N, int K,
         const __nv_bfloat16* __restrict__ Ah, const __nv_bfloat16* __restrict__ Al,
         const __nv_bfloat16* __restrict__ Bh, const __nv_bfloat16* __restrict__ Bl,
         const float* __restrict__ bias, float* __restrict__ C,
         float* __restrict__ stats) {
    extern __shared__ char smem[];

    const int tid = threadIdx.x, lane = tid & 31, wid = tid >> 5;
    const int wr = wid >> 2, wc = wid & 3;
    const int brow = blockIdx.y, bcol = blockIdx.x;

    const size_t Kb = (size_t)K * 2;
    const char* pAh = (const char*)(Ah + (size_t)brow * 128 * K);
    const char* pAl = (const char*)(Al + (size_t)brow * 128 * K);
    const char* pBh = (const char*)(Bh + (size_t)bcol * 128 * K);
    const char* pBl = (const char*)(Bl + (size_t)bcol * 128 * K);

    const uint32_t ubase = smem_u32(smem);
    const int lr0 = tid >> 2, lc0 = tid & 3;
    const int lr1 = (tid >> 2) + 64, lc1 = tid & 3;
    const uint32_t so0 = swz(lr0, lc0), so1 = swz(lr1, lc1);

    auto issue = [&](int k0, int s) {
        uint32_t base = ubase + s * STAGEB;
        size_t g0 = (size_t)lr0 * Kb + (size_t)k0 * 64 + lc0 * 16;
        size_t g1 = (size_t)lr1 * Kb + (size_t)k0 * 64 + lc1 * 16;
        cpasync16(base + so0,             pAh + g0);
        cpasync16(base + so1,             pAh + g1);
        cpasync16(base + TILEB + so0,     pAl + g0);
        cpasync16(base + TILEB + so1,     pAl + g1);
        cpasync16(base + 2 * TILEB + so0, pBh + g0);
        cpasync16(base + 2 * TILEB + so1, pBh + g1);
        cpasync16(base + 3 * TILEB + so0, pBl + g0);
        cpasync16(base + 3 * TILEB + so1, pBl + g1);
    };

    float acc[4][4][4];
#pragma unroll
    for (int i = 0; i < 4; i++)
#pragma unroll
        for (int j = 0; j < 4; j++)
#pragma unroll
            for (int q = 0; q < 4; q++) acc[i][j][q] = 0.f;

    const int a_row = (lane & 15);
    const int a_c   = (lane >> 4);
    const int b_row = (lane & 7) + ((lane >> 4) << 3);
    const int b_c   = ((lane >> 3) & 1);

    auto compute = [&](int s) {
        uint32_t uAh = ubase + s * STAGEB;
        uint32_t uAl = uAh + TILEB, uBh = uAl + TILEB, uBl = uBh + TILEB;
#pragma unroll
        for (int ks = 0; ks < 2; ks++) {
            uint32_t ah[4][4], al[4][4];
#pragma unroll
            for (int mt = 0; mt < 4; mt++) {
                int row = wr * 64 + mt * 16 + a_row;
                uint32_t off = swz(row, 2 * ks + a_c);
                ldm_x4(ah[mt], uAh + off);
                ldm_x4(al[mt], uAl + off);
            }
            uint32_t bh[4][2], bl[4][2];
#pragma unroll
            for (int np = 0; np < 2; np++) {
                int row = wc * 32 + np * 16 + b_row;
                uint32_t off = swz(row, 2 * ks + b_c);
                uint32_t r[4];
                ldm_x4(r, uBh + off);
                bh[np * 2][0] = r[0]; bh[np * 2][1] = r[1];
                bh[np * 2 + 1][0] = r[2]; bh[np * 2 + 1][1] = r[3];
                ldm_x4(r, uBl + off);
                bl[np * 2][0] = r[0]; bl[np * 2][1] = r[1];
                bl[np * 2 + 1][0] = r[2]; bl[np * 2 + 1][1] = r[3];
            }
#pragma unroll
            for (int mt = 0; mt < 4; mt++)
#pragma unroll
                for (int nt = 0; nt < 4; nt++) {
                    mma_bf16(acc[mt][nt], ah[mt], bh[nt]);
                    mma_bf16(acc[mt][nt], ah[mt], bl[nt]);
                    mma_bf16(acc[mt][nt], al[mt], bh[nt]);
                }
        }
    };

    const int nk = K >> 5;
    issue(0, 0); CP_COMMIT();
    issue(1, 1); CP_COMMIT();
    CP_WAIT1();
    __syncthreads();
    int s = 0, snext = 2;
    for (int k = 0; k < nk; k++) {
        compute(s);
        if (k + 2 < nk) issue(k + 2, snext);
        CP_COMMIT();
        CP_WAIT1();
        __syncthreads();
        s = (s == 2) ? 0 : s + 1;
        snext = (snext == 2) ? 0 : snext + 1;
    }

    float s1[8], s2[8];
    if (STATS) {
#pragma unroll
        for (int j = 0; j < 8; j++) { s1[j] = 0.f; s2[j] = 0.f; }
    }
#pragma unroll
    for (int mt = 0; mt < 4; mt++) {
        int row0 = brow * 128 + wr * 64 + mt * 16 + (lane >> 2);
#pragma unroll
        for (int nt = 0; nt < 4; nt++) {
            int col = bcol * 128 + wc * 32 + nt * 8 + (lane & 3) * 2;
            float b0 = bias[col], b1 = bias[col + 1];
            float v00 = acc[mt][nt][0] + b0, v01 = acc[mt][nt][1] + b1;
            float v10 = acc[mt][nt][2] + b0, v11 = acc[mt][nt][3] + b1;
            *(float2*)(C + (size_t)row0 * N + col) = make_float2(v00, v01);
            *(float2*)(C + (size_t)(row0 + 8) * N + col) = make_float2(v10, v11);
            if (STATS) {
                s1[nt * 2 + 0] += v00 + v10;
                s1[nt * 2 + 1] += v01 + v11;
                s2[nt * 2 + 0] += v00 * v00 + v10 * v10;
                s2[nt * 2 + 1] += v01 * v01 + v11 * v11;
            }
        }
    }
    if (STATS) {
#pragma unroll
        for (int j = 0; j < 8; j++) {
#pragma unroll
            for (int o = 4; o <= 16; o <<= 1) {
                s1[j] += __shfl_xor_sync(0xffffffffu, s1[j], o);
                s2[j] += __shfl_xor_sync(0xffffffffu, s2[j], o);
            }
        }
        if (lane < 4) {
#pragma unroll
            for (int nt = 0; nt < 4; nt++) {
#pragma unroll
                for (int p = 0; p < 2; p++) {
                    int col = bcol * 128 + wc * 32 + nt * 8 + lane * 2 + p;
                    atomicAdd(&stats[col], s1[nt * 2 + p]);
                    atomicAdd(&stats[1024 + col], s2[nt * 2 + p]);
                }
            }
        }
    }
}

// ---------------- per-graph aggregation (BN+ReLU fused on input) ----------------
template <bool BN>
__global__ void __launch_bounds__(512, 2)
graph_aggregate(const float* __restrict__ zsrc, const float* __restrict__ bnp,
                const float* __restrict__ eeact,
                const int* __restrict__ eidx, const int* __restrict__ combo,
                __nv_bfloat16* __restrict__ aggh, __nv_bfloat16* __restrict__ aggl) {
    extern __shared__ float sagg[];
    __shared__ int s_src[EPG], s_dst[EPG], s_u[EPG];

    const int b = blockIdx.x;
    const int tid = threadIdx.x;

    float sc = 1.f, sh = 0.f;
    if (BN) { sc = bnp[tid]; sh = bnp[1024 + tid]; }

    if (tid < EPG) {
        s_src[tid] = eidx[b * EPG + tid] - b * NPG;
        s_dst[tid] = eidx[EE + b * EPG + tid] - b * NPG;
        s_u[tid]   = combo[b * EPG + tid];
    }
    const float* zb = zsrc + (size_t)b * NPG * HH;
#pragma unroll
    for (int n = 0; n < NPG; n++) {
        float v = zb[n * HH + tid];
        if (BN) v = fmaxf(0.f, v * sc + sh);
        sagg[n * HH + tid] = v;
    }
    __syncthreads();

    float zv = __ldg(&zb[s_src[0] * HH + tid]);
    float ev = __ldg(&eeact[(size_t)s_u[0] * HH + tid]);
#pragma unroll 4
    for (int e = 0; e < EPG; e++) {
        float zcur = zv;
        if (BN) zcur = fmaxf(0.f, zcur * sc + sh);
        float cur = zcur + ev;
        int d = s_dst[e];
        if (e + 1 < EPG) {
            zv = __ldg(&zb[s_src[e + 1] * HH + tid]);
            ev = __ldg(&eeact[(size_t)s_u[e + 1] * HH + tid]);
        }
        sagg[d * HH + tid] += cur;
    }
    __syncthreads();

    __nv_bfloat16* oh = aggh + (size_t)b * NPG * HH + tid;
    __nv_bfloat16* ol = aggl + (size_t)b * NPG * HH + tid;
#pragma unroll
    for (int n = 0; n < NPG; n++) {
        float v = sagg[n * HH + tid];
        __nv_bfloat16 h = __float2bfloat16(v);
        __nv_bfloat16 l = __float2bfloat16(v - __bfloat162float(h));
        oh[n * HH] = h;
        ol[n * HH] = l;
    }
}

// ---------------- weight transpose + split ----------------
__global__ void transpose_split(const float* __restrict__ S,
                                __nv_bfloat16* __restrict__ Dh,
                                __nv_bfloat16* __restrict__ Dl, int K, int N) {
    __shared__ float t[32][33];
    int k0 = blockIdx.y * 32, n0 = blockIdx.x * 32;
    int x = threadIdx.x, y = threadIdx.y;
#pragma unroll
    for (int i = 0; i < 32; i += 8) t[y + i][x] = S[(size_t)(k0 + y + i) * N + n0 + x];
    __syncthreads();
#pragma unroll
    for (int i = 0; i < 32; i += 8) {
        float v = t[x][y + i];
        __nv_bfloat16 h = __float2bfloat16(v);
        __nv_bfloat16 l = __float2bfloat16(v - __bfloat162float(h));
        Dh[(size_t)(n0 + y + i) * K + k0 + x] = h;
        Dl[(size_t)(n0 + y + i) * K + k0 + x] = l;
    }
}

// ---------------- split / bn passes ----------------
__global__ void split_f32(const float* __restrict__ X,
                          __nv_bfloat16* __restrict__ Xh, __nv_bfloat16* __restrict__ Xl,
                          size_t total4) {
    size_t i = (size_t)blockIdx.x * blockDim.x + threadIdx.x;
    if (i >= total4) return;
    uint2 hi, lo;
    split4(((const float4*)X)[i], hi, lo);
    ((uint2*)Xh)[i] = hi;
    ((uint2*)Xl)[i] = lo;
}

__global__ void bn_relu_split(const float* __restrict__ X,
                              __nv_bfloat16* __restrict__ Xh, __nv_bfloat16* __restrict__ Xl,
                              size_t total4, int cols, const float* __restrict__ bnp) {
    size_t i = (size_t)blockIdx.x * blockDim.x + threadIdx.x;
    if (i >= total4) return;
    int c = (int)((i * 4) % cols);
    float4 x = ((const float4*)X)[i];
    float4 y;
    y.x = fmaxf(0.f, x.x * bnp[c + 0] + bnp[1024 + c + 0]);
    y.y = fmaxf(0.f, x.y * bnp[c + 1] + bnp[1024 + c + 1]);
    y.z = fmaxf(0.f, x.z * bnp[c + 2] + bnp[1024 + c + 2]);
    y.w = fmaxf(0.f, x.w * bnp[c + 3] + bnp[1024 + c + 3]);
    uint2 hi, lo;
    split4(y, hi, lo);
    ((uint2*)Xh)[i] = hi;
    ((uint2*)Xl)[i] = lo;
}

// ---------------- embeddings / batched bond path ----------------
__global__ void embed_nodes(const int* __restrict__ x, const float* __restrict__ tab,
                            float* __restrict__ z) {
    int n = blockIdx.x;
    __shared__ int idx[9];
    if (threadIdx.x < 9) idx[threadIdx.x] = x[n * 9 + threadIdx.x] + c_node_off[threadIdx.x];
    __syncthreads();
    for (int c = threadIdx.x; c < HH; c += blockDim.x) {
        float acc = 0.f;
#pragma unroll
        for (int f = 0; f < 9; f++) acc += tab[(size_t)idx[f] * HH + c];
        z[(size_t)n * HH + c] = acc;
    }
}

__global__ void combo_hist(const int* __restrict__ ea, int* __restrict__ combo,
                           int* __restrict__ cnt) {
    int e = blockIdx.x * 256 + threadIdx.x;
    if (e >= EE) return;
    int c = ea[e * 3] * 12 + ea[e * 3 + 1] * 2 + ea[e * 3 + 2];
    combo[e] = c;
    atomicAdd(&cnt[c], 1);
}

__global__ void embed_edges_u(const float* __restrict__ tab, float* __restrict__ embu) {
    int u = blockIdx.x;
    int a0 = u / 12, a1 = (u % 12) / 2, a2 = u & 1;
    int c = threadIdx.x;
    embu[u * HEH + c] = tab[(size_t)a0 * HEH + c]
                      + tab[(size_t)(119 + a1) * HEH + c]
                      + tab[(size_t)(128 + a2) * HEH + c];
}

__global__ void bond_small(const float* __restrict__ embu, const float* __restrict__ bondW,
                           const float* __restrict__ bondB, float* __restrict__ eeu) {
    __shared__ float se[HEH];
    int u = blockIdx.x, l = blockIdx.y;
    const float* bW = bondW + (size_t)l * HEH * HH;
    if (threadIdx.x < HEH) se[threadIdx.x] = embu[u * HEH + threadIdx.x];
    __syncthreads();
    int c = threadIdx.x;
    float acc = bondB[l * HH + c];
#pragma unroll 4
    for (int k = 0; k < HEH; k++) acc += se[k] * bW[(size_t)k * HH + c];
    eeu[((size_t)l * NCOMBO + u) * HH + c] = acc;
}

__global__ void wstats(const float* __restrict__ eeu, const int* __restrict__ cnt,
                       float* __restrict__ estats) {
    int l = blockIdx.y;
    int c = blockIdx.x * 256 + threadIdx.x;
    const float* base = eeu + (size_t)l * NCOMBO * HH;
    float m = 0.f, q = 0.f;
    for (int u = 0; u < NCOMBO; u++) {
        float w = (float)cnt[u];
        float v = base[u * HH + c];
        m += w * v;
        q += w * v * v;
    }
    estats[l * 2048 + c] = m;
    estats[l * 2048 + 1024 + c] = q;
}

__global__ void bn_prep_e(float* __restrict__ estats, const float* __restrict__ g,
                          const float* __restrict__ b) {
    int l = blockIdx.y;
    int c = blockIdx.x * 256 + threadIdx.x;
    float* st = estats + l * 2048;
    float m = st[c] * (1.f / EE);
    float var = st[1024 + c] * (1.f / EE) - m * m;
    float sc = g[l * HH + c] * rsqrtf(var + EPSV);
    st[c] = sc;
    st[1024 + c] = b[l * HH + c] - m * sc;
}

__global__ void eeact_apply(const float* __restrict__ eeu, const float* __restrict__ estats,
                            float* __restrict__ eeact) {
    int u = blockIdx.x, l = blockIdx.y;
    int c = threadIdx.x;
    const float* st = estats + l * 2048;
    size_t i = ((size_t)l * NCOMBO + u) * HH + c;
    eeact[i] = fmaxf(0.f, eeu[i] * st[c] + st[1024 + c]);
}

__global__ void bn_prep2(float* __restrict__ stats, float* __restrict__ bnp, int cols,
                         float inv_rows, const float* __restrict__ g,
                         const float* __restrict__ b) {
    int c = blockIdx.x * blockDim.x + threadIdx.x;
    if (c >= cols) return;
    float m = stats[c] * inv_rows;
    float var = stats[1024 + c] * inv_rows - m * m;
    float sc = g[c] * rsqrtf(var + EPSV);
    bnp[c] = sc;
    bnp[1024 + c] = b[c] - m * sc;
    stats[c] = 0.f;
    stats[1024 + c] = 0.f;
}

// ---------------- collapsed output head ----------------
// v[j] = sum_h gapW[j,h]*attW[h]; v[1024] = gapB.attW + attB
__global__ void att_vec(const float* __restrict__ gapW, const float* __restrict__ gapB,
                        const float* __restrict__ attW, const float* __restrict__ attB,
                        float* __restrict__ v) {
    int w = blockIdx.x * (blockDim.x / 32) + (threadIdx.x / 32);
    int lane = threadIdx.x & 31;
    if (w > OUTD) return;
    const float* row = (w < OUTD) ? (gapW + (size_t)w * HH) : gapB;
    float acc = 0.f;
    for (int h = lane; h < HH; h += 32) acc += row[h] * attW[h];
#pragma unroll
    for (int o = 16; o; o >>= 1) acc += __shfl_xor_sync(0xffffffffu, acc, o);
    if (lane == 0) v[w] = acc + ((w == OUTD) ? attB[0] : 0.f);
}

// w[c] = sum_j outW[c,j]*v[j] (c<512); w[512] = outB.v + v[1024]
__global__ void att_w(const float* __restrict__ outW, const float* __restrict__ outB,
                      const float* __restrict__ v, float* __restrict__ w) {
    int r = blockIdx.x * 8 + (threadIdx.x >> 5);
    int lane = threadIdx.x & 31;
    if (r > HH) return;
    const float* row = (r < HH) ? (outW + (size_t)r * OUTD) : outB;
    float acc = 0.f;
    for (int j = lane; j < OUTD; j += 32) acc += row[j] * v[j];
#pragma unroll
    for (int o = 16; o; o >>= 1) acc += __shfl_xor_sync(0xffffffffu, acc, o);
    if (lane == 0) w[r] = acc + ((r == HH) ? v[OUTD] : 0.f);
}

// Fused: z = relu(bn(zpre)) per column; att = z.w + const; softmax over 32 nodes;
// zg[b] = sum_n alpha_n z_n; write zg as bf16 hi/lo split.
__global__ void __launch_bounds__(256)
pool_z(const float* __restrict__ zpre, const float* __restrict__ bnp,
       const float* __restrict__ w,
       __nv_bfloat16* __restrict__ zgh, __nv_bfloat16* __restrict__ zgl) {
    __shared__ float satt[NPG];
    __shared__ float salpha[NPG];
    int b = blockIdx.x;
    int warp = threadIdx.x >> 5, lane = threadIdx.x & 31;
    const float cst = w[HH];
    const float* zb = zpre + (size_t)b * NPG * HH;

    for (int n = warp; n < NPG; n += 8) {
        float acc = 0.f;
        for (int k = lane; k < HH; k += 32) {
            float zz = fmaxf(0.f, zb[n * HH + k] * bnp[k] + bnp[1024 + k]);
            acc += zz * w[k];
        }
#pragma unroll
        for (int o = 16; o; o >>= 1) acc += __shfl_xor_sync(0xffffffffu, acc, o);
        if (lane == 0) satt[n] = acc + cst;
    }
    __syncthreads();
    if (threadIdx.x < 32) {
        float a = satt[threadIdx.x];
        float mx = a;
#pragma unroll
        for (int o = 16; o; o >>= 1) mx = fmaxf(mx, __shfl_xor_sync(0xffffffffu, mx, o));
        float ex = expf(a - mx);
        float sm = ex;
#pragma unroll
        for (int o = 16; o; o >>= 1) sm += __shfl_xor_sync(0xffffffffu, sm, o);
        salpha[threadIdx.x] = ex / sm;
    }
    __syncthreads();
    for (int j = threadIdx.x; j < HH; j += 256) {
        float sc = bnp[j], sh = bnp[1024 + j];
        float acc = 0.f;
#pragma unroll
        for (int n = 0; n < NPG; n++)
            acc += salpha[n] * fmaxf(0.f, zb[n * HH + j] * sc + sh);
        __nv_bfloat16 h = __float2bfloat16(acc);
        zgh[(size_t)b * HH + j] = h;
        zgl[(size_t)b * HH + j] = __float2bfloat16(acc - __bfloat162float(h));
    }
}

// ---------------- host orchestration ----------------
extern "C" void kernel_launch(void* const* d_in, const int* in_sizes, int n_in,
                              void* d_out, int out_size) {
    const int*   x        = (const int*)  d_in[0];
    const int*   edgeattr = (const int*)  d_in[1];
    const int*   eidx     = (const int*)  d_in[2];
    const float* node_tab = (const float*)d_in[4];
    const float* edge_tab = (const float*)d_in[5];
    const float* bondW    = (const float*)d_in[6];
    const float* bondB    = (const float*)d_in[7];
    const float* bondG    = (const float*)d_in[8];
    const float* bondBeta = (const float*)d_in[9];
    const float* atomW1   = (const float*)d_in[10];
    const float* atomB1   = (const float*)d_in[11];
    const float* atomG    = (const float*)d_in[12];
    const float* atomBeta = (const float*)d_in[13];
    const float* atomW2   = (const float*)d_in[14];
    const float* atomB2   = (const float*)d_in[15];
    const float* normG    = (const float*)d_in[16];
    const float* normB    = (const float*)d_in[17];
    const float* outW     = (const float*)d_in[18];
    const float* outB     = (const float*)d_in[19];
    const float* gapW     = (const float*)d_in[20];
    const float* gapB     = (const float*)d_in[21];
    const float* attW     = (const float*)d_in[22];
    const float* attB     = (const float*)d_in[23];
    const float* projW    = (const float*)d_in[24];
    const float* projB    = (const float*)d_in[25];
    float* out = (float*)d_out;

    float *p_z, *p_h, *p_zpre, *p_v, *p_w, *p_hgpre, *p_stats, *p_estats;
    float *p_embu, *p_eeu, *p_eeact;
    int *p_combo, *p_cnt;
    __nv_bfloat16 *p_aggh, *p_aggl, *p_hh, *p_hl, *p_zgh, *p_zgl, *p_hgh, *p_hgl;
    __nv_bfloat16 *p_aW1h, *p_aW1l, *p_aW2h, *p_aW2l, *p_oWh, *p_oWl, *p_pWh, *p_pWl;
    cudaGetSymbolAddress((void**)&p_z, g_z);
    cudaGetSymbolAddress((void**)&p_h, g_h);
    cudaGetSymbolAddress((void**)&p_zpre, g_zpre);
    cudaGetSymbolAddress((void**)&p_v, g_v);
    cudaGetSymbolAddress((void**)&p_w, g_w);
    cudaGetSymbolAddress((void**)&p_hgpre, g_hgpre);
    cudaGetSymbolAddress((void**)&p_stats, g_stats);
    cudaGetSymbolAddress((void**)&p_estats, g_estats);
    cudaGetSymbolAddress((void**)&p_combo, g_combo);
    cudaGetSymbolAddress((void**)&p_cnt, g_cnt);
    cudaGetSymbolAddress((void**)&p_embu, g_embu);
    cudaGetSymbolAddress((void**)&p_eeu, g_eeu);
    cudaGetSymbolAddress((void**)&p_eeact, g_eeact);
    cudaGetSymbolAddress((void**)&p_aggh, g_aggh);
    cudaGetSymbolAddress((void**)&p_aggl, g_aggl);
    cudaGetSymbolAddress((void**)&p_hh, g_hh);
    cudaGetSymbolAddress((void**)&p_hl, g_hl);
    cudaGetSymbolAddress((void**)&p_zgh, g_zgh);
    cudaGetSymbolAddress((void**)&p_zgl, g_zgl);
    cudaGetSymbolAddress((void**)&p_hgh, g_hgh);
    cudaGetSymbolAddress((void**)&p_hgl, g_hgl);
    cudaGetSymbolAddress((void**)&p_aW1h, g_aW1h);
    cudaGetSymbolAddress((void**)&p_aW1l, g_aW1l);
    cudaGetSymbolAddress((void**)&p_aW2h, g_aW2h);
    cudaGetSymbolAddress((void**)&p_aW2l, g_aW2l);
    cudaGetSymbolAddress((void**)&p_oWh, g_oWh);
    cudaGetSymbolAddress((void**)&p_oWl, g_oWl);
    cudaGetSymbolAddress((void**)&p_pWh, g_pWh);
    cudaGetSymbolAddress((void**)&p_pWl, g_pWl);

    float* stats1 = p_stats;
    float* stats2 = p_stats + 2048;
    float* bnp1   = p_stats + 4096;
    float* bnp2   = p_stats + 6144;

    cudaFuncSetAttribute(gemm_mma<true >, cudaFuncAttributeMaxDynamicSharedMemorySize, GEMM_SMEM);
    cudaFuncSetAttribute(gemm_mma<false>, cudaFuncAttributeMaxDynamicSharedMemorySize, GEMM_SMEM);
    cudaFuncSetAttribute(graph_aggregate<false>, cudaFuncAttributeMaxDynamicSharedMemorySize,
                         NPG * HH * (int)sizeof(float));
    cudaFuncSetAttribute(graph_aggregate<true>, cudaFuncAttributeMaxDynamicSharedMemorySize,
                         NPG * HH * (int)sizeof(float));

    // weight transposes + bf16 split
    for (int l = 0; l < LL; l++) {
        transpose_split<<<dim3(H2 / 32, HH / 32), dim3(32, 8)>>>(
            atomW1 + (size_t)l * HH * H2, p_aW1h + (size_t)l * H2 * HH,
            p_aW1l + (size_t)l * H2 * HH, HH, H2);
        transpose_split<<<dim3(HH / 32, H2 / 32), dim3(32, 8)>>>(
            atomW2 + (size_t)l * H2 * HH, p_aW2h + (size_t)l * HH * H2,
            p_aW2l + (size_t)l * HH * H2, H2, HH);
    }
    transpose_split<<<dim3(OUTD / 32, HH / 32), dim3(32, 8)>>>(outW, p_oWh, p_oWl, HH, OUTD);
    transpose_split<<<dim3(OUTD / 32, OUTD / 32), dim3(32, 8)>>>(projW, p_pWh, p_pWl, OUTD, OUTD);

    // output-head vectors (independent of layers)
    att_vec<<<129, 256>>>(gapW, gapB, attW, attB, p_v);
    att_w<<<65, 256>>>(outW, outB, p_v, p_w);

    // embeddings + edge combo machinery
    embed_nodes<<<NN, 256>>>(x, node_tab, p_z);
    cudaMemsetAsync(p_cnt, 0, NCOMBO * sizeof(int));
    cudaMemsetAsync(p_stats, 0, 4096 * sizeof(float));
    combo_hist<<<(EE + 255) / 256, 256>>>(edgeattr, p_combo, p_cnt);
    embed_edges_u<<<NCOMBO, HEH>>>(edge_tab, p_embu);

    // precompute ALL layers' bond tables
    bond_small<<<dim3(NCOMBO, LL), HH>>>(p_embu, bondW, bondB, p_eeu);
    wstats<<<dim3(2, LL), 256>>>(p_eeu, p_cnt, p_estats);
    bn_prep_e<<<dim3(2, LL), 256>>>(p_estats, bondG, bondBeta);
    eeact_apply<<<dim3(NCOMBO, LL), HH>>>(p_eeu, p_estats, p_eeact);

    for (int l = 0; l < LL; l++) {
        const __nv_bfloat16* aW1h = p_aW1h + (size_t)l * H2 * HH;
        const __nv_bfloat16* aW1l = p_aW1l + (size_t)l * H2 * HH;
        const float* aB1  = atomB1   + (size_t)l * H2;
        const float* aG   = atomG    + (size_t)l * H2;
        const float* aBe  = atomBeta + (size_t)l * H2;
        const __nv_bfloat16* aW2h = p_aW2h + (size_t)l * HH * H2;
        const __nv_bfloat16* aW2l = p_aW2l + (size_t)l * HH * H2;
        const float* aB2  = atomB2   + (size_t)l * HH;
        const float* nG   = normG    + (size_t)l * HH;
        const float* nB   = normB    + (size_t)l * HH;
        const float* eea  = p_eeact + (size_t)l * NCOMBO * HH;

        if (l == 0)
            graph_aggregate<false><<<BB, 512, NPG * HH * sizeof(float)>>>(
                p_z, nullptr, eea, eidx, p_combo, p_aggh, p_aggl);
        else
            graph_aggregate<true><<<BB, 512, NPG * HH * sizeof(float)>>>(
                p_zpre, bnp2, eea, eidx, p_combo, p_aggh, p_aggl);

        gemm_mma<true><<<dim3(H2 / 128, NN / 128), 256, GEMM_SMEM>>>(
            H2, HH, p_aggh, p_aggl, aW1h, aW1l, aB1, p_h, stats1);
        bn_prep2<<<4, 256>>>(stats1, bnp1, H2, 1.f / NN, aG, aBe);

        bn_relu_split<<<(unsigned)(((size_t)NN * H2 / 4 + 255) / 256), 256>>>(
            p_h, p_hh, p_hl, (size_t)NN * H2 / 4, H2, bnp1);

        gemm_mma<true><<<dim3(HH / 128, NN / 128), 256, GEMM_SMEM>>>(
            HH, H2, p_hh, p_hl, aW2h, aW2l, aB2, p_zpre, stats2);
        bn_prep2<<<2, 256>>>(stats2, bnp2, HH, 1.f / NN, nG, nB);
    }

    // collapsed head: pool directly on z (= relu(bn(zpre)), fused), then two tiny GEMMs
    pool_z<<<BB, 256>>>(p_zpre, bnp2, p_w, p_zgh, p_zgl);

    // hg_pre = zg @ outW + outB   [1024, 1024], K=512
    gemm_mma<false><<<dim3(OUTD / 128, BB / 128), 256, GEMM_SMEM>>>(
        OUTD, HH, p_zgh, p_zgl, p_oWh, p_oWl, outB, p_hgpre, nullptr);

    split_f32<<<(unsigned)(((size_t)BB * OUTD / 4 + 255) / 256), 256>>>(
        p_hgpre, p_hgh, p_hgl, (size_t)BB * OUTD / 4);

    // out = hg_pre @ projW + projB   [1024, 1024], K=1024
    gemm_mma<false><<<dim3(OUTD / 128, BB / 128), 256, GEMM_SMEM>>>(
        OUTD, OUTD, p_hgh, p_hgl, p_pWh, p_pWl, projB, out, nullptr);
}